// round 2
// baseline (speedup 1.0000x reference)
#include <cuda_runtime.h>
#include <cuda_bf16.h>
#include <math.h>

#define BB 8
#define TT 4096
#define DD 512
#define HH 8
#define HD 64
#define TP 4224   // T + 128 (padded for local attention)
#define NLOC 32   // T / 128
#define NDIL 64   // T / 64

// ---------------- scratch (static device memory; no allocs allowed) ----------------
__device__ float g_x  [BB*TT*DD];
__device__ float g_xn [BB*TT*DD];
__device__ float g_q  [BB*TT*DD];
__device__ float g_att[BB*TT*DD];
__device__ float g_tmp[BB*TT*DD];
__device__ float g_kp [BB*TP*DD];
__device__ float g_vp [BB*TP*DD];
__device__ float g_h1 [BB*TT*1024];
__device__ float g_h2 [BB*TT*1024];
__device__ float g_lcos[256*64];
__device__ float g_lsin[256*64];

// ---------------- local rope tables: rope_tables(256, 64) in double ----------------
__global__ void rope_init_kernel() {
    int idx = blockIdx.x * blockDim.x + threadIdx.x;
    if (idx >= 256 * 64) return;
    int t = idx >> 6, d = idx & 63;
    double inv = pow(10000.0, -(double)(d & 31) / 32.0);
    double a = (double)t * inv;
    g_lcos[idx] = (float)cos(a);
    g_lsin[idx] = (float)sin(a);
}

// ---------------- elementwise (mask is int32/float32 words; nonzero = keep) ----------------
__global__ void mask_mul4_kernel(const float* __restrict__ X,
                                 const int* __restrict__ pm,
                                 float* __restrict__ Y, int n4) {
    int i = blockIdx.x * blockDim.x + threadIdx.x;
    if (i >= n4) return;
    float m = pm[i >> 7] ? 1.0f : 0.0f;   // row = (i*4)/512
    float4 v = ((const float4*)X)[i];
    v.x *= m; v.y *= m; v.z *= m; v.w *= m;
    ((float4*)Y)[i] = v;
}

__global__ void add_mask4_kernel(const float* __restrict__ A,
                                 const float* __restrict__ Bv,
                                 const int* __restrict__ pm,
                                 float* __restrict__ Y, int n4) {
    int i = blockIdx.x * blockDim.x + threadIdx.x;
    if (i >= n4) return;
    float m = pm[i >> 7] ? 1.0f : 0.0f;
    float4 a = ((const float4*)A)[i];
    float4 b = ((const float4*)Bv)[i];
    float4 o;
    o.x = (a.x + b.x) * m; o.y = (a.y + b.y) * m;
    o.z = (a.z + b.z) * m; o.w = (a.w + b.w) * m;
    ((float4*)Y)[i] = o;
}

// ---------------- layernorm over 512, optional mask-multiply on output ----------------
__global__ void __launch_bounds__(128) ln_kernel(
    const float* __restrict__ X, const float* __restrict__ g,
    const float* __restrict__ b, const int* __restrict__ pm,
    float* __restrict__ Y, int maskOut)
{
    int row = blockIdx.x;
    int tid = threadIdx.x;  // 128
    const float4* x4 = (const float4*)(X + (size_t)row * DD);
    float4 v = x4[tid];
    float s  = v.x + v.y + v.z + v.w;
    float ss = v.x*v.x + v.y*v.y + v.z*v.z + v.w*v.w;
    #pragma unroll
    for (int o = 16; o; o >>= 1) {
        s  += __shfl_xor_sync(~0u, s,  o);
        ss += __shfl_xor_sync(~0u, ss, o);
    }
    __shared__ float sh[8];
    int w = tid >> 5, lane = tid & 31;
    if (lane == 0) { sh[w] = s; sh[4 + w] = ss; }
    __syncthreads();
    s  = sh[0] + sh[1] + sh[2] + sh[3];
    ss = sh[4] + sh[5] + sh[6] + sh[7];
    float mean = s * (1.0f / 512.0f);
    float var  = ss * (1.0f / 512.0f) - mean * mean;
    float inv  = rsqrtf(var + 1e-5f);
    float m = maskOut ? (pm[row] ? 1.0f : 0.0f) : 1.0f;
    float4 gg = ((const float4*)g)[tid];
    float4 bb = ((const float4*)b)[tid];
    float4 o;
    o.x = ((v.x - mean) * inv * gg.x + bb.x) * m;
    o.y = ((v.y - mean) * inv * gg.y + bb.y) * m;
    o.z = ((v.z - mean) * inv * gg.z + bb.z) * m;
    o.w = ((v.w - mean) * inv * gg.w + bb.w) * m;
    ((float4*)(Y + (size_t)row * DD))[tid] = o;
}

// ---------------- SGEMM: C[M,N] = A[M,K] @ W[N,K]^T + bias, optional GELU / padded scatter ----------------
__global__ void __launch_bounds__(256) sgemm_kernel(
    const float* __restrict__ A, const float* __restrict__ W,
    const float* __restrict__ bias, float* __restrict__ C,
    int M, int N, int K, int act, int padOut)
{
    __shared__ float As[16][128];
    __shared__ float Ws[16][128];
    int row0 = blockIdx.y * 128;
    int col0 = blockIdx.x * 128;
    int tid = threadIdx.x;
    int tx = tid & 15, ty = tid >> 4;
    float acc[8][8];
    #pragma unroll
    for (int i = 0; i < 8; i++)
        #pragma unroll
        for (int j = 0; j < 8; j++) acc[i][j] = 0.0f;

    for (int k0 = 0; k0 < K; k0 += 16) {
        #pragma unroll
        for (int l = 0; l < 2; l++) {
            int idx = tid + l * 256;
            int r = idx >> 2;
            int c4 = (idx & 3) << 2;
            float4 v = *(const float4*)(A + (size_t)(row0 + r) * K + k0 + c4);
            As[c4 + 0][r] = v.x; As[c4 + 1][r] = v.y;
            As[c4 + 2][r] = v.z; As[c4 + 3][r] = v.w;
        }
        #pragma unroll
        for (int l = 0; l < 2; l++) {
            int idx = tid + l * 256;
            int r = idx >> 2;
            int c4 = (idx & 3) << 2;
            float4 v = *(const float4*)(W + (size_t)(col0 + r) * K + k0 + c4);
            Ws[c4 + 0][r] = v.x; Ws[c4 + 1][r] = v.y;
            Ws[c4 + 2][r] = v.z; Ws[c4 + 3][r] = v.w;
        }
        __syncthreads();
        #pragma unroll
        for (int kk = 0; kk < 16; kk++) {
            float4 a0 = *(const float4*)&As[kk][ty * 4];
            float4 a1 = *(const float4*)&As[kk][64 + ty * 4];
            float4 b0 = *(const float4*)&Ws[kk][tx * 4];
            float4 b1 = *(const float4*)&Ws[kk][64 + tx * 4];
            float ar[8] = {a0.x, a0.y, a0.z, a0.w, a1.x, a1.y, a1.z, a1.w};
            float br[8] = {b0.x, b0.y, b0.z, b0.w, b1.x, b1.y, b1.z, b1.w};
            #pragma unroll
            for (int i = 0; i < 8; i++)
                #pragma unroll
                for (int j = 0; j < 8; j++)
                    acc[i][j] += ar[i] * br[j];
        }
        __syncthreads();
    }

    #pragma unroll
    for (int ii = 0; ii < 8; ii++) {
        int rl = (ii < 4) ? (ty * 4 + ii) : (64 + ty * 4 + (ii - 4));
        int r = row0 + rl;
        size_t orow = padOut ? ((size_t)(r >> 12) * TP + 64 + (r & 4095)) : (size_t)r;
        float* crow = C + orow * N;
        int c0a = col0 + tx * 4;
        int c0b = col0 + 64 + tx * 4;
        float4 oa, ob;
        float va[4], vb[4];
        #pragma unroll
        for (int j = 0; j < 4; j++) {
            va[j] = acc[ii][j]     + bias[c0a + j];
            vb[j] = acc[ii][4 + j] + bias[c0b + j];
            if (act) {
                va[j] = 0.5f * va[j] * (1.0f + erff(va[j] * 0.70710678118654752f));
                vb[j] = 0.5f * vb[j] * (1.0f + erff(vb[j] * 0.70710678118654752f));
            }
        }
        oa.x = va[0]; oa.y = va[1]; oa.z = va[2]; oa.w = va[3];
        ob.x = vb[0]; ob.y = vb[1]; ob.z = vb[2]; ob.w = vb[3];
        *(float4*)(crow + c0a) = oa;
        *(float4*)(crow + c0b) = ob;
    }
}

// ---------------- fill pad rows of padded K/V projections with bias ----------------
__global__ void fill_pad_kernel(const float* __restrict__ kb, const float* __restrict__ vb) {
    int idx = blockIdx.x * blockDim.x + threadIdx.x;  // 8*128*512
    if (idx >= BB * 128 * DD) return;
    int c  = idx & 511;
    int rr = (idx >> 9) & 127;
    int b  = idx >> 16;
    int prow = (rr < 64) ? rr : (TT + rr);
    size_t o = ((size_t)b * TP + prow) * DD + c;
    g_kp[o] = kb[c];
    g_vp[o] = vb[c];
}

// ---------------- local attention: CTA = (window j, head h, batch b) ----------------
// Q: 128 queries, K/V: 256 padded keys, RoPE from g_lcos/g_lsin
#define LKS 68    // row stride for K/V/Q tiles
#define LSS 257   // row stride for score tile
__global__ void __launch_bounds__(256) local_attn_kernel(
    const float* __restrict__ Qg, const int* __restrict__ pm,
    float* __restrict__ Og)
{
    int j = blockIdx.x, h = blockIdx.y, b = blockIdx.z;
    extern __shared__ float sm[];
    float* Ks = sm;                      // 256*68
    float* Vs = Ks + 256 * LKS;          // 256*68
    float* Qs = Vs + 256 * LKS;          // 32*68
    float* Ss = Qs + 32 * LKS;           // 32*257
    int*  keep = (int*)(Ss + 32 * LSS);  // 256
    int tid = threadIdx.x;

    // load K (rope) and V
    for (int r0 = 0; r0 < 256; r0 += 4) {
        int r = r0 + (tid >> 6);
        int d = tid & 63;
        size_t base = ((size_t)b * TP + (size_t)j * 128 + r) * DD + h * HD;
        float kv = g_kp[base + d];
        float ko = g_kp[base + (d ^ 32)];
        float c = g_lcos[r * 64 + d], s = g_lsin[r * 64 + d];
        Ks[r * LKS + d] = (d < 32) ? (kv * c - ko * s) : (kv * c + ko * s);
        Vs[r * LKS + d] = g_vp[base + d];
    }
    if (tid < 256) {
        int orig = j * 128 + tid - 64;
        keep[tid] = (orig >= 0 && orig < TT && pm[(size_t)b * TT + orig]) ? 1 : 0;
    }
    __syncthreads();
    if (tid == 0) {
        int any = 0;
        for (int i = 0; i < 256; i++) any |= keep[i];
        if (!any) keep[0] = 1;
    }
    __syncthreads();

    for (int c0 = 0; c0 < 128; c0 += 32) {
        // load Q chunk with rope (table index 64 + c0 + i)
        for (int r0 = 0; r0 < 32; r0 += 4) {
            int i = r0 + (tid >> 6);
            int d = tid & 63;
            int t = j * 128 + c0 + i;
            size_t base = ((size_t)b * TT + t) * DD + h * HD;
            float qv = Qg[base + d];
            float qo = Qg[base + (d ^ 32)];
            int ti = 64 + c0 + i;
            float c = g_lcos[ti * 64 + d], s = g_lsin[ti * 64 + d];
            Qs[i * LKS + d] = (d < 32) ? (qv * c - qo * s) : (qv * c + qo * s);
        }
        __syncthreads();

        // scores: thread -> query (tid&31), 32 keys starting (tid>>5)*32
        {
            int qi = tid & 31;
            int kb = (tid >> 5) * 32;
            float acc[32];
            #pragma unroll
            for (int i = 0; i < 32; i++) acc[i] = 0.0f;
            for (int d0 = 0; d0 < 64; d0 += 16) {
                float qr[16];
                #pragma unroll
                for (int dd = 0; dd < 16; dd += 4) {
                    float4 qv = *(const float4*)&Qs[qi * LKS + d0 + dd];
                    qr[dd] = qv.x; qr[dd+1] = qv.y; qr[dd+2] = qv.z; qr[dd+3] = qv.w;
                }
                #pragma unroll 4
                for (int kk = 0; kk < 32; kk++) {
                    const float* kp = &Ks[(kb + kk) * LKS + d0];
                    #pragma unroll
                    for (int dd = 0; dd < 16; dd += 4) {
                        float4 kv = *(const float4*)(kp + dd);
                        acc[kk] += qr[dd] * kv.x + qr[dd+1] * kv.y
                                 + qr[dd+2] * kv.z + qr[dd+3] * kv.w;
                    }
                }
            }
            #pragma unroll
            for (int kk = 0; kk < 32; kk++) {
                int k = kb + kk;
                Ss[qi * LSS + k] = keep[k] ? acc[kk] * 0.125f : -1e9f;
            }
        }
        __syncthreads();

        // softmax: 8 warps x 4 rows
        {
            int wp = tid >> 5, lane = tid & 31;
            for (int rr = 0; rr < 4; rr++) {
                int r = wp * 4 + rr;
                float* row = Ss + r * LSS;
                float vals[8];
                float mx = -1e30f;
                #pragma unroll
                for (int m = 0; m < 8; m++) {
                    vals[m] = row[lane + 32 * m];
                    mx = fmaxf(mx, vals[m]);
                }
                #pragma unroll
                for (int o = 16; o; o >>= 1) mx = fmaxf(mx, __shfl_xor_sync(~0u, mx, o));
                float sum = 0.0f;
                #pragma unroll
                for (int m = 0; m < 8; m++) { vals[m] = expf(vals[m] - mx); sum += vals[m]; }
                #pragma unroll
                for (int o = 16; o; o >>= 1) sum += __shfl_xor_sync(~0u, sum, o);
                float inv = 1.0f / sum;
                #pragma unroll
                for (int m = 0; m < 8; m++) row[lane + 32 * m] = vals[m] * inv;
            }
        }
        __syncthreads();

        // AV: thread -> query (tid&31), 8 dims starting (tid>>5)*8
        {
            int qi = tid & 31;
            int db = (tid >> 5) * 8;
            float acc[8];
            #pragma unroll
            for (int i = 0; i < 8; i++) acc[i] = 0.0f;
            #pragma unroll 4
            for (int k = 0; k < 256; k++) {
                float p = Ss[qi * LSS + k];
                float4 v0 = *(const float4*)&Vs[k * LKS + db];
                float4 v1 = *(const float4*)&Vs[k * LKS + db + 4];
                acc[0] += p * v0.x; acc[1] += p * v0.y;
                acc[2] += p * v0.z; acc[3] += p * v0.w;
                acc[4] += p * v1.x; acc[5] += p * v1.y;
                acc[6] += p * v1.z; acc[7] += p * v1.w;
            }
            int t = j * 128 + c0 + qi;
            size_t base = ((size_t)b * TT + t) * DD + h * HD + db;
            float4 o0, o1;
            o0.x = acc[0]; o0.y = acc[1]; o0.z = acc[2]; o0.w = acc[3];
            o1.x = acc[4]; o1.y = acc[5]; o1.z = acc[6]; o1.w = acc[7];
            *(float4*)(Og + base)     = o0;
            *(float4*)(Og + base + 4) = o1;
        }
        __syncthreads();
    }
}

// ---------------- global (dilated) attention: CTA = (w, head, batch); seq = {w, w+64, ...} ----------------
__global__ void __launch_bounds__(256) global_attn_kernel(
    const float* __restrict__ Qg, const float* __restrict__ Kg,
    const float* __restrict__ Vg, const int* __restrict__ pm,
    const float* __restrict__ cosp, const float* __restrict__ sinp,
    float* __restrict__ Og)
{
    int w = blockIdx.x, h = blockIdx.y, b = blockIdx.z;
    extern __shared__ float sm[];
    float* Qs = sm;                      // 64*68
    float* Ks = Qs + 64 * LKS;
    float* Vs = Ks + 64 * LKS;
    float* Ss = Vs + 64 * LKS;           // 64*257
    int*  keep = (int*)(Ss + 64 * LSS);  // 64
    int tid = threadIdx.x;

    for (int r0 = 0; r0 < 64; r0 += 4) {
        int nn = r0 + (tid >> 6);
        int d = tid & 63;
        int p = nn * 64 + w;
        size_t base = ((size_t)b * TT + p) * DD + h * HD;
        float c = cosp[p * 64 + d], s = sinp[p * 64 + d];
        float qv = Qg[base + d], qo = Qg[base + (d ^ 32)];
        float kv = Kg[base + d], ko = Kg[base + (d ^ 32)];
        Qs[nn * LKS + d] = (d < 32) ? (qv * c - qo * s) : (qv * c + qo * s);
        Ks[nn * LKS + d] = (d < 32) ? (kv * c - ko * s) : (kv * c + ko * s);
        Vs[nn * LKS + d] = Vg[base + d];
    }
    if (tid < 64) keep[tid] = pm[(size_t)b * TT + tid * 64 + w] ? 1 : 0;
    __syncthreads();

    // scores: thread -> query (tid&63), 16 keys starting (tid>>6)*16
    {
        int qi = tid & 63;
        int kb = (tid >> 6) * 16;
        float acc[16];
        #pragma unroll
        for (int i = 0; i < 16; i++) acc[i] = 0.0f;
        for (int d0 = 0; d0 < 64; d0 += 16) {
            float qr[16];
            #pragma unroll
            for (int dd = 0; dd < 16; dd += 4) {
                float4 qv = *(const float4*)&Qs[qi * LKS + d0 + dd];
                qr[dd] = qv.x; qr[dd+1] = qv.y; qr[dd+2] = qv.z; qr[dd+3] = qv.w;
            }
            #pragma unroll 4
            for (int kk = 0; kk < 16; kk++) {
                const float* kp = &Ks[(kb + kk) * LKS + d0];
                #pragma unroll
                for (int dd = 0; dd < 16; dd += 4) {
                    float4 kv = *(const float4*)(kp + dd);
                    acc[kk] += qr[dd] * kv.x + qr[dd+1] * kv.y
                             + qr[dd+2] * kv.z + qr[dd+3] * kv.w;
                }
            }
        }
        #pragma unroll
        for (int kk = 0; kk < 16; kk++) {
            int k = kb + kk;
            Ss[qi * LSS + k] = keep[k] ? acc[kk] * 0.125f : -1e9f;
        }
    }
    __syncthreads();

    // softmax: 8 warps x 8 rows, 64 cols
    {
        int wp = tid >> 5, lane = tid & 31;
        for (int rr = 0; rr < 8; rr++) {
            int r = wp * 8 + rr;
            float* row = Ss + r * LSS;
            float a0 = row[lane], a1 = row[lane + 32];
            float mx = fmaxf(a0, a1);
            #pragma unroll
            for (int o = 16; o; o >>= 1) mx = fmaxf(mx, __shfl_xor_sync(~0u, mx, o));
            float e0 = expf(a0 - mx), e1 = expf(a1 - mx);
            float sum = e0 + e1;
            #pragma unroll
            for (int o = 16; o; o >>= 1) sum += __shfl_xor_sync(~0u, sum, o);
            float inv = 1.0f / sum;
            row[lane] = e0 * inv; row[lane + 32] = e1 * inv;
        }
    }
    __syncthreads();

    // AV: thread -> query (tid&63), 16 dims starting (tid>>6)*16
    {
        int qi = tid & 63;
        int db = (tid >> 6) * 16;
        float acc[16];
        #pragma unroll
        for (int i = 0; i < 16; i++) acc[i] = 0.0f;
        #pragma unroll 4
        for (int k = 0; k < 64; k++) {
            float p = Ss[qi * LSS + k];
            #pragma unroll
            for (int dd = 0; dd < 16; dd += 4) {
                float4 v = *(const float4*)&Vs[k * LKS + db + dd];
                acc[dd]   += p * v.x; acc[dd+1] += p * v.y;
                acc[dd+2] += p * v.z; acc[dd+3] += p * v.w;
            }
        }
        int p = qi * 64 + w;
        size_t base = ((size_t)b * TT + p) * DD + h * HD + db;
        #pragma unroll
        for (int dd = 0; dd < 16; dd += 4) {
            float4 o;
            o.x = acc[dd]; o.y = acc[dd+1]; o.z = acc[dd+2]; o.w = acc[dd+3];
            *(float4*)(Og + base + dd) = o;
        }
    }
}

// ---------------- host ----------------
extern "C" void kernel_launch(void* const* d_in, const int* in_sizes, int n_in,
                              void* d_out, int out_size)
{
    const float* x    = (const float*)d_in[0];
    const int*   pm   = (const int*)d_in[1];   // bool mask shipped as 4-byte words
    const float* cosp = (const float*)d_in[2];
    const float* sinp = (const float*)d_in[3];
    const float* ln1_g = (const float*)d_in[4];
    const float* ln1_b = (const float*)d_in[5];
    const float* ln2_g = (const float*)d_in[6];
    const float* ln2_b = (const float*)d_in[7];
    const float* ln3_g = (const float*)d_in[8];
    const float* ln3_b = (const float*)d_in[9];
    const float* lq_w = (const float*)d_in[10];
    const float* lq_b = (const float*)d_in[11];
    const float* lk_w = (const float*)d_in[12];
    const float* lk_b = (const float*)d_in[13];
    const float* lv_w = (const float*)d_in[14];
    const float* lv_b = (const float*)d_in[15];
    const float* lo_w = (const float*)d_in[16];
    const float* lo_b = (const float*)d_in[17];
    const float* gq_w = (const float*)d_in[18];
    const float* gq_b = (const float*)d_in[19];
    const float* gk_w = (const float*)d_in[20];
    const float* gk_b = (const float*)d_in[21];
    const float* gv_w = (const float*)d_in[22];
    const float* gv_b = (const float*)d_in[23];
    const float* go_w = (const float*)d_in[24];
    const float* go_b = (const float*)d_in[25];
    const float* f1_w = (const float*)d_in[26];
    const float* f1_b = (const float*)d_in[27];
    const float* f2_w = (const float*)d_in[28];
    const float* f2_b = (const float*)d_in[29];
    const float* f3_w = (const float*)d_in[30];
    const float* f3_b = (const float*)d_in[31];
    float* out = (float*)d_out;

    float *px, *pxn, *pq, *patt, *ptmp, *pkp, *pvp, *ph1, *ph2;
    cudaGetSymbolAddress((void**)&px,   g_x);
    cudaGetSymbolAddress((void**)&pxn,  g_xn);
    cudaGetSymbolAddress((void**)&pq,   g_q);
    cudaGetSymbolAddress((void**)&patt, g_att);
    cudaGetSymbolAddress((void**)&ptmp, g_tmp);
    cudaGetSymbolAddress((void**)&pkp,  g_kp);
    cudaGetSymbolAddress((void**)&pvp,  g_vp);
    cudaGetSymbolAddress((void**)&ph1,  g_h1);
    cudaGetSymbolAddress((void**)&ph2,  g_h2);

    const int M = BB * TT;           // 32768 rows
    const int n4 = M * DD / 4;       // float4 count for (B,T,D)
    const int EW = 256;

    // dynamic smem sizes
    size_t smLoc = (size_t)(2 * 256 * LKS + 32 * LKS + 32 * LSS) * 4 + 256 * 4;
    size_t smGlb = (size_t)(3 * 64 * LKS + 64 * LSS) * 4 + 64 * 4;
    cudaFuncSetAttribute(local_attn_kernel,  cudaFuncAttributeMaxDynamicSharedMemorySize, (int)smLoc);
    cudaFuncSetAttribute(global_attn_kernel, cudaFuncAttributeMaxDynamicSharedMemorySize, (int)smGlb);

    // 0) local rope tables
    rope_init_kernel<<<64, 256>>>();

    // 1) x = x * mask
    mask_mul4_kernel<<<(n4 + EW - 1) / EW, EW>>>(x, pm, px, n4);

    // 2) xn = LN1(x) * mask   (xm for local attention)
    ln_kernel<<<M, 128>>>(px, ln1_g, ln1_b, pm, pxn, 1);

    // 3) local projections
    sgemm_kernel<<<dim3(DD / 128, M / 128), 256>>>(pxn, lq_w, lq_b, pq,  M, DD, DD, 0, 0);
    sgemm_kernel<<<dim3(DD / 128, M / 128), 256>>>(pxn, lk_w, lk_b, pkp, M, DD, DD, 0, 1);
    sgemm_kernel<<<dim3(DD / 128, M / 128), 256>>>(pxn, lv_w, lv_b, pvp, M, DD, DD, 0, 1);
    fill_pad_kernel<<<(BB * 128 * DD + EW - 1) / EW, EW>>>(lk_b, lv_b);

    // 4) local attention
    local_attn_kernel<<<dim3(NLOC, HH, BB), 256, smLoc>>>(pq, pm, patt);

    // 5) O projection + residual
    sgemm_kernel<<<dim3(DD / 128, M / 128), 256>>>(patt, lo_w, lo_b, ptmp, M, DD, DD, 0, 0);
    add_mask4_kernel<<<(n4 + EW - 1) / EW, EW>>>(px, ptmp, pm, px, n4);

    // 6) xn = LN2(x) (unmasked)
    ln_kernel<<<M, 128>>>(px, ln2_g, ln2_b, pm, pxn, 0);

    // 7) global projections (plain layout; reuse kp/vp buffers)
    sgemm_kernel<<<dim3(DD / 128, M / 128), 256>>>(pxn, gq_w, gq_b, pq,  M, DD, DD, 0, 0);
    sgemm_kernel<<<dim3(DD / 128, M / 128), 256>>>(pxn, gk_w, gk_b, pkp, M, DD, DD, 0, 0);
    sgemm_kernel<<<dim3(DD / 128, M / 128), 256>>>(pxn, gv_w, gv_b, pvp, M, DD, DD, 0, 0);

    // 8) global attention
    global_attn_kernel<<<dim3(NDIL, HH, BB), 256, smGlb>>>(pq, pkp, pvp, pm, cosp, sinp, patt);

    // 9) O projection + residual
    sgemm_kernel<<<dim3(DD / 128, M / 128), 256>>>(patt, go_w, go_b, ptmp, M, DD, DD, 0, 0);
    add_mask4_kernel<<<(n4 + EW - 1) / EW, EW>>>(px, ptmp, pm, px, n4);

    // 10) FFN
    ln_kernel<<<M, 128>>>(px, ln3_g, ln3_b, pm, pxn, 0);
    sgemm_kernel<<<dim3(1024 / 128, M / 128), 256>>>(pxn, f1_w, f1_b, ph1, M, 1024, 512,  1, 0);
    sgemm_kernel<<<dim3(1024 / 128, M / 128), 256>>>(ph1, f2_w, f2_b, ph2, M, 1024, 1024, 1, 0);
    sgemm_kernel<<<dim3(DD / 128,  M / 128), 256>>>(ph2, f3_w, f3_b, ptmp, M, DD, 1024, 0, 0);

    // 11) out = (x + h) * mask
    add_mask4_kernel<<<(n4 + EW - 1) / EW, EW>>>(px, ptmp, pm, out, n4);
}

// round 4
// speedup vs baseline: 1.6328x; 1.6328x over previous
#include <cuda_runtime.h>
#include <cuda_bf16.h>
#include <math.h>
#include <stdint.h>

#define BB 8
#define TT 4096
#define DD 512
#define HH 8
#define HD 64
#define TP 4224   // T + 128 (padded for local attention)
#define NLOC 32   // T / 128
#define NDIL 64   // T / 64

// ---------------- scratch (static device memory; no allocs allowed) ----------------
__device__ float g_x  [BB*TT*DD];
__device__ float g_xn [BB*TT*DD];
__device__ float g_q  [BB*TT*DD];
__device__ float g_att[BB*TT*DD];
__device__ float g_tmp[BB*TT*DD];
__device__ float g_kp [BB*TP*DD];
__device__ float g_vp [BB*TP*DD];
__device__ float g_h1 [BB*TT*1024];
__device__ float g_h2 [BB*TT*1024];
__device__ float g_lcos[256*64];
__device__ float g_lsin[256*64];

// ---------------- helpers ----------------
__device__ __forceinline__ uint32_t smem_u32(const void* p) {
    uint32_t a;
    asm("{ .reg .u64 t; cvta.to.shared.u64 t, %1; cvt.u32.u64 %0, t; }" : "=r"(a) : "l"(p));
    return a;
}
__device__ __forceinline__ void ldsm4(uint32_t* r, uint32_t addr) {
    asm volatile("ldmatrix.sync.aligned.m8n8.x4.shared.b16 {%0,%1,%2,%3}, [%4];"
        : "=r"(r[0]), "=r"(r[1]), "=r"(r[2]), "=r"(r[3]) : "r"(addr));
}
__device__ __forceinline__ void mma_bf16(float* c, const uint32_t* a, uint32_t b0, uint32_t b1) {
    asm volatile("mma.sync.aligned.m16n8k16.row.col.f32.bf16.bf16.f32 "
        "{%0,%1,%2,%3}, {%4,%5,%6,%7}, {%8,%9}, {%0,%1,%2,%3};"
        : "+f"(c[0]), "+f"(c[1]), "+f"(c[2]), "+f"(c[3])
        : "r"(a[0]), "r"(a[1]), "r"(a[2]), "r"(a[3]), "r"(b0), "r"(b1));
}
// swizzle for 64-byte-row bf16 tiles: XOR 16B-block index with row bits 1-2
#define SWZ64(x) ((x) ^ (((x) >> 3) & 0x30))

__device__ __forceinline__ uint32_t packbf(__nv_bfloat16 a, __nv_bfloat16 b) {
    return (uint32_t)__bfloat16_as_ushort(a) | ((uint32_t)__bfloat16_as_ushort(b) << 16);
}
// convert fp32x4 -> bf16 hi tile + bf16 residual tile, store 8B each
__device__ __forceinline__ void cvt_store(char* base_h, char* base_l, uint32_t sx, float4 v) {
    __nv_bfloat16 bx = __float2bfloat16_rn(v.x), by = __float2bfloat16_rn(v.y);
    __nv_bfloat16 bz = __float2bfloat16_rn(v.z), bw = __float2bfloat16_rn(v.w);
    float lx = v.x - __bfloat162float(bx), ly = v.y - __bfloat162float(by);
    float lz = v.z - __bfloat162float(bz), lw = v.w - __bfloat162float(bw);
    uint2 h = make_uint2(packbf(bx, by), packbf(bz, bw));
    uint2 l = make_uint2(packbf(__float2bfloat16_rn(lx), __float2bfloat16_rn(ly)),
                         packbf(__float2bfloat16_rn(lz), __float2bfloat16_rn(lw)));
    *(uint2*)(base_h + sx) = h;
    *(uint2*)(base_l + sx) = l;
}

// ---------------- tensor-core GEMM via mma.sync (bf16 compensated split) ----------------
// C[M,N] = A[M,K] @ W[N,K]^T + bias, optional exact GELU, optional padded row scatter.
// CTA: 128x128 tile, 256 threads, BK=32 double-buffered.
// smem stage layout (32KB): Ah[128x32] @0, Al @8192, Wh @16384, Wl @24576. Two stages.
__global__ void __launch_bounds__(256, 1) gemm_mma_kernel(
    const float* __restrict__ A, const float* __restrict__ W,
    const float* __restrict__ bias, float* __restrict__ C,
    int K, int Nt, int act, int padOut)
{
    extern __shared__ char sm[];
    uint32_t smb = smem_u32(sm);
    int tid = threadIdx.x, lane = tid & 31, wid = tid >> 5;
    int row0 = blockIdx.y * 128, col0 = blockIdx.x * 128;
    int m0 = (wid & 3) * 32, n0 = (wid >> 2) * 64;

    float acc[2][8][4];
    #pragma unroll
    for (int i = 0; i < 2; i++)
        #pragma unroll
        for (int j = 0; j < 8; j++)
            #pragma unroll
            for (int c = 0; c < 4; c++) acc[i][j][c] = 0.0f;

    int q = tid & 7, r4 = tid >> 3;
    const float* Ap = A + (size_t)(row0 + r4) * K + q * 4;
    const float* Wp = W + (size_t)(col0 + r4) * K + q * 4;

    // ldmatrix fragment byte offsets within a tile (row*64 + colblock*16)
    uint32_t aoff[2], boff[4];
    #pragma unroll
    for (int i = 0; i < 2; i++) {
        int row = m0 + i * 16 + (lane & 15);
        aoff[i] = row * 64 + ((lane >> 4) << 4);
    }
    #pragma unroll
    for (int j = 0; j < 4; j++) {
        int row = n0 + j * 16 + (lane & 7) + ((lane >> 4) & 1) * 8;
        boff[j] = row * 64 + ((lane >> 3) & 1) * 16;
    }

    float4 ra[4], rw[4];
    #pragma unroll
    for (int p = 0; p < 4; p++) {
        ra[p] = *(const float4*)(Ap + (size_t)(p * 32) * K);
        rw[p] = *(const float4*)(Wp + (size_t)(p * 32) * K);
    }
    {
        char* stc = sm;
        #pragma unroll
        for (int p = 0; p < 4; p++) {
            uint32_t sx = SWZ64((uint32_t)((p * 32 + r4) * 64 + q * 8));
            cvt_store(stc,         stc + 8192,  sx, ra[p]);
            cvt_store(stc + 16384, stc + 24576, sx, rw[p]);
        }
    }
    __syncthreads();

    int nch = K >> 5;
    for (int ch = 0; ch < nch; ch++) {
        if (ch + 1 < nch) {
            const float* Ap2 = Ap + (ch + 1) * 32;
            const float* Wp2 = Wp + (ch + 1) * 32;
            #pragma unroll
            for (int p = 0; p < 4; p++) {
                ra[p] = *(const float4*)(Ap2 + (size_t)(p * 32) * K);
                rw[p] = *(const float4*)(Wp2 + (size_t)(p * 32) * K);
            }
        }
        uint32_t st = smb + (ch & 1) * 32768;
        #pragma unroll
        for (int ks = 0; ks < 2; ks++) {
            uint32_t ah[2][4], alr[2][4], bh[4][4], bl[4][4];
            #pragma unroll
            for (int i = 0; i < 2; i++) {
                uint32_t x = SWZ64(aoff[i] + ks * 32);
                ldsm4(ah[i],  st + x);
                ldsm4(alr[i], st + 8192 + x);
            }
            #pragma unroll
            for (int j = 0; j < 4; j++) {
                uint32_t x = SWZ64(boff[j] + ks * 32);
                ldsm4(bh[j], st + 16384 + x);
                ldsm4(bl[j], st + 24576 + x);
            }
            #pragma unroll
            for (int i = 0; i < 2; i++)
                #pragma unroll
                for (int j = 0; j < 4; j++) {
                    mma_bf16(acc[i][2*j],   ah[i],  bh[j][0], bh[j][1]);
                    mma_bf16(acc[i][2*j+1], ah[i],  bh[j][2], bh[j][3]);
                    mma_bf16(acc[i][2*j],   alr[i], bh[j][0], bh[j][1]);
                    mma_bf16(acc[i][2*j+1], alr[i], bh[j][2], bh[j][3]);
                    mma_bf16(acc[i][2*j],   ah[i],  bl[j][0], bl[j][1]);
                    mma_bf16(acc[i][2*j+1], ah[i],  bl[j][2], bl[j][3]);
                }
        }
        if (ch + 1 < nch) {
            char* stc = sm + ((ch + 1) & 1) * 32768;
            #pragma unroll
            for (int p = 0; p < 4; p++) {
                uint32_t sx = SWZ64((uint32_t)((p * 32 + r4) * 64 + q * 8));
                cvt_store(stc,         stc + 8192,  sx, ra[p]);
                cvt_store(stc + 16384, stc + 24576, sx, rw[p]);
            }
        }
        __syncthreads();
    }

    // epilogue
    int g = lane >> 2, t4 = lane & 3;
    #pragma unroll
    for (int mi = 0; mi < 2; mi++) {
        int r1 = row0 + m0 + mi * 16 + g;
        int r2 = r1 + 8;
        size_t o1 = padOut ? ((size_t)(r1 >> 12) * TP + 64 + (r1 & 4095)) : (size_t)r1;
        size_t o2 = padOut ? ((size_t)(r2 >> 12) * TP + 64 + (r2 & 4095)) : (size_t)r2;
        float* c1 = C + o1 * Nt;
        float* c2 = C + o2 * Nt;
        #pragma unroll
        for (int nj = 0; nj < 8; nj++) {
            int colG = col0 + n0 + nj * 8 + t4 * 2;
            float b0 = bias[colG], b1 = bias[colG + 1];
            float v0 = acc[mi][nj][0] + b0, v1 = acc[mi][nj][1] + b1;
            float v2 = acc[mi][nj][2] + b0, v3 = acc[mi][nj][3] + b1;
            if (act) {
                v0 = 0.5f * v0 * (1.0f + erff(v0 * 0.70710678118654752f));
                v1 = 0.5f * v1 * (1.0f + erff(v1 * 0.70710678118654752f));
                v2 = 0.5f * v2 * (1.0f + erff(v2 * 0.70710678118654752f));
                v3 = 0.5f * v3 * (1.0f + erff(v3 * 0.70710678118654752f));
            }
            float2 w1; w1.x = v0; w1.y = v1;
            float2 w2; w2.x = v2; w2.y = v3;
            *(float2*)(c1 + colG) = w1;
            *(float2*)(c2 + colG) = w2;
        }
    }
}

// ---------------- local rope tables: rope_tables(256, 64) in double ----------------
__global__ void rope_init_kernel() {
    int idx = blockIdx.x * blockDim.x + threadIdx.x;
    if (idx >= 256 * 64) return;
    int t = idx >> 6, d = idx & 63;
    double inv = pow(10000.0, -(double)(d & 31) / 32.0);
    double a = (double)t * inv;
    g_lcos[idx] = (float)cos(a);
    g_lsin[idx] = (float)sin(a);
}

// ---------------- elementwise (mask is int32/float32 words; nonzero = keep) ----------------
__global__ void mask_mul4_kernel(const float* __restrict__ X,
                                 const int* __restrict__ pm,
                                 float* __restrict__ Y, int n4) {
    int i = blockIdx.x * blockDim.x + threadIdx.x;
    if (i >= n4) return;
    float m = pm[i >> 7] ? 1.0f : 0.0f;
    float4 v = ((const float4*)X)[i];
    v.x *= m; v.y *= m; v.z *= m; v.w *= m;
    ((float4*)Y)[i] = v;
}

__global__ void add_mask4_kernel(const float* __restrict__ A,
                                 const float* __restrict__ Bv,
                                 const int* __restrict__ pm,
                                 float* __restrict__ Y, int n4) {
    int i = blockIdx.x * blockDim.x + threadIdx.x;
    if (i >= n4) return;
    float m = pm[i >> 7] ? 1.0f : 0.0f;
    float4 a = ((const float4*)A)[i];
    float4 b = ((const float4*)Bv)[i];
    float4 o;
    o.x = (a.x + b.x) * m; o.y = (a.y + b.y) * m;
    o.z = (a.z + b.z) * m; o.w = (a.w + b.w) * m;
    ((float4*)Y)[i] = o;
}

// ---------------- layernorm over 512, optional mask-multiply on output ----------------
__global__ void __launch_bounds__(128) ln_kernel(
    const float* __restrict__ X, const float* __restrict__ g,
    const float* __restrict__ b, const int* __restrict__ pm,
    float* __restrict__ Y, int maskOut)
{
    int row = blockIdx.x;
    int tid = threadIdx.x;  // 128
    const float4* x4 = (const float4*)(X + (size_t)row * DD);
    float4 v = x4[tid];
    float s  = v.x + v.y + v.z + v.w;
    float ss = v.x*v.x + v.y*v.y + v.z*v.z + v.w*v.w;
    #pragma unroll
    for (int o = 16; o; o >>= 1) {
        s  += __shfl_xor_sync(~0u, s,  o);
        ss += __shfl_xor_sync(~0u, ss, o);
    }
    __shared__ float sh[8];
    int w = tid >> 5, lane = tid & 31;
    if (lane == 0) { sh[w] = s; sh[4 + w] = ss; }
    __syncthreads();
    s  = sh[0] + sh[1] + sh[2] + sh[3];
    ss = sh[4] + sh[5] + sh[6] + sh[7];
    float mean = s * (1.0f / 512.0f);
    float var  = ss * (1.0f / 512.0f) - mean * mean;
    float inv  = rsqrtf(var + 1e-5f);
    float m = maskOut ? (pm[row] ? 1.0f : 0.0f) : 1.0f;
    float4 gg = ((const float4*)g)[tid];
    float4 bb = ((const float4*)b)[tid];
    float4 o;
    o.x = ((v.x - mean) * inv * gg.x + bb.x) * m;
    o.y = ((v.y - mean) * inv * gg.y + bb.y) * m;
    o.z = ((v.z - mean) * inv * gg.z + bb.z) * m;
    o.w = ((v.w - mean) * inv * gg.w + bb.w) * m;
    ((float4*)(Y + (size_t)row * DD))[tid] = o;
}

// ---------------- fill pad rows of padded K/V projections with bias ----------------
__global__ void fill_pad_kernel(const float* __restrict__ kb, const float* __restrict__ vb) {
    int idx = blockIdx.x * blockDim.x + threadIdx.x;
    if (idx >= BB * 128 * DD) return;
    int c  = idx & 511;
    int rr = (idx >> 9) & 127;
    int b  = idx >> 16;
    int prow = (rr < 64) ? rr : (TT + rr);
    size_t o = ((size_t)b * TP + prow) * DD + c;
    g_kp[o] = kb[c];
    g_vp[o] = vb[c];
}

// ---------------- local attention ----------------
#define LKS 68
#define LSS 257
__global__ void __launch_bounds__(256) local_attn_kernel(
    const float* __restrict__ Qg, const int* __restrict__ pm,
    float* __restrict__ Og)
{
    int j = blockIdx.x, h = blockIdx.y, b = blockIdx.z;
    extern __shared__ float smf[];
    float* Ks = smf;
    float* Vs = Ks + 256 * LKS;
    float* Qs = Vs + 256 * LKS;
    float* Ss = Qs + 32 * LKS;
    int*  keep = (int*)(Ss + 32 * LSS);
    int tid = threadIdx.x;

    for (int r0 = 0; r0 < 256; r0 += 4) {
        int r = r0 + (tid >> 6);
        int d = tid & 63;
        size_t base = ((size_t)b * TP + (size_t)j * 128 + r) * DD + h * HD;
        float kv = g_kp[base + d];
        float ko = g_kp[base + (d ^ 32)];
        float c = g_lcos[r * 64 + d], s = g_lsin[r * 64 + d];
        Ks[r * LKS + d] = (d < 32) ? (kv * c - ko * s) : (kv * c + ko * s);
        Vs[r * LKS + d] = g_vp[base + d];
    }
    if (tid < 256) {
        int orig = j * 128 + tid - 64;
        keep[tid] = (orig >= 0 && orig < TT && pm[(size_t)b * TT + orig]) ? 1 : 0;
    }
    __syncthreads();
    if (tid == 0) {
        int any = 0;
        for (int i = 0; i < 256; i++) any |= keep[i];
        if (!any) keep[0] = 1;
    }
    __syncthreads();

    for (int c0 = 0; c0 < 128; c0 += 32) {
        for (int r0 = 0; r0 < 32; r0 += 4) {
            int i = r0 + (tid >> 6);
            int d = tid & 63;
            int t = j * 128 + c0 + i;
            size_t base = ((size_t)b * TT + t) * DD + h * HD;
            float qv = Qg[base + d];
            float qo = Qg[base + (d ^ 32)];
            int ti = 64 + c0 + i;
            float c = g_lcos[ti * 64 + d], s = g_lsin[ti * 64 + d];
            Qs[i * LKS + d] = (d < 32) ? (qv * c - qo * s) : (qv * c + qo * s);
        }
        __syncthreads();

        {
            int qi = tid & 31;
            int kb = (tid >> 5) * 32;
            float acc[32];
            #pragma unroll
            for (int i = 0; i < 32; i++) acc[i] = 0.0f;
            for (int d0 = 0; d0 < 64; d0 += 16) {
                float qr[16];
                #pragma unroll
                for (int dd = 0; dd < 16; dd += 4) {
                    float4 qv = *(const float4*)&Qs[qi * LKS + d0 + dd];
                    qr[dd] = qv.x; qr[dd+1] = qv.y; qr[dd+2] = qv.z; qr[dd+3] = qv.w;
                }
                #pragma unroll 4
                for (int kk = 0; kk < 32; kk++) {
                    const float* kp = &Ks[(kb + kk) * LKS + d0];
                    #pragma unroll
                    for (int dd = 0; dd < 16; dd += 4) {
                        float4 kv = *(const float4*)(kp + dd);
                        acc[kk] += qr[dd] * kv.x + qr[dd+1] * kv.y
                                 + qr[dd+2] * kv.z + qr[dd+3] * kv.w;
                    }
                }
            }
            #pragma unroll
            for (int kk = 0; kk < 32; kk++) {
                int k = kb + kk;
                Ss[qi * LSS + k] = keep[k] ? acc[kk] * 0.125f : -1e9f;
            }
        }
        __syncthreads();

        {
            int wp = tid >> 5, lane = tid & 31;
            for (int rr = 0; rr < 4; rr++) {
                int r = wp * 4 + rr;
                float* row = Ss + r * LSS;
                float vals[8];
                float mx = -1e30f;
                #pragma unroll
                for (int m = 0; m < 8; m++) {
                    vals[m] = row[lane + 32 * m];
                    mx = fmaxf(mx, vals[m]);
                }
                #pragma unroll
                for (int o = 16; o; o >>= 1) mx = fmaxf(mx, __shfl_xor_sync(~0u, mx, o));
                float sum = 0.0f;
                #pragma unroll
                for (int m = 0; m < 8; m++) { vals[m] = expf(vals[m] - mx); sum += vals[m]; }
                #pragma unroll
                for (int o = 16; o; o >>= 1) sum += __shfl_xor_sync(~0u, sum, o);
                float inv = 1.0f / sum;
                #pragma unroll
                for (int m = 0; m < 8; m++) row[lane + 32 * m] = vals[m] * inv;
            }
        }
        __syncthreads();

        {
            int qi = tid & 31;
            int db = (tid >> 5) * 8;
            float acc[8];
            #pragma unroll
            for (int i = 0; i < 8; i++) acc[i] = 0.0f;
            #pragma unroll 4
            for (int k = 0; k < 256; k++) {
                float p = Ss[qi * LSS + k];
                float4 v0 = *(const float4*)&Vs[k * LKS + db];
                float4 v1 = *(const float4*)&Vs[k * LKS + db + 4];
                acc[0] += p * v0.x; acc[1] += p * v0.y;
                acc[2] += p * v0.z; acc[3] += p * v0.w;
                acc[4] += p * v1.x; acc[5] += p * v1.y;
                acc[6] += p * v1.z; acc[7] += p * v1.w;
            }
            int t = j * 128 + c0 + qi;
            size_t base = ((size_t)b * TT + t) * DD + h * HD + db;
            float4 o0, o1;
            o0.x = acc[0]; o0.y = acc[1]; o0.z = acc[2]; o0.w = acc[3];
            o1.x = acc[4]; o1.y = acc[5]; o1.z = acc[6]; o1.w = acc[7];
            *(float4*)(Og + base)     = o0;
            *(float4*)(Og + base + 4) = o1;
        }
        __syncthreads();
    }
}

// ---------------- global (dilated) attention ----------------
__global__ void __launch_bounds__(256) global_attn_kernel(
    const float* __restrict__ Qg, const float* __restrict__ Kg,
    const float* __restrict__ Vg, const int* __restrict__ pm,
    const float* __restrict__ cosp, const float* __restrict__ sinp,
    float* __restrict__ Og)
{
    int w = blockIdx.x, h = blockIdx.y, b = blockIdx.z;
    extern __shared__ float smf[];
    float* Qs = smf;
    float* Ks = Qs + 64 * LKS;
    float* Vs = Ks + 64 * LKS;
    float* Ss = Vs + 64 * LKS;
    int*  keep = (int*)(Ss + 64 * LSS);
    int tid = threadIdx.x;

    for (int r0 = 0; r0 < 64; r0 += 4) {
        int nn = r0 + (tid >> 6);
        int d = tid & 63;
        int p = nn * 64 + w;
        size_t base = ((size_t)b * TT + p) * DD + h * HD;
        float c = cosp[p * 64 + d], s = sinp[p * 64 + d];
        float qv = Qg[base + d], qo = Qg[base + (d ^ 32)];
        float kv = Kg[base + d], ko = Kg[base + (d ^ 32)];
        Qs[nn * LKS + d] = (d < 32) ? (qv * c - qo * s) : (qv * c + qo * s);
        Ks[nn * LKS + d] = (d < 32) ? (kv * c - ko * s) : (kv * c + ko * s);
        Vs[nn * LKS + d] = Vg[base + d];
    }
    if (tid < 64) keep[tid] = pm[(size_t)b * TT + tid * 64 + w] ? 1 : 0;
    __syncthreads();

    {
        int qi = tid & 63;
        int kb = (tid >> 6) * 16;
        float acc[16];
        #pragma unroll
        for (int i = 0; i < 16; i++) acc[i] = 0.0f;
        for (int d0 = 0; d0 < 64; d0 += 16) {
            float qr[16];
            #pragma unroll
            for (int dd = 0; dd < 16; dd += 4) {
                float4 qv = *(const float4*)&Qs[qi * LKS + d0 + dd];
                qr[dd] = qv.x; qr[dd+1] = qv.y; qr[dd+2] = qv.z; qr[dd+3] = qv.w;
            }
            #pragma unroll 4
            for (int kk = 0; kk < 16; kk++) {
                const float* kp = &Ks[(kb + kk) * LKS + d0];
                #pragma unroll
                for (int dd = 0; dd < 16; dd += 4) {
                    float4 kv = *(const float4*)(kp + dd);
                    acc[kk] += qr[dd] * kv.x + qr[dd+1] * kv.y
                             + qr[dd+2] * kv.z + qr[dd+3] * kv.w;
                }
            }
        }
        #pragma unroll
        for (int kk = 0; kk < 16; kk++) {
            int k = kb + kk;
            Ss[qi * LSS + k] = keep[k] ? acc[kk] * 0.125f : -1e9f;
        }
    }
    __syncthreads();

    {
        int wp = tid >> 5, lane = tid & 31;
        for (int rr = 0; rr < 8; rr++) {
            int r = wp * 8 + rr;
            float* row = Ss + r * LSS;
            float a0 = row[lane], a1 = row[lane + 32];
            float mx = fmaxf(a0, a1);
            #pragma unroll
            for (int o = 16; o; o >>= 1) mx = fmaxf(mx, __shfl_xor_sync(~0u, mx, o));
            float e0 = expf(a0 - mx), e1 = expf(a1 - mx);
            float sum = e0 + e1;
            #pragma unroll
            for (int o = 16; o; o >>= 1) sum += __shfl_xor_sync(~0u, sum, o);
            float inv = 1.0f / sum;
            row[lane] = e0 * inv; row[lane + 32] = e1 * inv;
        }
    }
    __syncthreads();

    {
        int qi = tid & 63;
        int db = (tid >> 6) * 16;
        float acc[16];
        #pragma unroll
        for (int i = 0; i < 16; i++) acc[i] = 0.0f;
        #pragma unroll 4
        for (int k = 0; k < 64; k++) {
            float p = Ss[qi * LSS + k];
            #pragma unroll
            for (int dd = 0; dd < 16; dd += 4) {
                float4 v = *(const float4*)&Vs[k * LKS + db + dd];
                acc[dd]   += p * v.x; acc[dd+1] += p * v.y;
                acc[dd+2] += p * v.z; acc[dd+3] += p * v.w;
            }
        }
        int p = qi * 64 + w;
        size_t base = ((size_t)b * TT + p) * DD + h * HD + db;
        #pragma unroll
        for (int dd = 0; dd < 16; dd += 4) {
            float4 o;
            o.x = acc[dd]; o.y = acc[dd+1]; o.z = acc[dd+2]; o.w = acc[dd+3];
            *(float4*)(Og + base + dd) = o;
        }
    }
}

// ---------------- host ----------------
extern "C" void kernel_launch(void* const* d_in, const int* in_sizes, int n_in,
                              void* d_out, int out_size)
{
    const float* x    = (const float*)d_in[0];
    const int*   pm   = (const int*)d_in[1];
    const float* cosp = (const float*)d_in[2];
    const float* sinp = (const float*)d_in[3];
    const float* ln1_g = (const float*)d_in[4];
    const float* ln1_b = (const float*)d_in[5];
    const float* ln2_g = (const float*)d_in[6];
    const float* ln2_b = (const float*)d_in[7];
    const float* ln3_g = (const float*)d_in[8];
    const float* ln3_b = (const float*)d_in[9];
    const float* lq_w = (const float*)d_in[10];
    const float* lq_b = (const float*)d_in[11];
    const float* lk_w = (const float*)d_in[12];
    const float* lk_b = (const float*)d_in[13];
    const float* lv_w = (const float*)d_in[14];
    const float* lv_b = (const float*)d_in[15];
    const float* lo_w = (const float*)d_in[16];
    const float* lo_b = (const float*)d_in[17];
    const float* gq_w = (const float*)d_in[18];
    const float* gq_b = (const float*)d_in[19];
    const float* gk_w = (const float*)d_in[20];
    const float* gk_b = (const float*)d_in[21];
    const float* gv_w = (const float*)d_in[22];
    const float* gv_b = (const float*)d_in[23];
    const float* go_w = (const float*)d_in[24];
    const float* go_b = (const float*)d_in[25];
    const float* f1_w = (const float*)d_in[26];
    const float* f1_b = (const float*)d_in[27];
    const float* f2_w = (const float*)d_in[28];
    const float* f2_b = (const float*)d_in[29];
    const float* f3_w = (const float*)d_in[30];
    const float* f3_b = (const float*)d_in[31];
    float* out = (float*)d_out;

    float *px, *pxn, *pq, *patt, *ptmp, *pkp, *pvp, *ph1, *ph2;
    cudaGetSymbolAddress((void**)&px,   g_x);
    cudaGetSymbolAddress((void**)&pxn,  g_xn);
    cudaGetSymbolAddress((void**)&pq,   g_q);
    cudaGetSymbolAddress((void**)&patt, g_att);
    cudaGetSymbolAddress((void**)&ptmp, g_tmp);
    cudaGetSymbolAddress((void**)&pkp,  g_kp);
    cudaGetSymbolAddress((void**)&pvp,  g_vp);
    cudaGetSymbolAddress((void**)&ph1,  g_h1);
    cudaGetSymbolAddress((void**)&ph2,  g_h2);

    const int M = BB * TT;
    const int n4 = M * DD / 4;
    const int EW = 256;

    size_t smLoc = (size_t)(2 * 256 * LKS + 32 * LKS + 32 * LSS) * 4 + 256 * 4;
    size_t smGlb = (size_t)(3 * 64 * LKS + 64 * LSS) * 4 + 64 * 4;
    cudaFuncSetAttribute(local_attn_kernel,  cudaFuncAttributeMaxDynamicSharedMemorySize, (int)smLoc);
    cudaFuncSetAttribute(global_attn_kernel, cudaFuncAttributeMaxDynamicSharedMemorySize, (int)smGlb);
    cudaFuncSetAttribute(gemm_mma_kernel, cudaFuncAttributeMaxDynamicSharedMemorySize, 65536);

    dim3 g512(DD / 128,  M / 128);     // (4, 256)
    dim3 g1k (1024 / 128, M / 128);    // (8, 256)

    rope_init_kernel<<<64, 256>>>();

    mask_mul4_kernel<<<(n4 + EW - 1) / EW, EW>>>(x, pm, px, n4);
    ln_kernel<<<M, 128>>>(px, ln1_g, ln1_b, pm, pxn, 1);

    gemm_mma_kernel<<<g512, 256, 65536>>>(pxn, lq_w, lq_b, pq,  DD, DD, 0, 0);
    gemm_mma_kernel<<<g512, 256, 65536>>>(pxn, lk_w, lk_b, pkp, DD, DD, 0, 1);
    gemm_mma_kernel<<<g512, 256, 65536>>>(pxn, lv_w, lv_b, pvp, DD, DD, 0, 1);
    fill_pad_kernel<<<(BB * 128 * DD + EW - 1) / EW, EW>>>(lk_b, lv_b);

    local_attn_kernel<<<dim3(NLOC, HH, BB), 256, smLoc>>>(pq, pm, patt);

    gemm_mma_kernel<<<g512, 256, 65536>>>(patt, lo_w, lo_b, ptmp, DD, DD, 0, 0);
    add_mask4_kernel<<<(n4 + EW - 1) / EW, EW>>>(px, ptmp, pm, px, n4);

    ln_kernel<<<M, 128>>>(px, ln2_g, ln2_b, pm, pxn, 0);

    gemm_mma_kernel<<<g512, 256, 65536>>>(pxn, gq_w, gq_b, pq,  DD, DD, 0, 0);
    gemm_mma_kernel<<<g512, 256, 65536>>>(pxn, gk_w, gk_b, pkp, DD, DD, 0, 0);
    gemm_mma_kernel<<<g512, 256, 65536>>>(pxn, gv_w, gv_b, pvp, DD, DD, 0, 0);

    global_attn_kernel<<<dim3(NDIL, HH, BB), 256, smGlb>>>(pq, pkp, pvp, pm, cosp, sinp, patt);

    gemm_mma_kernel<<<g512, 256, 65536>>>(patt, go_w, go_b, ptmp, DD, DD, 0, 0);
    add_mask4_kernel<<<(n4 + EW - 1) / EW, EW>>>(px, ptmp, pm, px, n4);

    ln_kernel<<<M, 128>>>(px, ln3_g, ln3_b, pm, pxn, 0);
    gemm_mma_kernel<<<g1k,  256, 65536>>>(pxn, f1_w, f1_b, ph1, 512,  1024, 1, 0);
    gemm_mma_kernel<<<g1k,  256, 65536>>>(ph1, f2_w, f2_b, ph2, 1024, 1024, 1, 0);
    gemm_mma_kernel<<<g512, 256, 65536>>>(ph2, f3_w, f3_b, ptmp, 1024, 512,  0, 0);

    add_mask4_kernel<<<(n4 + EW - 1) / EW, EW>>>(px, ptmp, pm, out, n4);
}

// round 5
// speedup vs baseline: 1.8130x; 1.1104x over previous
#include <cuda_runtime.h>
#include <cuda_bf16.h>
#include <math.h>
#include <stdint.h>

#define BB 8
#define TT 4096
#define DD 512
#define HH 8
#define HD 64
#define TP 4224
#define NLOC 32
#define NDIL 64

// ---------------- scratch ----------------
__device__ float g_x  [BB*TT*DD];
__device__ float g_q  [BB*TT*DD];
__device__ float g_tmp[BB*TT*DD];
__device__ float g_kp [BB*TP*DD];
__device__ float g_vp [BB*TP*DD];
__device__ __nv_bfloat16 g_xnh [BB*TT*DD];
__device__ __nv_bfloat16 g_xnl [BB*TT*DD];
__device__ __nv_bfloat16 g_atth[BB*TT*DD];
__device__ __nv_bfloat16 g_attl[BB*TT*DD];
__device__ __nv_bfloat16 g_h1h [BB*TT*1024];
__device__ __nv_bfloat16 g_h1l [BB*TT*1024];
__device__ __nv_bfloat16 g_h2h [BB*TT*1024];
__device__ __nv_bfloat16 g_h2l [BB*TT*1024];
__device__ __nv_bfloat16 g_wh  [4194304];
__device__ __nv_bfloat16 g_wl  [4194304];
__device__ float g_lcos[256*64];
__device__ float g_lsin[256*64];

// ---------------- helpers ----------------
__device__ __forceinline__ uint32_t smem_u32(const void* p) {
    uint32_t a;
    asm("{ .reg .u64 t; cvta.to.shared.u64 t, %1; cvt.u32.u64 %0, t; }" : "=r"(a) : "l"(p));
    return a;
}
__device__ __forceinline__ void ldsm4(uint32_t* r, uint32_t addr) {
    asm volatile("ldmatrix.sync.aligned.m8n8.x4.shared.b16 {%0,%1,%2,%3}, [%4];"
        : "=r"(r[0]), "=r"(r[1]), "=r"(r[2]), "=r"(r[3]) : "r"(addr));
}
__device__ __forceinline__ void mma_bf16(float* c, const uint32_t* a, uint32_t b0, uint32_t b1) {
    asm volatile("mma.sync.aligned.m16n8k16.row.col.f32.bf16.bf16.f32 "
        "{%0,%1,%2,%3}, {%4,%5,%6,%7}, {%8,%9}, {%0,%1,%2,%3};"
        : "+f"(c[0]), "+f"(c[1]), "+f"(c[2]), "+f"(c[3])
        : "r"(a[0]), "r"(a[1]), "r"(a[2]), "r"(a[3]), "r"(b0), "r"(b1));
}
#define SWZ64(x) ((x) ^ (((x) >> 3) & 0x30))
#define CPA(dst, src) asm volatile("cp.async.cg.shared.global [%0], [%1], 16;" :: "r"(dst), "l"(src))
#define CPC() asm volatile("cp.async.commit_group;" ::: "memory")
#define CPW(n) asm volatile("cp.async.wait_group %0;" :: "n"(n) : "memory")

__device__ __forceinline__ uint32_t packbf(__nv_bfloat16 a, __nv_bfloat16 b) {
    return (uint32_t)__bfloat16_as_ushort(a) | ((uint32_t)__bfloat16_as_ushort(b) << 16);
}
// split fp32x4 -> bf16 hi uint2 + bf16 lo uint2
__device__ __forceinline__ void split4(float4 v, uint2& h, uint2& l) {
    __nv_bfloat16 bx = __float2bfloat16_rn(v.x), by = __float2bfloat16_rn(v.y);
    __nv_bfloat16 bz = __float2bfloat16_rn(v.z), bw = __float2bfloat16_rn(v.w);
    h.x = packbf(bx, by); h.y = packbf(bz, bw);
    l.x = packbf(__float2bfloat16_rn(v.x - __bfloat162float(bx)),
                 __float2bfloat16_rn(v.y - __bfloat162float(by)));
    l.y = packbf(__float2bfloat16_rn(v.z - __bfloat162float(bz)),
                 __float2bfloat16_rn(v.w - __bfloat162float(bw)));
}

// ---------------- GEMM: C[M,N] = A @ W^T + bias; A,W pre-split bf16 hi/lo ----------------
// CTA 128x128, 512 threads (16 warps, warp tile 32x32), BK=32, 3-stage cp.async ring.
__global__ void __launch_bounds__(512, 1) gemm_mma_kernel(
    const __nv_bfloat16* __restrict__ Ah, const __nv_bfloat16* __restrict__ Al,
    const __nv_bfloat16* __restrict__ Wh, const __nv_bfloat16* __restrict__ Wl,
    const float* __restrict__ bias,
    float* __restrict__ Cf, __nv_bfloat16* __restrict__ Ch, __nv_bfloat16* __restrict__ Cl,
    int K, int Nt, int act, int padOut, int outBf)
{
    extern __shared__ char sm[];
    uint32_t smb = smem_u32(sm);
    int tid = threadIdx.x, lane = tid & 31, wid = tid >> 5;
    int row0 = blockIdx.y * 128, col0 = blockIdx.x * 128;
    int wm = (wid & 3) * 32, wn = (wid >> 2) * 32;

    float acc[2][4][4];
    #pragma unroll
    for (int i = 0; i < 2; i++)
        #pragma unroll
        for (int j = 0; j < 4; j++)
            #pragma unroll
            for (int c = 0; c < 4; c++) acc[i][j][c] = 0.0f;

    int srow = tid >> 2, sc16 = tid & 3;
    uint32_t sdst = SWZ64((uint32_t)(srow * 64 + sc16 * 16));
    size_t gA = (size_t)(row0 + srow) * K + sc16 * 8;
    size_t gW = (size_t)(col0 + srow) * K + sc16 * 8;

    uint32_t aoff[2], boff[2];
    #pragma unroll
    for (int i = 0; i < 2; i++) {
        int r = wm + i * 16 + (lane & 15);
        aoff[i] = r * 64 + ((lane >> 4) << 4);
    }
    #pragma unroll
    for (int j = 0; j < 2; j++) {
        int r = wn + j * 16 + (lane & 7) + ((lane >> 4) & 1) * 8;
        boff[j] = r * 64 + (((lane >> 3) & 1) << 4);
    }

    int nch = K >> 5;
    #define G_ISSUE(ch) { \
        uint32_t st_ = smb + ((ch) % 3) * 32768; \
        size_t k0_ = (size_t)(ch) * 32; \
        CPA(st_ + sdst,          Ah + gA + k0_); \
        CPA(st_ + 8192 + sdst,   Al + gA + k0_); \
        CPA(st_ + 16384 + sdst,  Wh + gW + k0_); \
        CPA(st_ + 24576 + sdst,  Wl + gW + k0_); \
        CPC(); }

    G_ISSUE(0);
    if (nch > 1) G_ISSUE(1);

    for (int ch = 0; ch < nch; ch++) {
        if (ch + 1 < nch) { CPW(1); } else { CPW(0); }
        __syncthreads();
        if (ch + 2 < nch) G_ISSUE(ch + 2);
        uint32_t st = smb + (ch % 3) * 32768;
        #pragma unroll
        for (int ks = 0; ks < 2; ks++) {
            uint32_t ah[2][4], al[2][4], bh[2][4], bl[2][4];
            #pragma unroll
            for (int i = 0; i < 2; i++) {
                uint32_t x = SWZ64(aoff[i] + ks * 32);
                ldsm4(ah[i], st + x);
                ldsm4(al[i], st + 8192 + x);
            }
            #pragma unroll
            for (int j = 0; j < 2; j++) {
                uint32_t x = SWZ64(boff[j] + ks * 32);
                ldsm4(bh[j], st + 16384 + x);
                ldsm4(bl[j], st + 24576 + x);
            }
            #pragma unroll
            for (int i = 0; i < 2; i++)
                #pragma unroll
                for (int j = 0; j < 2; j++) {
                    mma_bf16(acc[i][2*j],   ah[i], bh[j][0], bh[j][1]);
                    mma_bf16(acc[i][2*j+1], ah[i], bh[j][2], bh[j][3]);
                    mma_bf16(acc[i][2*j],   al[i], bh[j][0], bh[j][1]);
                    mma_bf16(acc[i][2*j+1], al[i], bh[j][2], bh[j][3]);
                    mma_bf16(acc[i][2*j],   ah[i], bl[j][0], bl[j][1]);
                    mma_bf16(acc[i][2*j+1], ah[i], bl[j][2], bl[j][3]);
                }
        }
    }

    // epilogue
    int g = lane >> 2, t4 = lane & 3;
    #pragma unroll
    for (int i = 0; i < 2; i++) {
        int r1 = row0 + wm + i * 16 + g;
        int r2 = r1 + 8;
        #pragma unroll
        for (int nj = 0; nj < 4; nj++) {
            int colG = col0 + wn + nj * 8 + t4 * 2;
            float b0 = bias[colG], b1 = bias[colG + 1];
            float v0 = acc[i][nj][0] + b0, v1 = acc[i][nj][1] + b1;
            float v2 = acc[i][nj][2] + b0, v3 = acc[i][nj][3] + b1;
            if (act) {
                v0 = 0.5f * v0 * (1.0f + erff(v0 * 0.70710678118654752f));
                v1 = 0.5f * v1 * (1.0f + erff(v1 * 0.70710678118654752f));
                v2 = 0.5f * v2 * (1.0f + erff(v2 * 0.70710678118654752f));
                v3 = 0.5f * v3 * (1.0f + erff(v3 * 0.70710678118654752f));
            }
            if (outBf) {
                __nv_bfloat16 h0 = __float2bfloat16_rn(v0), h1 = __float2bfloat16_rn(v1);
                __nv_bfloat16 h2 = __float2bfloat16_rn(v2), h3 = __float2bfloat16_rn(v3);
                uint32_t lw0 = packbf(__float2bfloat16_rn(v0 - __bfloat162float(h0)),
                                      __float2bfloat16_rn(v1 - __bfloat162float(h1)));
                uint32_t lw1 = packbf(__float2bfloat16_rn(v2 - __bfloat162float(h2)),
                                      __float2bfloat16_rn(v3 - __bfloat162float(h3)));
                *(uint32_t*)(Ch + (size_t)r1 * Nt + colG) = packbf(h0, h1);
                *(uint32_t*)(Cl + (size_t)r1 * Nt + colG) = lw0;
                *(uint32_t*)(Ch + (size_t)r2 * Nt + colG) = packbf(h2, h3);
                *(uint32_t*)(Cl + (size_t)r2 * Nt + colG) = lw1;
            } else {
                size_t o1 = padOut ? ((size_t)(r1 >> 12) * TP + 64 + (r1 & 4095)) : (size_t)r1;
                size_t o2 = padOut ? ((size_t)(r2 >> 12) * TP + 64 + (r2 & 4095)) : (size_t)r2;
                float2 w1; w1.x = v0; w1.y = v1;
                float2 w2; w2.x = v2; w2.y = v3;
                *(float2*)(Cf + o1 * Nt + colG) = w1;
                *(float2*)(Cf + o2 * Nt + colG) = w2;
            }
        }
    }
}

// ---------------- weight split kernel ----------------
struct WPtrs { const float* p[11]; };
__global__ void cvt_w_kernel(WPtrs wp) {
    const int sizes[11] = {262144,262144,262144,262144,262144,262144,262144,262144,
                           524288,1048576,524288};
    const int offs[11]  = {0,262144,524288,786432,1048576,1310720,1572864,1835008,
                           2097152,2621440,3670016};
    int wi = blockIdx.y;
    int i4 = blockIdx.x * blockDim.x + threadIdx.x;
    if (i4 >= (sizes[wi] >> 2)) return;
    float4 v = ((const float4*)wp.p[wi])[i4];
    uint2 h, l;
    split4(v, h, l);
    ((uint2*)(g_wh + offs[wi]))[i4] = h;
    ((uint2*)(g_wl + offs[wi]))[i4] = l;
}

// ---------------- local rope tables ----------------
__global__ void rope_init_kernel() {
    int idx = blockIdx.x * blockDim.x + threadIdx.x;
    if (idx >= 256 * 64) return;
    int t = idx >> 6, d = idx & 63;
    double inv = pow(10000.0, -(double)(d & 31) / 32.0);
    double a = (double)t * inv;
    g_lcos[idx] = (float)cos(a);
    g_lsin[idx] = (float)sin(a);
}

// ---------------- elementwise ----------------
__global__ void mask_mul4_kernel(const float* __restrict__ X,
                                 const int* __restrict__ pm,
                                 float* __restrict__ Y, int n4) {
    int i = blockIdx.x * blockDim.x + threadIdx.x;
    if (i >= n4) return;
    float m = pm[i >> 7] ? 1.0f : 0.0f;
    float4 v = ((const float4*)X)[i];
    v.x *= m; v.y *= m; v.z *= m; v.w *= m;
    ((float4*)Y)[i] = v;
}

__global__ void add_mask4_kernel(const float* __restrict__ A,
                                 const float* __restrict__ Bv,
                                 const int* __restrict__ pm,
                                 float* __restrict__ Y, int n4) {
    int i = blockIdx.x * blockDim.x + threadIdx.x;
    if (i >= n4) return;
    float m = pm[i >> 7] ? 1.0f : 0.0f;
    float4 a = ((const float4*)A)[i];
    float4 b = ((const float4*)Bv)[i];
    float4 o;
    o.x = (a.x + b.x) * m; o.y = (a.y + b.y) * m;
    o.z = (a.z + b.z) * m; o.w = (a.w + b.w) * m;
    ((float4*)Y)[i] = o;
}

// ---------------- layernorm -> bf16 hi/lo ----------------
__global__ void __launch_bounds__(128) ln_kernel(
    const float* __restrict__ X, const float* __restrict__ g,
    const float* __restrict__ b, const int* __restrict__ pm,
    __nv_bfloat16* __restrict__ Yh, __nv_bfloat16* __restrict__ Yl, int maskOut)
{
    int row = blockIdx.x;
    int tid = threadIdx.x;
    const float4* x4 = (const float4*)(X + (size_t)row * DD);
    float4 v = x4[tid];
    float s  = v.x + v.y + v.z + v.w;
    float ss = v.x*v.x + v.y*v.y + v.z*v.z + v.w*v.w;
    #pragma unroll
    for (int o = 16; o; o >>= 1) {
        s  += __shfl_xor_sync(~0u, s,  o);
        ss += __shfl_xor_sync(~0u, ss, o);
    }
    __shared__ float sh[8];
    int w = tid >> 5, lane = tid & 31;
    if (lane == 0) { sh[w] = s; sh[4 + w] = ss; }
    __syncthreads();
    s  = sh[0] + sh[1] + sh[2] + sh[3];
    ss = sh[4] + sh[5] + sh[6] + sh[7];
    float mean = s * (1.0f / 512.0f);
    float var  = ss * (1.0f / 512.0f) - mean * mean;
    float inv  = rsqrtf(var + 1e-5f);
    float m = maskOut ? (pm[row] ? 1.0f : 0.0f) : 1.0f;
    float4 gg = ((const float4*)g)[tid];
    float4 bb = ((const float4*)b)[tid];
    float4 o;
    o.x = ((v.x - mean) * inv * gg.x + bb.x) * m;
    o.y = ((v.y - mean) * inv * gg.y + bb.y) * m;
    o.z = ((v.z - mean) * inv * gg.z + bb.z) * m;
    o.w = ((v.w - mean) * inv * gg.w + bb.w) * m;
    uint2 h, l;
    split4(o, h, l);
    ((uint2*)(Yh + (size_t)row * DD))[tid] = h;
    ((uint2*)(Yl + (size_t)row * DD))[tid] = l;
}

// ---------------- fill pad rows ----------------
__global__ void fill_pad_kernel(const float* __restrict__ kb, const float* __restrict__ vb) {
    int idx = blockIdx.x * blockDim.x + threadIdx.x;
    if (idx >= BB * 128 * DD) return;
    int c  = idx & 511;
    int rr = (idx >> 9) & 127;
    int b  = idx >> 16;
    int prow = (rr < 64) ? rr : (TT + rr);
    size_t o = ((size_t)b * TP + prow) * DD + c;
    g_kp[o] = kb[c];
    g_vp[o] = vb[c];
}

// ---------------- local attention (out: bf16 hi/lo) ----------------
#define LKS 68
#define LSS 257
__global__ void __launch_bounds__(256) local_attn_kernel(
    const float* __restrict__ Qg, const int* __restrict__ pm,
    __nv_bfloat16* __restrict__ Oh, __nv_bfloat16* __restrict__ Ol)
{
    int j = blockIdx.x, h = blockIdx.y, b = blockIdx.z;
    extern __shared__ float smf[];
    float* Ks = smf;
    float* Vs = Ks + 256 * LKS;
    float* Qs = Vs + 256 * LKS;
    float* Ss = Qs + 32 * LKS;
    int*  keep = (int*)(Ss + 32 * LSS);
    int tid = threadIdx.x;

    for (int r0 = 0; r0 < 256; r0 += 4) {
        int r = r0 + (tid >> 6);
        int d = tid & 63;
        size_t base = ((size_t)b * TP + (size_t)j * 128 + r) * DD + h * HD;
        float kv = g_kp[base + d];
        float ko = g_kp[base + (d ^ 32)];
        float c = g_lcos[r * 64 + d], s = g_lsin[r * 64 + d];
        Ks[r * LKS + d] = (d < 32) ? (kv * c - ko * s) : (kv * c + ko * s);
        Vs[r * LKS + d] = g_vp[base + d];
    }
    if (tid < 256) {
        int orig = j * 128 + tid - 64;
        keep[tid] = (orig >= 0 && orig < TT && pm[(size_t)b * TT + orig]) ? 1 : 0;
    }
    __syncthreads();
    if (tid == 0) {
        int any = 0;
        for (int i = 0; i < 256; i++) any |= keep[i];
        if (!any) keep[0] = 1;
    }
    __syncthreads();

    for (int c0 = 0; c0 < 128; c0 += 32) {
        for (int r0 = 0; r0 < 32; r0 += 4) {
            int i = r0 + (tid >> 6);
            int d = tid & 63;
            int t = j * 128 + c0 + i;
            size_t base = ((size_t)b * TT + t) * DD + h * HD;
            float qv = Qg[base + d];
            float qo = Qg[base + (d ^ 32)];
            int ti = 64 + c0 + i;
            float c = g_lcos[ti * 64 + d], s = g_lsin[ti * 64 + d];
            Qs[i * LKS + d] = (d < 32) ? (qv * c - qo * s) : (qv * c + qo * s);
        }
        __syncthreads();

        {
            int qi = tid & 31;
            int kb = (tid >> 5) * 32;
            float acc[32];
            #pragma unroll
            for (int i = 0; i < 32; i++) acc[i] = 0.0f;
            for (int d0 = 0; d0 < 64; d0 += 16) {
                float qr[16];
                #pragma unroll
                for (int dd = 0; dd < 16; dd += 4) {
                    float4 qv = *(const float4*)&Qs[qi * LKS + d0 + dd];
                    qr[dd] = qv.x; qr[dd+1] = qv.y; qr[dd+2] = qv.z; qr[dd+3] = qv.w;
                }
                #pragma unroll 4
                for (int kk = 0; kk < 32; kk++) {
                    const float* kp = &Ks[(kb + kk) * LKS + d0];
                    #pragma unroll
                    for (int dd = 0; dd < 16; dd += 4) {
                        float4 kv = *(const float4*)(kp + dd);
                        acc[kk] += qr[dd] * kv.x + qr[dd+1] * kv.y
                                 + qr[dd+2] * kv.z + qr[dd+3] * kv.w;
                    }
                }
            }
            #pragma unroll
            for (int kk = 0; kk < 32; kk++) {
                int k = kb + kk;
                Ss[qi * LSS + k] = keep[k] ? acc[kk] * 0.125f : -1e9f;
            }
        }
        __syncthreads();

        {
            int wp = tid >> 5, lane = tid & 31;
            for (int rr = 0; rr < 4; rr++) {
                int r = wp * 4 + rr;
                float* row = Ss + r * LSS;
                float vals[8];
                float mx = -1e30f;
                #pragma unroll
                for (int m = 0; m < 8; m++) {
                    vals[m] = row[lane + 32 * m];
                    mx = fmaxf(mx, vals[m]);
                }
                #pragma unroll
                for (int o = 16; o; o >>= 1) mx = fmaxf(mx, __shfl_xor_sync(~0u, mx, o));
                float sum = 0.0f;
                #pragma unroll
                for (int m = 0; m < 8; m++) { vals[m] = expf(vals[m] - mx); sum += vals[m]; }
                #pragma unroll
                for (int o = 16; o; o >>= 1) sum += __shfl_xor_sync(~0u, sum, o);
                float inv = 1.0f / sum;
                #pragma unroll
                for (int m = 0; m < 8; m++) row[lane + 32 * m] = vals[m] * inv;
            }
        }
        __syncthreads();

        {
            int qi = tid & 31;
            int db = (tid >> 5) * 8;
            float acc[8];
            #pragma unroll
            for (int i = 0; i < 8; i++) acc[i] = 0.0f;
            #pragma unroll 4
            for (int k = 0; k < 256; k++) {
                float p = Ss[qi * LSS + k];
                float4 v0 = *(const float4*)&Vs[k * LKS + db];
                float4 v1 = *(const float4*)&Vs[k * LKS + db + 4];
                acc[0] += p * v0.x; acc[1] += p * v0.y;
                acc[2] += p * v0.z; acc[3] += p * v0.w;
                acc[4] += p * v1.x; acc[5] += p * v1.y;
                acc[6] += p * v1.z; acc[7] += p * v1.w;
            }
            int t = j * 128 + c0 + qi;
            size_t base = ((size_t)b * TT + t) * DD + h * HD + db;
            float4 p0; p0.x = acc[0]; p0.y = acc[1]; p0.z = acc[2]; p0.w = acc[3];
            float4 p1; p1.x = acc[4]; p1.y = acc[5]; p1.z = acc[6]; p1.w = acc[7];
            uint2 h0, l0, h1, l1;
            split4(p0, h0, l0); split4(p1, h1, l1);
            *(uint2*)(Oh + base)     = h0;
            *(uint2*)(Oh + base + 4) = h1;
            *(uint2*)(Ol + base)     = l0;
            *(uint2*)(Ol + base + 4) = l1;
        }
        __syncthreads();
    }
}

// ---------------- global attention (out: bf16 hi/lo) ----------------
__global__ void __launch_bounds__(256) global_attn_kernel(
    const float* __restrict__ Qg, const float* __restrict__ Kg,
    const float* __restrict__ Vg, const int* __restrict__ pm,
    const float* __restrict__ cosp, const float* __restrict__ sinp,
    __nv_bfloat16* __restrict__ Oh, __nv_bfloat16* __restrict__ Ol)
{
    int w = blockIdx.x, h = blockIdx.y, b = blockIdx.z;
    extern __shared__ float smf[];
    float* Qs = smf;
    float* Ks = Qs + 64 * LKS;
    float* Vs = Ks + 64 * LKS;
    float* Ss = Vs + 64 * LKS;
    int*  keep = (int*)(Ss + 64 * LSS);
    int tid = threadIdx.x;

    for (int r0 = 0; r0 < 64; r0 += 4) {
        int nn = r0 + (tid >> 6);
        int d = tid & 63;
        int p = nn * 64 + w;
        size_t base = ((size_t)b * TT + p) * DD + h * HD;
        float c = cosp[p * 64 + d], s = sinp[p * 64 + d];
        float qv = Qg[base + d], qo = Qg[base + (d ^ 32)];
        float kv = Kg[base + d], ko = Kg[base + (d ^ 32)];
        Qs[nn * LKS + d] = (d < 32) ? (qv * c - qo * s) : (qv * c + qo * s);
        Ks[nn * LKS + d] = (d < 32) ? (kv * c - ko * s) : (kv * c + ko * s);
        Vs[nn * LKS + d] = Vg[base + d];
    }
    if (tid < 64) keep[tid] = pm[(size_t)b * TT + tid * 64 + w] ? 1 : 0;
    __syncthreads();

    {
        int qi = tid & 63;
        int kb = (tid >> 6) * 16;
        float acc[16];
        #pragma unroll
        for (int i = 0; i < 16; i++) acc[i] = 0.0f;
        for (int d0 = 0; d0 < 64; d0 += 16) {
            float qr[16];
            #pragma unroll
            for (int dd = 0; dd < 16; dd += 4) {
                float4 qv = *(const float4*)&Qs[qi * LKS + d0 + dd];
                qr[dd] = qv.x; qr[dd+1] = qv.y; qr[dd+2] = qv.z; qr[dd+3] = qv.w;
            }
            #pragma unroll 4
            for (int kk = 0; kk < 16; kk++) {
                const float* kp = &Ks[(kb + kk) * LKS + d0];
                #pragma unroll
                for (int dd = 0; dd < 16; dd += 4) {
                    float4 kv = *(const float4*)(kp + dd);
                    acc[kk] += qr[dd] * kv.x + qr[dd+1] * kv.y
                             + qr[dd+2] * kv.z + qr[dd+3] * kv.w;
                }
            }
        }
        #pragma unroll
        for (int kk = 0; kk < 16; kk++) {
            int k = kb + kk;
            Ss[qi * LSS + k] = keep[k] ? acc[kk] * 0.125f : -1e9f;
        }
    }
    __syncthreads();

    {
        int wp = tid >> 5, lane = tid & 31;
        for (int rr = 0; rr < 8; rr++) {
            int r = wp * 8 + rr;
            float* row = Ss + r * LSS;
            float a0 = row[lane], a1 = row[lane + 32];
            float mx = fmaxf(a0, a1);
            #pragma unroll
            for (int o = 16; o; o >>= 1) mx = fmaxf(mx, __shfl_xor_sync(~0u, mx, o));
            float e0 = expf(a0 - mx), e1 = expf(a1 - mx);
            float sum = e0 + e1;
            #pragma unroll
            for (int o = 16; o; o >>= 1) sum += __shfl_xor_sync(~0u, sum, o);
            float inv = 1.0f / sum;
            row[lane] = e0 * inv; row[lane + 32] = e1 * inv;
        }
    }
    __syncthreads();

    {
        int qi = tid & 63;
        int db = (tid >> 6) * 16;
        float acc[16];
        #pragma unroll
        for (int i = 0; i < 16; i++) acc[i] = 0.0f;
        #pragma unroll 4
        for (int k = 0; k < 64; k++) {
            float p = Ss[qi * LSS + k];
            #pragma unroll
            for (int dd = 0; dd < 16; dd += 4) {
                float4 v = *(const float4*)&Vs[k * LKS + db + dd];
                acc[dd]   += p * v.x; acc[dd+1] += p * v.y;
                acc[dd+2] += p * v.z; acc[dd+3] += p * v.w;
            }
        }
        int p = qi * 64 + w;
        size_t base = ((size_t)b * TT + p) * DD + h * HD + db;
        #pragma unroll
        for (int dd = 0; dd < 16; dd += 4) {
            float4 pv;
            pv.x = acc[dd]; pv.y = acc[dd+1]; pv.z = acc[dd+2]; pv.w = acc[dd+3];
            uint2 hq, lq;
            split4(pv, hq, lq);
            *(uint2*)(Oh + base + dd) = hq;
            *(uint2*)(Ol + base + dd) = lq;
        }
    }
}

// ---------------- host ----------------
extern "C" void kernel_launch(void* const* d_in, const int* in_sizes, int n_in,
                              void* d_out, int out_size)
{
    const float* x    = (const float*)d_in[0];
    const int*   pm   = (const int*)d_in[1];
    const float* cosp = (const float*)d_in[2];
    const float* sinp = (const float*)d_in[3];
    const float* ln1_g = (const float*)d_in[4];
    const float* ln1_b = (const float*)d_in[5];
    const float* ln2_g = (const float*)d_in[6];
    const float* ln2_b = (const float*)d_in[7];
    const float* ln3_g = (const float*)d_in[8];
    const float* ln3_b = (const float*)d_in[9];
    const float* lq_w = (const float*)d_in[10];
    const float* lq_b = (const float*)d_in[11];
    const float* lk_w = (const float*)d_in[12];
    const float* lk_b = (const float*)d_in[13];
    const float* lv_w = (const float*)d_in[14];
    const float* lv_b = (const float*)d_in[15];
    const float* lo_w = (const float*)d_in[16];
    const float* lo_b = (const float*)d_in[17];
    const float* gq_w = (const float*)d_in[18];
    const float* gq_b = (const float*)d_in[19];
    const float* gk_w = (const float*)d_in[20];
    const float* gk_b = (const float*)d_in[21];
    const float* gv_w = (const float*)d_in[22];
    const float* gv_b = (const float*)d_in[23];
    const float* go_w = (const float*)d_in[24];
    const float* go_b = (const float*)d_in[25];
    const float* f1_w = (const float*)d_in[26];
    const float* f1_b = (const float*)d_in[27];
    const float* f2_w = (const float*)d_in[28];
    const float* f2_b = (const float*)d_in[29];
    const float* f3_w = (const float*)d_in[30];
    const float* f3_b = (const float*)d_in[31];
    float* out = (float*)d_out;

    float *px, *pq, *ptmp, *pkp, *pvp, *plc;
    __nv_bfloat16 *pxnh, *pxnl, *patth, *pattl, *ph1h, *ph1l, *ph2h, *ph2l, *pwh, *pwl;
    cudaGetSymbolAddress((void**)&px,    g_x);
    cudaGetSymbolAddress((void**)&pq,    g_q);
    cudaGetSymbolAddress((void**)&ptmp,  g_tmp);
    cudaGetSymbolAddress((void**)&pkp,   g_kp);
    cudaGetSymbolAddress((void**)&pvp,   g_vp);
    cudaGetSymbolAddress((void**)&plc,   g_lcos);
    cudaGetSymbolAddress((void**)&pxnh,  g_xnh);
    cudaGetSymbolAddress((void**)&pxnl,  g_xnl);
    cudaGetSymbolAddress((void**)&patth, g_atth);
    cudaGetSymbolAddress((void**)&pattl, g_attl);
    cudaGetSymbolAddress((void**)&ph1h,  g_h1h);
    cudaGetSymbolAddress((void**)&ph1l,  g_h1l);
    cudaGetSymbolAddress((void**)&ph2h,  g_h2h);
    cudaGetSymbolAddress((void**)&ph2l,  g_h2l);
    cudaGetSymbolAddress((void**)&pwh,   g_wh);
    cudaGetSymbolAddress((void**)&pwl,   g_wl);

    const int M = BB * TT;
    const int n4 = M * DD / 4;
    const int EW = 256;

    size_t smLoc = (size_t)(2 * 256 * LKS + 32 * LKS + 32 * LSS) * 4 + 256 * 4;
    size_t smGlb = (size_t)(3 * 64 * LKS + 64 * LSS) * 4 + 64 * 4;
    cudaFuncSetAttribute(local_attn_kernel,  cudaFuncAttributeMaxDynamicSharedMemorySize, (int)smLoc);
    cudaFuncSetAttribute(global_attn_kernel, cudaFuncAttributeMaxDynamicSharedMemorySize, (int)smGlb);
    cudaFuncSetAttribute(gemm_mma_kernel, cudaFuncAttributeMaxDynamicSharedMemorySize, 98304);

    // weight hi/lo offsets in g_wh/g_wl
    const int OLQ=0, OLK=262144, OLV=524288, OLO=786432, OGQ=1048576, OGK=1310720,
              OGV=1572864, OGO=1835008, OF1=2097152, OF2=2621440, OF3=3670016;

    dim3 g512(4,  M / 128);
    dim3 g1k (8,  M / 128);

    rope_init_kernel<<<64, 256>>>();
    WPtrs wp;
    wp.p[0]=lq_w; wp.p[1]=lk_w; wp.p[2]=lv_w; wp.p[3]=lo_w; wp.p[4]=gq_w;
    wp.p[5]=gk_w; wp.p[6]=gv_w; wp.p[7]=go_w; wp.p[8]=f1_w; wp.p[9]=f2_w; wp.p[10]=f3_w;
    cvt_w_kernel<<<dim3(1024, 11), 256>>>(wp);

    mask_mul4_kernel<<<(n4 + EW - 1) / EW, EW>>>(x, pm, px, n4);
    ln_kernel<<<M, 128>>>(px, ln1_g, ln1_b, pm, pxnh, pxnl, 1);

    gemm_mma_kernel<<<g512, 512, 98304>>>(pxnh, pxnl, pwh+OLQ, pwl+OLQ, lq_b, pq,  0, 0, DD, DD, 0, 0, 0);
    gemm_mma_kernel<<<g512, 512, 98304>>>(pxnh, pxnl, pwh+OLK, pwl+OLK, lk_b, pkp, 0, 0, DD, DD, 0, 1, 0);
    gemm_mma_kernel<<<g512, 512, 98304>>>(pxnh, pxnl, pwh+OLV, pwl+OLV, lv_b, pvp, 0, 0, DD, DD, 0, 1, 0);
    fill_pad_kernel<<<(BB * 128 * DD + EW - 1) / EW, EW>>>(lk_b, lv_b);

    local_attn_kernel<<<dim3(NLOC, HH, BB), 256, smLoc>>>(pq, pm, patth, pattl);

    gemm_mma_kernel<<<g512, 512, 98304>>>(patth, pattl, pwh+OLO, pwl+OLO, lo_b, ptmp, 0, 0, DD, DD, 0, 0, 0);
    add_mask4_kernel<<<(n4 + EW - 1) / EW, EW>>>(px, ptmp, pm, px, n4);

    ln_kernel<<<M, 128>>>(px, ln2_g, ln2_b, pm, pxnh, pxnl, 0);

    gemm_mma_kernel<<<g512, 512, 98304>>>(pxnh, pxnl, pwh+OGQ, pwl+OGQ, gq_b, pq,  0, 0, DD, DD, 0, 0, 0);
    gemm_mma_kernel<<<g512, 512, 98304>>>(pxnh, pxnl, pwh+OGK, pwl+OGK, gk_b, pkp, 0, 0, DD, DD, 0, 0, 0);
    gemm_mma_kernel<<<g512, 512, 98304>>>(pxnh, pxnl, pwh+OGV, pwl+OGV, gv_b, pvp, 0, 0, DD, DD, 0, 0, 0);

    global_attn_kernel<<<dim3(NDIL, HH, BB), 256, smGlb>>>(pq, pkp, pvp, pm, cosp, sinp, patth, pattl);

    gemm_mma_kernel<<<g512, 512, 98304>>>(patth, pattl, pwh+OGO, pwl+OGO, go_b, ptmp, 0, 0, DD, DD, 0, 0, 0);
    add_mask4_kernel<<<(n4 + EW - 1) / EW, EW>>>(px, ptmp, pm, px, n4);

    ln_kernel<<<M, 128>>>(px, ln3_g, ln3_b, pm, pxnh, pxnl, 0);
    gemm_mma_kernel<<<g1k,  512, 98304>>>(pxnh, pxnl, pwh+OF1, pwl+OF1, f1_b, 0, ph1h, ph1l, 512,  1024, 1, 0, 1);
    gemm_mma_kernel<<<g1k,  512, 98304>>>(ph1h, ph1l, pwh+OF2, pwl+OF2, f2_b, 0, ph2h, ph2l, 1024, 1024, 1, 0, 1);
    gemm_mma_kernel<<<g512, 512, 98304>>>(ph2h, ph2l, pwh+OF3, pwl+OF3, f3_b, ptmp, 0, 0, 1024, 512, 0, 0, 0);

    add_mask4_kernel<<<(n4 + EW - 1) / EW, EW>>>(px, ptmp, pm, out, n4);
}

// round 6
// speedup vs baseline: 1.8420x; 1.0160x over previous
#include <cuda_runtime.h>
#include <cuda_bf16.h>
#include <math.h>
#include <stdint.h>

#define BB 8
#define TT 4096
#define DD 512
#define HH 8
#define HD 64
#define TP 4224
#define NLOC 32
#define NDIL 64

// ---------------- scratch ----------------
__device__ float g_x  [BB*TT*DD];
__device__ float g_q  [BB*TT*DD];
__device__ float g_kp [BB*TP*DD];
__device__ float g_vp [BB*TP*DD];
__device__ __nv_bfloat16 g_xnh [BB*TT*DD];
__device__ __nv_bfloat16 g_xnl [BB*TT*DD];
__device__ __nv_bfloat16 g_atth[BB*TT*DD];
__device__ __nv_bfloat16 g_attl[BB*TT*DD];
__device__ __nv_bfloat16 g_h1h [BB*TT*1024];
__device__ __nv_bfloat16 g_h1l [BB*TT*1024];
__device__ __nv_bfloat16 g_h2h [BB*TT*1024];
__device__ __nv_bfloat16 g_h2l [BB*TT*1024];
__device__ __nv_bfloat16 g_wh  [4194304];
__device__ __nv_bfloat16 g_wl  [4194304];
__device__ float g_bcat[3072];
__device__ float g_lcos[256*64];
__device__ float g_lsin[256*64];

// ---------------- helpers ----------------
__device__ __forceinline__ uint32_t smem_u32(const void* p) {
    uint32_t a;
    asm("{ .reg .u64 t; cvta.to.shared.u64 t, %1; cvt.u32.u64 %0, t; }" : "=r"(a) : "l"(p));
    return a;
}
__device__ __forceinline__ void ldsm4(uint32_t* r, uint32_t addr) {
    asm volatile("ldmatrix.sync.aligned.m8n8.x4.shared.b16 {%0,%1,%2,%3}, [%4];"
        : "=r"(r[0]), "=r"(r[1]), "=r"(r[2]), "=r"(r[3]) : "r"(addr));
}
__device__ __forceinline__ void mma_bf16(float* c, const uint32_t* a, uint32_t b0, uint32_t b1) {
    asm volatile("mma.sync.aligned.m16n8k16.row.col.f32.bf16.bf16.f32 "
        "{%0,%1,%2,%3}, {%4,%5,%6,%7}, {%8,%9}, {%0,%1,%2,%3};"
        : "+f"(c[0]), "+f"(c[1]), "+f"(c[2]), "+f"(c[3])
        : "r"(a[0]), "r"(a[1]), "r"(a[2]), "r"(a[3]), "r"(b0), "r"(b1));
}
#define SWZ64(x) ((x) ^ (((x) >> 3) & 0x30))
#define CPA(dst, src) asm volatile("cp.async.cg.shared.global [%0], [%1], 16;" :: "r"(dst), "l"(src))
#define CPC() asm volatile("cp.async.commit_group;" ::: "memory")
#define CPW(n) asm volatile("cp.async.wait_group %0;" :: "n"(n) : "memory")

__device__ __forceinline__ uint32_t packbf(__nv_bfloat16 a, __nv_bfloat16 b) {
    return (uint32_t)__bfloat16_as_ushort(a) | ((uint32_t)__bfloat16_as_ushort(b) << 16);
}
__device__ __forceinline__ void split4(float4 v, uint2& h, uint2& l) {
    __nv_bfloat16 bx = __float2bfloat16_rn(v.x), by = __float2bfloat16_rn(v.y);
    __nv_bfloat16 bz = __float2bfloat16_rn(v.z), bw = __float2bfloat16_rn(v.w);
    h.x = packbf(bx, by); h.y = packbf(bz, bw);
    l.x = packbf(__float2bfloat16_rn(v.x - __bfloat162float(bx)),
                 __float2bfloat16_rn(v.y - __bfloat162float(by)));
    l.y = packbf(__float2bfloat16_rn(v.z - __bfloat162float(bz)),
                 __float2bfloat16_rn(v.w - __bfloat162float(bw)));
}

// ---------------- GEMM: modes 1=bf16 hi/lo out, 2=QKV triple out, 3=fp32+residual+mask ----
// CTA 128x128, 512 threads, BK=32, 4-stage cp.async ring.
__global__ void __launch_bounds__(512, 1) gemm_mma_kernel(
    const __nv_bfloat16* __restrict__ Ah, const __nv_bfloat16* __restrict__ Al,
    const __nv_bfloat16* __restrict__ Wh, const __nv_bfloat16* __restrict__ Wl,
    const float* __restrict__ bias,
    float* __restrict__ Cf, __nv_bfloat16* __restrict__ Ch, __nv_bfloat16* __restrict__ Cl,
    float* __restrict__ Ck, float* __restrict__ Cv,
    const float* __restrict__ R, const int* __restrict__ pm,
    int K, int Nt, int act, int mode, int padKV)
{
    extern __shared__ char sm[];
    uint32_t smb = smem_u32(sm);
    int tid = threadIdx.x, lane = tid & 31, wid = tid >> 5;
    int row0 = blockIdx.y * 128, col0 = blockIdx.x * 128;
    int wm = (wid & 3) * 32, wn = (wid >> 2) * 32;

    float acc[2][4][4];
    #pragma unroll
    for (int i = 0; i < 2; i++)
        #pragma unroll
        for (int j = 0; j < 4; j++)
            #pragma unroll
            for (int c = 0; c < 4; c++) acc[i][j][c] = 0.0f;

    int srow = tid >> 2, sc16 = tid & 3;
    uint32_t sdst = SWZ64((uint32_t)(srow * 64 + sc16 * 16));
    size_t gA = (size_t)(row0 + srow) * K + sc16 * 8;
    size_t gW = (size_t)(col0 + srow) * K + sc16 * 8;

    uint32_t aoff[2], boff[2];
    #pragma unroll
    for (int i = 0; i < 2; i++) {
        int r = wm + i * 16 + (lane & 15);
        aoff[i] = r * 64 + ((lane >> 4) << 4);
    }
    #pragma unroll
    for (int j = 0; j < 2; j++) {
        int r = wn + j * 16 + (lane & 7) + ((lane >> 4) & 1) * 8;
        boff[j] = r * 64 + (((lane >> 3) & 1) << 4);
    }

    int nch = K >> 5;
    #define G_ISSUE(ch) { \
        uint32_t st_ = smb + ((ch) & 3) * 32768; \
        size_t k0_ = (size_t)(ch) * 32; \
        CPA(st_ + sdst,          Ah + gA + k0_); \
        CPA(st_ + 8192 + sdst,   Al + gA + k0_); \
        CPA(st_ + 16384 + sdst,  Wh + gW + k0_); \
        CPA(st_ + 24576 + sdst,  Wl + gW + k0_); \
        CPC(); }

    G_ISSUE(0); G_ISSUE(1); G_ISSUE(2);

    for (int ch = 0; ch < nch; ch++) {
        CPW(2);
        __syncthreads();
        if (ch + 3 < nch) { G_ISSUE(ch + 3); } else { CPC(); }
        uint32_t st = smb + (ch & 3) * 32768;
        #pragma unroll
        for (int ks = 0; ks < 2; ks++) {
            uint32_t ah[2][4], al[2][4], bh[2][4], bl[2][4];
            #pragma unroll
            for (int i = 0; i < 2; i++) {
                uint32_t x = SWZ64(aoff[i] + ks * 32);
                ldsm4(ah[i], st + x);
                ldsm4(al[i], st + 8192 + x);
            }
            #pragma unroll
            for (int j = 0; j < 2; j++) {
                uint32_t x = SWZ64(boff[j] + ks * 32);
                ldsm4(bh[j], st + 16384 + x);
                ldsm4(bl[j], st + 24576 + x);
            }
            #pragma unroll
            for (int i = 0; i < 2; i++)
                #pragma unroll
                for (int j = 0; j < 2; j++) {
                    mma_bf16(acc[i][2*j],   ah[i], bh[j][0], bh[j][1]);
                    mma_bf16(acc[i][2*j+1], ah[i], bh[j][2], bh[j][3]);
                    mma_bf16(acc[i][2*j],   al[i], bh[j][0], bh[j][1]);
                    mma_bf16(acc[i][2*j+1], al[i], bh[j][2], bh[j][3]);
                    mma_bf16(acc[i][2*j],   ah[i], bl[j][0], bl[j][1]);
                    mma_bf16(acc[i][2*j+1], ah[i], bl[j][2], bl[j][3]);
                }
        }
    }

    // epilogue
    int g = lane >> 2, t4 = lane & 3;
    int seg = col0 >> 9;       // mode-2 segment: 0=q,1=k,2=v
    #pragma unroll
    for (int i = 0; i < 2; i++) {
        int r1 = row0 + wm + i * 16 + g;
        int r2 = r1 + 8;
        #pragma unroll
        for (int nj = 0; nj < 4; nj++) {
            int colG = col0 + wn + nj * 8 + t4 * 2;
            float b0 = bias[colG], b1 = bias[colG + 1];
            float v0 = acc[i][nj][0] + b0, v1 = acc[i][nj][1] + b1;
            float v2 = acc[i][nj][2] + b0, v3 = acc[i][nj][3] + b1;
            if (act) {
                v0 = 0.5f * v0 * (1.0f + erff(v0 * 0.70710678118654752f));
                v1 = 0.5f * v1 * (1.0f + erff(v1 * 0.70710678118654752f));
                v2 = 0.5f * v2 * (1.0f + erff(v2 * 0.70710678118654752f));
                v3 = 0.5f * v3 * (1.0f + erff(v3 * 0.70710678118654752f));
            }
            if (mode == 1) {
                __nv_bfloat16 h0 = __float2bfloat16_rn(v0), h1 = __float2bfloat16_rn(v1);
                __nv_bfloat16 h2 = __float2bfloat16_rn(v2), h3 = __float2bfloat16_rn(v3);
                uint32_t lw0 = packbf(__float2bfloat16_rn(v0 - __bfloat162float(h0)),
                                      __float2bfloat16_rn(v1 - __bfloat162float(h1)));
                uint32_t lw1 = packbf(__float2bfloat16_rn(v2 - __bfloat162float(h2)),
                                      __float2bfloat16_rn(v3 - __bfloat162float(h3)));
                *(uint32_t*)(Ch + (size_t)r1 * Nt + colG) = packbf(h0, h1);
                *(uint32_t*)(Cl + (size_t)r1 * Nt + colG) = lw0;
                *(uint32_t*)(Ch + (size_t)r2 * Nt + colG) = packbf(h2, h3);
                *(uint32_t*)(Cl + (size_t)r2 * Nt + colG) = lw1;
            } else if (mode == 2) {
                int colLoc = colG - (seg << 9);
                float* dst = (seg == 0) ? Cf : (seg == 1 ? Ck : Cv);
                int doPad = (seg != 0) && padKV;
                size_t o1 = doPad ? ((size_t)(r1 >> 12) * TP + 64 + (r1 & 4095)) : (size_t)r1;
                size_t o2 = doPad ? ((size_t)(r2 >> 12) * TP + 64 + (r2 & 4095)) : (size_t)r2;
                float2 w1; w1.x = v0; w1.y = v1;
                float2 w2; w2.x = v2; w2.y = v3;
                *(float2*)(dst + o1 * 512 + colLoc) = w1;
                *(float2*)(dst + o2 * 512 + colLoc) = w2;
            } else {
                float m1 = pm[r1] ? 1.0f : 0.0f;
                float m2 = pm[r2] ? 1.0f : 0.0f;
                const float* rr1 = R + (size_t)r1 * Nt + colG;
                const float* rr2 = R + (size_t)r2 * Nt + colG;
                float2 w1; w1.x = (v0 + rr1[0]) * m1; w1.y = (v1 + rr1[1]) * m1;
                float2 w2; w2.x = (v2 + rr2[0]) * m2; w2.y = (v3 + rr2[1]) * m2;
                *(float2*)(Cf + (size_t)r1 * Nt + colG) = w1;
                *(float2*)(Cf + (size_t)r2 * Nt + colG) = w2;
            }
        }
    }
}

// ---------------- weight split (QKV concatenated) ----------------
struct WPtrs { const float* p[11]; };
__global__ void cvt_w_kernel(WPtrs wp) {
    // order: lq lk lv gq gk gv lo go f1 f2 f3
    const int sizes[11] = {262144,262144,262144,262144,262144,262144,262144,262144,
                           524288,1048576,524288};
    const int offs[11]  = {0,262144,524288, 786432,1048576,1310720,
                           1572864,1835008, 2097152,2621440,3670016};
    int wi = blockIdx.y;
    int i4 = blockIdx.x * blockDim.x + threadIdx.x;
    if (i4 >= (sizes[wi] >> 2)) return;
    float4 v = ((const float4*)wp.p[wi])[i4];
    uint2 h, l;
    split4(v, h, l);
    ((uint2*)(g_wh + offs[wi]))[i4] = h;
    ((uint2*)(g_wl + offs[wi]))[i4] = l;
}

struct BPtrs { const float* p[6]; };
__global__ void bias_cat_kernel(BPtrs bp) {
    int t = threadIdx.x;
    for (int i = 0; i < 6; i++)
        g_bcat[i * 512 + t] = bp.p[i][t];
}

// ---------------- local rope tables ----------------
__global__ void rope_init_kernel() {
    int idx = blockIdx.x * blockDim.x + threadIdx.x;
    if (idx >= 256 * 64) return;
    int t = idx >> 6, d = idx & 63;
    double inv = pow(10000.0, -(double)(d & 31) / 32.0);
    double a = (double)t * inv;
    g_lcos[idx] = (float)cos(a);
    g_lsin[idx] = (float)sin(a);
}

// ---------------- elementwise ----------------
__global__ void mask_mul4_kernel(const float* __restrict__ X,
                                 const int* __restrict__ pm,
                                 float* __restrict__ Y, int n4) {
    int i = blockIdx.x * blockDim.x + threadIdx.x;
    if (i >= n4) return;
    float m = pm[i >> 7] ? 1.0f : 0.0f;
    float4 v = ((const float4*)X)[i];
    v.x *= m; v.y *= m; v.z *= m; v.w *= m;
    ((float4*)Y)[i] = v;
}

// ---------------- layernorm -> bf16 hi/lo ----------------
__global__ void __launch_bounds__(128) ln_kernel(
    const float* __restrict__ X, const float* __restrict__ g,
    const float* __restrict__ b, const int* __restrict__ pm,
    __nv_bfloat16* __restrict__ Yh, __nv_bfloat16* __restrict__ Yl, int maskOut)
{
    int row = blockIdx.x;
    int tid = threadIdx.x;
    const float4* x4 = (const float4*)(X + (size_t)row * DD);
    float4 v = x4[tid];
    float s  = v.x + v.y + v.z + v.w;
    float ss = v.x*v.x + v.y*v.y + v.z*v.z + v.w*v.w;
    #pragma unroll
    for (int o = 16; o; o >>= 1) {
        s  += __shfl_xor_sync(~0u, s,  o);
        ss += __shfl_xor_sync(~0u, ss, o);
    }
    __shared__ float sh[8];
    int w = tid >> 5, lane = tid & 31;
    if (lane == 0) { sh[w] = s; sh[4 + w] = ss; }
    __syncthreads();
    s  = sh[0] + sh[1] + sh[2] + sh[3];
    ss = sh[4] + sh[5] + sh[6] + sh[7];
    float mean = s * (1.0f / 512.0f);
    float var  = ss * (1.0f / 512.0f) - mean * mean;
    float inv  = rsqrtf(var + 1e-5f);
    float m = maskOut ? (pm[row] ? 1.0f : 0.0f) : 1.0f;
    float4 gg = ((const float4*)g)[tid];
    float4 bb = ((const float4*)b)[tid];
    float4 o;
    o.x = ((v.x - mean) * inv * gg.x + bb.x) * m;
    o.y = ((v.y - mean) * inv * gg.y + bb.y) * m;
    o.z = ((v.z - mean) * inv * gg.z + bb.z) * m;
    o.w = ((v.w - mean) * inv * gg.w + bb.w) * m;
    uint2 h, l;
    split4(o, h, l);
    ((uint2*)(Yh + (size_t)row * DD))[tid] = h;
    ((uint2*)(Yl + (size_t)row * DD))[tid] = l;
}

// ---------------- fill pad rows ----------------
__global__ void fill_pad_kernel(const float* __restrict__ kb, const float* __restrict__ vb) {
    int idx = blockIdx.x * blockDim.x + threadIdx.x;
    if (idx >= BB * 128 * DD) return;
    int c  = idx & 511;
    int rr = (idx >> 9) & 127;
    int b  = idx >> 16;
    int prow = (rr < 64) ? rr : (TT + rr);
    size_t o = ((size_t)b * TP + prow) * DD + c;
    g_kp[o] = kb[c];
    g_vp[o] = vb[c];
}

// ---------------- local attention ----------------
#define LKS 68
#define LSS 257
__global__ void __launch_bounds__(256) local_attn_kernel(
    const float* __restrict__ Qg, const int* __restrict__ pm,
    __nv_bfloat16* __restrict__ Oh, __nv_bfloat16* __restrict__ Ol)
{
    int j = blockIdx.x, h = blockIdx.y, b = blockIdx.z;
    extern __shared__ float smf[];
    float* Ks = smf;
    float* Vs = Ks + 256 * LKS;
    float* Qs = Vs + 256 * LKS;
    float* Ss = Qs + 32 * LKS;
    int*  keep = (int*)(Ss + 32 * LSS);
    int tid = threadIdx.x;

    for (int r0 = 0; r0 < 256; r0 += 4) {
        int r = r0 + (tid >> 6);
        int d = tid & 63;
        size_t base = ((size_t)b * TP + (size_t)j * 128 + r) * DD + h * HD;
        float kv = g_kp[base + d];
        float ko = g_kp[base + (d ^ 32)];
        float c = g_lcos[r * 64 + d], s = g_lsin[r * 64 + d];
        Ks[r * LKS + d] = (d < 32) ? (kv * c - ko * s) : (kv * c + ko * s);
        Vs[r * LKS + d] = g_vp[base + d];
    }
    if (tid < 256) {
        int orig = j * 128 + tid - 64;
        keep[tid] = (orig >= 0 && orig < TT && pm[(size_t)b * TT + orig]) ? 1 : 0;
    }
    __syncthreads();
    if (tid == 0) {
        int any = 0;
        for (int i = 0; i < 256; i++) any |= keep[i];
        if (!any) keep[0] = 1;
    }
    __syncthreads();

    for (int c0 = 0; c0 < 128; c0 += 32) {
        for (int r0 = 0; r0 < 32; r0 += 4) {
            int i = r0 + (tid >> 6);
            int d = tid & 63;
            int t = j * 128 + c0 + i;
            size_t base = ((size_t)b * TT + t) * DD + h * HD;
            float qv = Qg[base + d];
            float qo = Qg[base + (d ^ 32)];
            int ti = 64 + c0 + i;
            float c = g_lcos[ti * 64 + d], s = g_lsin[ti * 64 + d];
            Qs[i * LKS + d] = (d < 32) ? (qv * c - qo * s) : (qv * c + qo * s);
        }
        __syncthreads();

        {
            int qi = tid & 31;
            int kb = (tid >> 5) * 32;
            float acc[32];
            #pragma unroll
            for (int i = 0; i < 32; i++) acc[i] = 0.0f;
            for (int d0 = 0; d0 < 64; d0 += 16) {
                float qr[16];
                #pragma unroll
                for (int dd = 0; dd < 16; dd += 4) {
                    float4 qv = *(const float4*)&Qs[qi * LKS + d0 + dd];
                    qr[dd] = qv.x; qr[dd+1] = qv.y; qr[dd+2] = qv.z; qr[dd+3] = qv.w;
                }
                #pragma unroll 4
                for (int kk = 0; kk < 32; kk++) {
                    const float* kp = &Ks[(kb + kk) * LKS + d0];
                    #pragma unroll
                    for (int dd = 0; dd < 16; dd += 4) {
                        float4 kv = *(const float4*)(kp + dd);
                        acc[kk] += qr[dd] * kv.x + qr[dd+1] * kv.y
                                 + qr[dd+2] * kv.z + qr[dd+3] * kv.w;
                    }
                }
            }
            #pragma unroll
            for (int kk = 0; kk < 32; kk++) {
                int k = kb + kk;
                Ss[qi * LSS + k] = keep[k] ? acc[kk] * 0.125f : -1e9f;
            }
        }
        __syncthreads();

        {
            int wp = tid >> 5, lane = tid & 31;
            for (int rr = 0; rr < 4; rr++) {
                int r = wp * 4 + rr;
                float* row = Ss + r * LSS;
                float vals[8];
                float mx = -1e30f;
                #pragma unroll
                for (int m = 0; m < 8; m++) {
                    vals[m] = row[lane + 32 * m];
                    mx = fmaxf(mx, vals[m]);
                }
                #pragma unroll
                for (int o = 16; o; o >>= 1) mx = fmaxf(mx, __shfl_xor_sync(~0u, mx, o));
                float sum = 0.0f;
                #pragma unroll
                for (int m = 0; m < 8; m++) { vals[m] = expf(vals[m] - mx); sum += vals[m]; }
                #pragma unroll
                for (int o = 16; o; o >>= 1) sum += __shfl_xor_sync(~0u, sum, o);
                float inv = 1.0f / sum;
                #pragma unroll
                for (int m = 0; m < 8; m++) row[lane + 32 * m] = vals[m] * inv;
            }
        }
        __syncthreads();

        {
            int qi = tid & 31;
            int db = (tid >> 5) * 8;
            float acc[8];
            #pragma unroll
            for (int i = 0; i < 8; i++) acc[i] = 0.0f;
            #pragma unroll 4
            for (int k = 0; k < 256; k++) {
                float p = Ss[qi * LSS + k];
                float4 v0 = *(const float4*)&Vs[k * LKS + db];
                float4 v1 = *(const float4*)&Vs[k * LKS + db + 4];
                acc[0] += p * v0.x; acc[1] += p * v0.y;
                acc[2] += p * v0.z; acc[3] += p * v0.w;
                acc[4] += p * v1.x; acc[5] += p * v1.y;
                acc[6] += p * v1.z; acc[7] += p * v1.w;
            }
            int t = j * 128 + c0 + qi;
            size_t base = ((size_t)b * TT + t) * DD + h * HD + db;
            float4 p0; p0.x = acc[0]; p0.y = acc[1]; p0.z = acc[2]; p0.w = acc[3];
            float4 p1; p1.x = acc[4]; p1.y = acc[5]; p1.z = acc[6]; p1.w = acc[7];
            uint2 h0, l0, h1, l1;
            split4(p0, h0, l0); split4(p1, h1, l1);
            *(uint2*)(Oh + base)     = h0;
            *(uint2*)(Oh + base + 4) = h1;
            *(uint2*)(Ol + base)     = l0;
            *(uint2*)(Ol + base + 4) = l1;
        }
        __syncthreads();
    }
}

// ---------------- global attention ----------------
__global__ void __launch_bounds__(256) global_attn_kernel(
    const float* __restrict__ Qg, const float* __restrict__ Kg,
    const float* __restrict__ Vg, const int* __restrict__ pm,
    const float* __restrict__ cosp, const float* __restrict__ sinp,
    __nv_bfloat16* __restrict__ Oh, __nv_bfloat16* __restrict__ Ol)
{
    int w = blockIdx.x, h = blockIdx.y, b = blockIdx.z;
    extern __shared__ float smf[];
    float* Qs = smf;
    float* Ks = Qs + 64 * LKS;
    float* Vs = Ks + 64 * LKS;
    float* Ss = Vs + 64 * LKS;
    int*  keep = (int*)(Ss + 64 * LSS);
    int tid = threadIdx.x;

    for (int r0 = 0; r0 < 64; r0 += 4) {
        int nn = r0 + (tid >> 6);
        int d = tid & 63;
        int p = nn * 64 + w;
        size_t base = ((size_t)b * TT + p) * DD + h * HD;
        float c = cosp[p * 64 + d], s = sinp[p * 64 + d];
        float qv = Qg[base + d], qo = Qg[base + (d ^ 32)];
        float kv = Kg[base + d], ko = Kg[base + (d ^ 32)];
        Qs[nn * LKS + d] = (d < 32) ? (qv * c - qo * s) : (qv * c + qo * s);
        Ks[nn * LKS + d] = (d < 32) ? (kv * c - ko * s) : (kv * c + ko * s);
        Vs[nn * LKS + d] = Vg[base + d];
    }
    if (tid < 64) keep[tid] = pm[(size_t)b * TT + tid * 64 + w] ? 1 : 0;
    __syncthreads();

    {
        int qi = tid & 63;
        int kb = (tid >> 6) * 16;
        float acc[16];
        #pragma unroll
        for (int i = 0; i < 16; i++) acc[i] = 0.0f;
        for (int d0 = 0; d0 < 64; d0 += 16) {
            float qr[16];
            #pragma unroll
            for (int dd = 0; dd < 16; dd += 4) {
                float4 qv = *(const float4*)&Qs[qi * LKS + d0 + dd];
                qr[dd] = qv.x; qr[dd+1] = qv.y; qr[dd+2] = qv.z; qr[dd+3] = qv.w;
            }
            #pragma unroll 4
            for (int kk = 0; kk < 16; kk++) {
                const float* kp = &Ks[(kb + kk) * LKS + d0];
                #pragma unroll
                for (int dd = 0; dd < 16; dd += 4) {
                    float4 kv = *(const float4*)(kp + dd);
                    acc[kk] += qr[dd] * kv.x + qr[dd+1] * kv.y
                             + qr[dd+2] * kv.z + qr[dd+3] * kv.w;
                }
            }
        }
        #pragma unroll
        for (int kk = 0; kk < 16; kk++) {
            int k = kb + kk;
            Ss[qi * LSS + k] = keep[k] ? acc[kk] * 0.125f : -1e9f;
        }
    }
    __syncthreads();

    {
        int wp = tid >> 5, lane = tid & 31;
        for (int rr = 0; rr < 8; rr++) {
            int r = wp * 8 + rr;
            float* row = Ss + r * LSS;
            float a0 = row[lane], a1 = row[lane + 32];
            float mx = fmaxf(a0, a1);
            #pragma unroll
            for (int o = 16; o; o >>= 1) mx = fmaxf(mx, __shfl_xor_sync(~0u, mx, o));
            float e0 = expf(a0 - mx), e1 = expf(a1 - mx);
            float sum = e0 + e1;
            #pragma unroll
            for (int o = 16; o; o >>= 1) sum += __shfl_xor_sync(~0u, sum, o);
            float inv = 1.0f / sum;
            row[lane] = e0 * inv; row[lane + 32] = e1 * inv;
        }
    }
    __syncthreads();

    {
        int qi = tid & 63;
        int db = (tid >> 6) * 16;
        float acc[16];
        #pragma unroll
        for (int i = 0; i < 16; i++) acc[i] = 0.0f;
        #pragma unroll 4
        for (int k = 0; k < 64; k++) {
            float p = Ss[qi * LSS + k];
            #pragma unroll
            for (int dd = 0; dd < 16; dd += 4) {
                float4 v = *(const float4*)&Vs[k * LKS + db + dd];
                acc[dd]   += p * v.x; acc[dd+1] += p * v.y;
                acc[dd+2] += p * v.z; acc[dd+3] += p * v.w;
            }
        }
        int p = qi * 64 + w;
        size_t base = ((size_t)b * TT + p) * DD + h * HD + db;
        #pragma unroll
        for (int dd = 0; dd < 16; dd += 4) {
            float4 pv;
            pv.x = acc[dd]; pv.y = acc[dd+1]; pv.z = acc[dd+2]; pv.w = acc[dd+3];
            uint2 hq, lq;
            split4(pv, hq, lq);
            *(uint2*)(Oh + base + dd) = hq;
            *(uint2*)(Ol + base + dd) = lq;
        }
    }
}

// ---------------- host ----------------
extern "C" void kernel_launch(void* const* d_in, const int* in_sizes, int n_in,
                              void* d_out, int out_size)
{
    const float* x    = (const float*)d_in[0];
    const int*   pm   = (const int*)d_in[1];
    const float* cosp = (const float*)d_in[2];
    const float* sinp = (const float*)d_in[3];
    const float* ln1_g = (const float*)d_in[4];
    const float* ln1_b = (const float*)d_in[5];
    const float* ln2_g = (const float*)d_in[6];
    const float* ln2_b = (const float*)d_in[7];
    const float* ln3_g = (const float*)d_in[8];
    const float* ln3_b = (const float*)d_in[9];
    const float* lq_w = (const float*)d_in[10];
    const float* lq_b = (const float*)d_in[11];
    const float* lk_w = (const float*)d_in[12];
    const float* lk_b = (const float*)d_in[13];
    const float* lv_w = (const float*)d_in[14];
    const float* lv_b = (const float*)d_in[15];
    const float* lo_w = (const float*)d_in[16];
    const float* lo_b = (const float*)d_in[17];
    const float* gq_w = (const float*)d_in[18];
    const float* gq_b = (const float*)d_in[19];
    const float* gk_w = (const float*)d_in[20];
    const float* gk_b = (const float*)d_in[21];
    const float* gv_w = (const float*)d_in[22];
    const float* gv_b = (const float*)d_in[23];
    const float* go_w = (const float*)d_in[24];
    const float* go_b = (const float*)d_in[25];
    const float* f1_w = (const float*)d_in[26];
    const float* f1_b = (const float*)d_in[27];
    const float* f2_w = (const float*)d_in[28];
    const float* f2_b = (const float*)d_in[29];
    const float* f3_w = (const float*)d_in[30];
    const float* f3_b = (const float*)d_in[31];
    float* out = (float*)d_out;

    float *px, *pq, *pkp, *pvp, *pbcat;
    __nv_bfloat16 *pxnh, *pxnl, *patth, *pattl, *ph1h, *ph1l, *ph2h, *ph2l, *pwh, *pwl;
    cudaGetSymbolAddress((void**)&px,    g_x);
    cudaGetSymbolAddress((void**)&pq,    g_q);
    cudaGetSymbolAddress((void**)&pkp,   g_kp);
    cudaGetSymbolAddress((void**)&pvp,   g_vp);
    cudaGetSymbolAddress((void**)&pbcat, g_bcat);
    cudaGetSymbolAddress((void**)&pxnh,  g_xnh);
    cudaGetSymbolAddress((void**)&pxnl,  g_xnl);
    cudaGetSymbolAddress((void**)&patth, g_atth);
    cudaGetSymbolAddress((void**)&pattl, g_attl);
    cudaGetSymbolAddress((void**)&ph1h,  g_h1h);
    cudaGetSymbolAddress((void**)&ph1l,  g_h1l);
    cudaGetSymbolAddress((void**)&ph2h,  g_h2h);
    cudaGetSymbolAddress((void**)&ph2l,  g_h2l);
    cudaGetSymbolAddress((void**)&pwh,   g_wh);
    cudaGetSymbolAddress((void**)&pwl,   g_wl);

    const int M = BB * TT;
    const int n4 = M * DD / 4;
    const int EW = 256;

    size_t smLoc = (size_t)(2 * 256 * LKS + 32 * LKS + 32 * LSS) * 4 + 256 * 4;
    size_t smGlb = (size_t)(3 * 64 * LKS + 64 * LSS) * 4 + 64 * 4;
    cudaFuncSetAttribute(local_attn_kernel,  cudaFuncAttributeMaxDynamicSharedMemorySize, (int)smLoc);
    cudaFuncSetAttribute(global_attn_kernel, cudaFuncAttributeMaxDynamicSharedMemorySize, (int)smGlb);
    cudaFuncSetAttribute(gemm_mma_kernel, cudaFuncAttributeMaxDynamicSharedMemorySize, 131072);

    const int OLQKV=0, OGQKV=786432, OLO=1572864, OGO=1835008,
              OF1=2097152, OF2=2621440, OF3=3670016;

    dim3 gQKV(12, M / 128);
    dim3 g512(4,  M / 128);
    dim3 g1k (8,  M / 128);

    rope_init_kernel<<<64, 256>>>();
    WPtrs wp;
    wp.p[0]=lq_w; wp.p[1]=lk_w; wp.p[2]=lv_w; wp.p[3]=gq_w; wp.p[4]=gk_w;
    wp.p[5]=gv_w; wp.p[6]=lo_w; wp.p[7]=go_w; wp.p[8]=f1_w; wp.p[9]=f2_w; wp.p[10]=f3_w;
    cvt_w_kernel<<<dim3(1024, 11), 256>>>(wp);
    BPtrs bp;
    bp.p[0]=lq_b; bp.p[1]=lk_b; bp.p[2]=lv_b; bp.p[3]=gq_b; bp.p[4]=gk_b; bp.p[5]=gv_b;
    bias_cat_kernel<<<1, 512>>>(bp);

    mask_mul4_kernel<<<(n4 + EW - 1) / EW, EW>>>(x, pm, px, n4);
    ln_kernel<<<M, 128>>>(px, ln1_g, ln1_b, pm, pxnh, pxnl, 1);

    // local QKV fused (k/v padded scatter)
    gemm_mma_kernel<<<gQKV, 512, 131072>>>(pxnh, pxnl, pwh+OLQKV, pwl+OLQKV, pbcat,
                                           pq, 0, 0, pkp, pvp, 0, 0, DD, DD, 0, 2, 1);
    fill_pad_kernel<<<(BB * 128 * DD + EW - 1) / EW, EW>>>(lk_b, lv_b);

    local_attn_kernel<<<dim3(NLOC, HH, BB), 256, smLoc>>>(pq, pm, patth, pattl);

    // O proj + residual + mask (in place on px)
    gemm_mma_kernel<<<g512, 512, 131072>>>(patth, pattl, pwh+OLO, pwl+OLO, lo_b,
                                           px, 0, 0, 0, 0, px, pm, DD, DD, 0, 3, 0);

    ln_kernel<<<M, 128>>>(px, ln2_g, ln2_b, pm, pxnh, pxnl, 0);

    // global QKV fused (plain layout)
    gemm_mma_kernel<<<gQKV, 512, 131072>>>(pxnh, pxnl, pwh+OGQKV, pwl+OGQKV, pbcat + 1536,
                                           pq, 0, 0, pkp, pvp, 0, 0, DD, DD, 0, 2, 0);

    global_attn_kernel<<<dim3(NDIL, HH, BB), 256, smGlb>>>(pq, pkp, pvp, pm, cosp, sinp, patth, pattl);

    gemm_mma_kernel<<<g512, 512, 131072>>>(patth, pattl, pwh+OGO, pwl+OGO, go_b,
                                           px, 0, 0, 0, 0, px, pm, DD, DD, 0, 3, 0);

    ln_kernel<<<M, 128>>>(px, ln3_g, ln3_b, pm, pxnh, pxnl, 0);
    gemm_mma_kernel<<<g1k,  512, 131072>>>(pxnh, pxnl, pwh+OF1, pwl+OF1, f1_b,
                                           0, ph1h, ph1l, 0, 0, 0, 0, 512,  1024, 1, 1, 0);
    gemm_mma_kernel<<<g1k,  512, 131072>>>(ph1h, ph1l, pwh+OF2, pwl+OF2, f2_b,
                                           0, ph2h, ph2l, 0, 0, 0, 0, 1024, 1024, 1, 1, 0);
    // f3 + residual + mask -> out
    gemm_mma_kernel<<<g512, 512, 131072>>>(ph2h, ph2l, pwh+OF3, pwl+OF3, f3_b,
                                           out, 0, 0, 0, 0, px, pm, 1024, 512, 0, 3, 0);
}

// round 8
// speedup vs baseline: 2.6624x; 1.4454x over previous
#include <cuda_runtime.h>
#include <cuda_bf16.h>
#include <cuda_fp16.h>
#include <math.h>
#include <stdint.h>

#define BB 8
#define TT 4096
#define DD 512
#define HH 8
#define HD 64
#define TP 4224
#define NLOC 32
#define NDIL 64

// ---------------- scratch ----------------
__device__ float g_x  [BB*TT*DD];
__device__ float g_q  [BB*TT*DD];
__device__ float g_kp [BB*TP*DD];
__device__ float g_vp [BB*TP*DD];
__device__ __half g_xn [BB*TT*DD];
__device__ __half g_att[BB*TT*DD];
__device__ __half g_h1 [BB*TT*1024];
__device__ __half g_h2 [BB*TT*1024];
__device__ __half g_w  [4194304];
__device__ float g_bcat[3072];
__device__ float g_lcos[256*64];
__device__ float g_lsin[256*64];

// ---------------- helpers ----------------
__device__ __forceinline__ uint32_t smem_u32(const void* p) {
    uint32_t a;
    asm("{ .reg .u64 t; cvta.to.shared.u64 t, %1; cvt.u32.u64 %0, t; }" : "=r"(a) : "l"(p));
    return a;
}
__device__ __forceinline__ void ldsm4(uint32_t* r, uint32_t addr) {
    asm volatile("ldmatrix.sync.aligned.m8n8.x4.shared.b16 {%0,%1,%2,%3}, [%4];"
        : "=r"(r[0]), "=r"(r[1]), "=r"(r[2]), "=r"(r[3]) : "r"(addr));
}
__device__ __forceinline__ void mma_f16(float* c, const uint32_t* a, uint32_t b0, uint32_t b1) {
    asm volatile("mma.sync.aligned.m16n8k16.row.col.f32.f16.f16.f32 "
        "{%0,%1,%2,%3}, {%4,%5,%6,%7}, {%8,%9}, {%0,%1,%2,%3};"
        : "+f"(c[0]), "+f"(c[1]), "+f"(c[2]), "+f"(c[3])
        : "r"(a[0]), "r"(a[1]), "r"(a[2]), "r"(a[3]), "r"(b0), "r"(b1));
}
#define SWZ64(x) ((x) ^ (((x) >> 3) & 0x30))
#define CPA(dst, src) asm volatile("cp.async.cg.shared.global [%0], [%1], 16;" :: "r"(dst), "l"(src))
#define CPC() asm volatile("cp.async.commit_group;" ::: "memory")
#define CPW(n) asm volatile("cp.async.wait_group %0;" :: "n"(n) : "memory")

__device__ __forceinline__ uint32_t packh(float a, float b) {
    __half2 h = __floats2half2_rn(a, b);
    return *(uint32_t*)&h;
}
__device__ __forceinline__ uint2 pack4h(float4 v) {
    uint2 r; r.x = packh(v.x, v.y); r.y = packh(v.z, v.w); return r;
}

// ---------------- GEMM (fp16 single-pass): modes 1=fp16 out, 2=QKV triple, 3=fp32+res+mask ----
// CTA 128x128, 512 threads (16 warps, warp tile 32x32), BK=32, 4-stage cp.async ring (64KB).
__global__ void __launch_bounds__(512, 1) gemm_mma_kernel(
    const __half* __restrict__ A, const __half* __restrict__ W,
    const float* __restrict__ bias,
    float* __restrict__ Cf, __half* __restrict__ Ch,
    float* __restrict__ Ck, float* __restrict__ Cv,
    const float* __restrict__ R, const int* __restrict__ pm,
    int K, int Nt, int act, int mode, int padKV)
{
    extern __shared__ char sm[];
    uint32_t smb = smem_u32(sm);
    int tid = threadIdx.x, lane = tid & 31, wid = tid >> 5;
    int row0 = blockIdx.y * 128, col0 = blockIdx.x * 128;
    int wm = (wid & 3) * 32, wn = (wid >> 2) * 32;

    float acc[2][4][4];
    #pragma unroll
    for (int i = 0; i < 2; i++)
        #pragma unroll
        for (int j = 0; j < 4; j++)
            #pragma unroll
            for (int c = 0; c < 4; c++) acc[i][j][c] = 0.0f;

    int srow = tid >> 2, sc16 = tid & 3;
    uint32_t sdst = SWZ64((uint32_t)(srow * 64 + sc16 * 16));
    size_t gA = (size_t)(row0 + srow) * K + sc16 * 8;
    size_t gW = (size_t)(col0 + srow) * K + sc16 * 8;

    uint32_t aoff[2], boff[2];
    #pragma unroll
    for (int i = 0; i < 2; i++) {
        int r = wm + i * 16 + (lane & 15);
        aoff[i] = r * 64 + ((lane >> 4) << 4);
    }
    #pragma unroll
    for (int j = 0; j < 2; j++) {
        int r = wn + j * 16 + (lane & 7) + ((lane >> 4) & 1) * 8;
        boff[j] = r * 64 + (((lane >> 3) & 1) << 4);
    }

    int nch = K >> 5;
    #define G_ISSUE(ch) { \
        uint32_t st_ = smb + ((ch) & 3) * 16384; \
        size_t k0_ = (size_t)(ch) * 32; \
        CPA(st_ + sdst,        A + gA + k0_); \
        CPA(st_ + 8192 + sdst, W + gW + k0_); \
        CPC(); }

    G_ISSUE(0); G_ISSUE(1); G_ISSUE(2);

    for (int ch = 0; ch < nch; ch++) {
        CPW(2);
        __syncthreads();
        if (ch + 3 < nch) { G_ISSUE(ch + 3); } else { CPC(); }
        uint32_t st = smb + (ch & 3) * 16384;
        #pragma unroll
        for (int ks = 0; ks < 2; ks++) {
            uint32_t ah[2][4], bh[2][4];
            #pragma unroll
            for (int i = 0; i < 2; i++)
                ldsm4(ah[i], st + SWZ64(aoff[i] + ks * 32));
            #pragma unroll
            for (int j = 0; j < 2; j++)
                ldsm4(bh[j], st + 8192 + SWZ64(boff[j] + ks * 32));
            #pragma unroll
            for (int i = 0; i < 2; i++)
                #pragma unroll
                for (int j = 0; j < 2; j++) {
                    mma_f16(acc[i][2*j],   ah[i], bh[j][0], bh[j][1]);
                    mma_f16(acc[i][2*j+1], ah[i], bh[j][2], bh[j][3]);
                }
        }
    }

    // epilogue
    int g = lane >> 2, t4 = lane & 3;
    int seg = col0 >> 9;
    #pragma unroll
    for (int i = 0; i < 2; i++) {
        int r1 = row0 + wm + i * 16 + g;
        int r2 = r1 + 8;
        #pragma unroll
        for (int nj = 0; nj < 4; nj++) {
            int colG = col0 + wn + nj * 8 + t4 * 2;
            float b0 = bias[colG], b1 = bias[colG + 1];
            float v0 = acc[i][nj][0] + b0, v1 = acc[i][nj][1] + b1;
            float v2 = acc[i][nj][2] + b0, v3 = acc[i][nj][3] + b1;
            if (act) {
                v0 = 0.5f * v0 * (1.0f + erff(v0 * 0.70710678118654752f));
                v1 = 0.5f * v1 * (1.0f + erff(v1 * 0.70710678118654752f));
                v2 = 0.5f * v2 * (1.0f + erff(v2 * 0.70710678118654752f));
                v3 = 0.5f * v3 * (1.0f + erff(v3 * 0.70710678118654752f));
            }
            if (mode == 1) {
                *(uint32_t*)(Ch + (size_t)r1 * Nt + colG) = packh(v0, v1);
                *(uint32_t*)(Ch + (size_t)r2 * Nt + colG) = packh(v2, v3);
            } else if (mode == 2) {
                int colLoc = colG - (seg << 9);
                float* dst = (seg == 0) ? Cf : (seg == 1 ? Ck : Cv);
                int doPad = (seg != 0) && padKV;
                size_t o1 = doPad ? ((size_t)(r1 >> 12) * TP + 64 + (r1 & 4095)) : (size_t)r1;
                size_t o2 = doPad ? ((size_t)(r2 >> 12) * TP + 64 + (r2 & 4095)) : (size_t)r2;
                float2 w1; w1.x = v0; w1.y = v1;
                float2 w2; w2.x = v2; w2.y = v3;
                *(float2*)(dst + o1 * 512 + colLoc) = w1;
                *(float2*)(dst + o2 * 512 + colLoc) = w2;
            } else {
                float m1 = pm[r1] ? 1.0f : 0.0f;
                float m2 = pm[r2] ? 1.0f : 0.0f;
                const float* rr1 = R + (size_t)r1 * Nt + colG;
                const float* rr2 = R + (size_t)r2 * Nt + colG;
                float2 w1; w1.x = (v0 + rr1[0]) * m1; w1.y = (v1 + rr1[1]) * m1;
                float2 w2; w2.x = (v2 + rr2[0]) * m2; w2.y = (v3 + rr2[1]) * m2;
                *(float2*)(Cf + (size_t)r1 * Nt + colG) = w1;
                *(float2*)(Cf + (size_t)r2 * Nt + colG) = w2;
            }
        }
    }
}

// ---------------- weight convert (QKV concatenated) ----------------
struct WPtrs { const float* p[11]; };
__global__ void cvt_w_kernel(WPtrs wp) {
    // order: lq lk lv gq gk gv lo go f1 f2 f3
    const int sizes[11] = {262144,262144,262144,262144,262144,262144,262144,262144,
                           524288,1048576,524288};
    const int offs[11]  = {0,262144,524288, 786432,1048576,1310720,
                           1572864,1835008, 2097152,2621440,3670016};
    int wi = blockIdx.y;
    int i4 = blockIdx.x * blockDim.x + threadIdx.x;
    if (i4 >= (sizes[wi] >> 2)) return;
    float4 v = ((const float4*)wp.p[wi])[i4];
    ((uint2*)(g_w + offs[wi]))[i4] = pack4h(v);
}

struct BPtrs { const float* p[6]; };
__global__ void bias_cat_kernel(BPtrs bp) {
    int t = threadIdx.x;
    for (int i = 0; i < 6; i++)
        g_bcat[i * 512 + t] = bp.p[i][t];
}

// ---------------- local rope tables ----------------
__global__ void rope_init_kernel() {
    int idx = blockIdx.x * blockDim.x + threadIdx.x;
    if (idx >= 256 * 64) return;
    int t = idx >> 6, d = idx & 63;
    double inv = pow(10000.0, -(double)(d & 31) / 32.0);
    double a = (double)t * inv;
    g_lcos[idx] = (float)cos(a);
    g_lsin[idx] = (float)sin(a);
}

// ---------------- elementwise ----------------
__global__ void mask_mul4_kernel(const float* __restrict__ X,
                                 const int* __restrict__ pm,
                                 float* __restrict__ Y, int n4) {
    int i = blockIdx.x * blockDim.x + threadIdx.x;
    if (i >= n4) return;
    float m = pm[i >> 7] ? 1.0f : 0.0f;
    float4 v = ((const float4*)X)[i];
    v.x *= m; v.y *= m; v.z *= m; v.w *= m;
    ((float4*)Y)[i] = v;
}

// ---------------- layernorm -> fp16 ----------------
__global__ void __launch_bounds__(128) ln_kernel(
    const float* __restrict__ X, const float* __restrict__ g,
    const float* __restrict__ b, const int* __restrict__ pm,
    __half* __restrict__ Yh, int maskOut)
{
    int row = blockIdx.x;
    int tid = threadIdx.x;
    const float4* x4 = (const float4*)(X + (size_t)row * DD);
    float4 v = x4[tid];
    float s  = v.x + v.y + v.z + v.w;
    float ss = v.x*v.x + v.y*v.y + v.z*v.z + v.w*v.w;
    #pragma unroll
    for (int o = 16; o; o >>= 1) {
        s  += __shfl_xor_sync(~0u, s,  o);
        ss += __shfl_xor_sync(~0u, ss, o);
    }
    __shared__ float sh[8];
    int w = tid >> 5, lane = tid & 31;
    if (lane == 0) { sh[w] = s; sh[4 + w] = ss; }
    __syncthreads();
    s  = sh[0] + sh[1] + sh[2] + sh[3];
    ss = sh[4] + sh[5] + sh[6] + sh[7];
    float mean = s * (1.0f / 512.0f);
    float var  = ss * (1.0f / 512.0f) - mean * mean;
    float inv  = rsqrtf(var + 1e-5f);
    float m = maskOut ? (pm[row] ? 1.0f : 0.0f) : 1.0f;
    float4 gg = ((const float4*)g)[tid];
    float4 bb = ((const float4*)b)[tid];
    float4 o;
    o.x = ((v.x - mean) * inv * gg.x + bb.x) * m;
    o.y = ((v.y - mean) * inv * gg.y + bb.y) * m;
    o.z = ((v.z - mean) * inv * gg.z + bb.z) * m;
    o.w = ((v.w - mean) * inv * gg.w + bb.w) * m;
    ((uint2*)(Yh + (size_t)row * DD))[tid] = pack4h(o);
}

// ---------------- fill pad rows ----------------
__global__ void fill_pad_kernel(const float* __restrict__ kb, const float* __restrict__ vb) {
    int idx = blockIdx.x * blockDim.x + threadIdx.x;
    if (idx >= BB * 128 * DD) return;
    int c  = idx & 511;
    int rr = (idx >> 9) & 127;
    int b  = idx >> 16;
    int prow = (rr < 64) ? rr : (TT + rr);
    size_t o = ((size_t)b * TP + prow) * DD + c;
    g_kp[o] = kb[c];
    g_vp[o] = vb[c];
}

// ---------------- local attention (out: fp16) ----------------
#define LKS 68
#define LSS 257
__global__ void __launch_bounds__(256) local_attn_kernel(
    const float* __restrict__ Qg, const int* __restrict__ pm,
    __half* __restrict__ Oh)
{
    int j = blockIdx.x, h = blockIdx.y, b = blockIdx.z;
    extern __shared__ float smf[];
    float* Ks = smf;
    float* Vs = Ks + 256 * LKS;
    float* Qs = Vs + 256 * LKS;
    float* Ss = Qs + 32 * LKS;
    int*  keep = (int*)(Ss + 32 * LSS);
    int tid = threadIdx.x;

    for (int r0 = 0; r0 < 256; r0 += 4) {
        int r = r0 + (tid >> 6);
        int d = tid & 63;
        size_t base = ((size_t)b * TP + (size_t)j * 128 + r) * DD + h * HD;
        float kv = g_kp[base + d];
        float ko = g_kp[base + (d ^ 32)];
        float c = g_lcos[r * 64 + d], s = g_lsin[r * 64 + d];
        Ks[r * LKS + d] = (d < 32) ? (kv * c - ko * s) : (kv * c + ko * s);
        Vs[r * LKS + d] = g_vp[base + d];
    }
    if (tid < 256) {
        int orig = j * 128 + tid - 64;
        keep[tid] = (orig >= 0 && orig < TT && pm[(size_t)b * TT + orig]) ? 1 : 0;
    }
    __syncthreads();
    if (tid == 0) {
        int any = 0;
        for (int i = 0; i < 256; i++) any |= keep[i];
        if (!any) keep[0] = 1;
    }
    __syncthreads();

    for (int c0 = 0; c0 < 128; c0 += 32) {
        for (int r0 = 0; r0 < 32; r0 += 4) {
            int i = r0 + (tid >> 6);
            int d = tid & 63;
            int t = j * 128 + c0 + i;
            size_t base = ((size_t)b * TT + t) * DD + h * HD;
            float qv = Qg[base + d];
            float qo = Qg[base + (d ^ 32)];
            int ti = 64 + c0 + i;
            float c = g_lcos[ti * 64 + d], s = g_lsin[ti * 64 + d];
            Qs[i * LKS + d] = (d < 32) ? (qv * c - qo * s) : (qv * c + qo * s);
        }
        __syncthreads();

        {
            int qi = tid & 31;
            int kb = (tid >> 5) * 32;
            float acc[32];
            #pragma unroll
            for (int i = 0; i < 32; i++) acc[i] = 0.0f;
            for (int d0 = 0; d0 < 64; d0 += 16) {
                float qr[16];
                #pragma unroll
                for (int dd = 0; dd < 16; dd += 4) {
                    float4 qv = *(const float4*)&Qs[qi * LKS + d0 + dd];
                    qr[dd] = qv.x; qr[dd+1] = qv.y; qr[dd+2] = qv.z; qr[dd+3] = qv.w;
                }
                #pragma unroll 4
                for (int kk = 0; kk < 32; kk++) {
                    const float* kp = &Ks[(kb + kk) * LKS + d0];
                    #pragma unroll
                    for (int dd = 0; dd < 16; dd += 4) {
                        float4 kv = *(const float4*)(kp + dd);
                        acc[kk] += qr[dd] * kv.x + qr[dd+1] * kv.y
                                 + qr[dd+2] * kv.z + qr[dd+3] * kv.w;
                    }
                }
            }
            #pragma unroll
            for (int kk = 0; kk < 32; kk++) {
                int k = kb + kk;
                Ss[qi * LSS + k] = keep[k] ? acc[kk] * 0.125f : -1e9f;
            }
        }
        __syncthreads();

        {
            int wp = tid >> 5, lane = tid & 31;
            for (int rr = 0; rr < 4; rr++) {
                int r = wp * 4 + rr;
                float* row = Ss + r * LSS;
                float vals[8];
                float mx = -1e30f;
                #pragma unroll
                for (int m = 0; m < 8; m++) {
                    vals[m] = row[lane + 32 * m];
                    mx = fmaxf(mx, vals[m]);
                }
                #pragma unroll
                for (int o = 16; o; o >>= 1) mx = fmaxf(mx, __shfl_xor_sync(~0u, mx, o));
                float sum = 0.0f;
                #pragma unroll
                for (int m = 0; m < 8; m++) { vals[m] = expf(vals[m] - mx); sum += vals[m]; }
                #pragma unroll
                for (int o = 16; o; o >>= 1) sum += __shfl_xor_sync(~0u, sum, o);
                float inv = 1.0f / sum;
                #pragma unroll
                for (int m = 0; m < 8; m++) row[lane + 32 * m] = vals[m] * inv;
            }
        }
        __syncthreads();

        {
            int qi = tid & 31;
            int db = (tid >> 5) * 8;
            float acc[8];
            #pragma unroll
            for (int i = 0; i < 8; i++) acc[i] = 0.0f;
            #pragma unroll 4
            for (int k = 0; k < 256; k++) {
                float p = Ss[qi * LSS + k];
                float4 v0 = *(const float4*)&Vs[k * LKS + db];
                float4 v1 = *(const float4*)&Vs[k * LKS + db + 4];
                acc[0] += p * v0.x; acc[1] += p * v0.y;
                acc[2] += p * v0.z; acc[3] += p * v0.w;
                acc[4] += p * v1.x; acc[5] += p * v1.y;
                acc[6] += p * v1.z; acc[7] += p * v1.w;
            }
            int t = j * 128 + c0 + qi;
            size_t base = ((size_t)b * TT + t) * DD + h * HD + db;
            float4 p0; p0.x = acc[0]; p0.y = acc[1]; p0.z = acc[2]; p0.w = acc[3];
            float4 p1; p1.x = acc[4]; p1.y = acc[5]; p1.z = acc[6]; p1.w = acc[7];
            *(uint2*)(Oh + base)     = pack4h(p0);
            *(uint2*)(Oh + base + 4) = pack4h(p1);
        }
        __syncthreads();
    }
}

// ---------------- global attention (out: fp16) ----------------
__global__ void __launch_bounds__(256) global_attn_kernel(
    const float* __restrict__ Qg, const float* __restrict__ Kg,
    const float* __restrict__ Vg, const int* __restrict__ pm,
    const float* __restrict__ cosp, const float* __restrict__ sinp,
    __half* __restrict__ Oh)
{
    int w = blockIdx.x, h = blockIdx.y, b = blockIdx.z;
    extern __shared__ float smf[];
    float* Qs = smf;
    float* Ks = Qs + 64 * LKS;
    float* Vs = Ks + 64 * LKS;
    float* Ss = Vs + 64 * LKS;
    int*  keep = (int*)(Ss + 64 * LSS);
    int tid = threadIdx.x;

    for (int r0 = 0; r0 < 64; r0 += 4) {
        int nn = r0 + (tid >> 6);
        int d = tid & 63;
        int p = nn * 64 + w;
        size_t base = ((size_t)b * TT + p) * DD + h * HD;
        float c = cosp[p * 64 + d], s = sinp[p * 64 + d];
        float qv = Qg[base + d], qo = Qg[base + (d ^ 32)];
        float kv = Kg[base + d], ko = Kg[base + (d ^ 32)];
        Qs[nn * LKS + d] = (d < 32) ? (qv * c - qo * s) : (qv * c + qo * s);
        Ks[nn * LKS + d] = (d < 32) ? (kv * c - ko * s) : (kv * c + ko * s);
        Vs[nn * LKS + d] = Vg[base + d];
    }
    if (tid < 64) keep[tid] = pm[(size_t)b * TT + tid * 64 + w] ? 1 : 0;
    __syncthreads();

    {
        int qi = tid & 63;
        int kb = (tid >> 6) * 16;
        float acc[16];
        #pragma unroll
        for (int i = 0; i < 16; i++) acc[i] = 0.0f;
        for (int d0 = 0; d0 < 64; d0 += 16) {
            float qr[16];
            #pragma unroll
            for (int dd = 0; dd < 16; dd += 4) {
                float4 qv = *(const float4*)&Qs[qi * LKS + d0 + dd];
                qr[dd] = qv.x; qr[dd+1] = qv.y; qr[dd+2] = qv.z; qr[dd+3] = qv.w;
            }
            #pragma unroll 4
            for (int kk = 0; kk < 16; kk++) {
                const float* kp = &Ks[(kb + kk) * LKS + d0];
                #pragma unroll
                for (int dd = 0; dd < 16; dd += 4) {
                    float4 kv = *(const float4*)(kp + dd);
                    acc[kk] += qr[dd] * kv.x + qr[dd+1] * kv.y
                             + qr[dd+2] * kv.z + qr[dd+3] * kv.w;
                }
            }
        }
        #pragma unroll
        for (int kk = 0; kk < 16; kk++) {
            int k = kb + kk;
            Ss[qi * LSS + k] = keep[k] ? acc[kk] * 0.125f : -1e9f;
        }
    }
    __syncthreads();

    {
        int wp = tid >> 5, lane = tid & 31;
        for (int rr = 0; rr < 8; rr++) {
            int r = wp * 8 + rr;
            float* row = Ss + r * LSS;
            float a0 = row[lane], a1 = row[lane + 32];
            float mx = fmaxf(a0, a1);
            #pragma unroll
            for (int o = 16; o; o >>= 1) mx = fmaxf(mx, __shfl_xor_sync(~0u, mx, o));
            float e0 = expf(a0 - mx), e1 = expf(a1 - mx);
            float sum = e0 + e1;
            #pragma unroll
            for (int o = 16; o; o >>= 1) sum += __shfl_xor_sync(~0u, sum, o);
            float inv = 1.0f / sum;
            row[lane] = e0 * inv; row[lane + 32] = e1 * inv;
        }
    }
    __syncthreads();

    {
        int qi = tid & 63;
        int db = (tid >> 6) * 16;
        float acc[16];
        #pragma unroll
        for (int i = 0; i < 16; i++) acc[i] = 0.0f;
        #pragma unroll 4
        for (int k = 0; k < 64; k++) {
            float p = Ss[qi * LSS + k];
            #pragma unroll
            for (int dd = 0; dd < 16; dd += 4) {
                float4 v = *(const float4*)&Vs[k * LKS + db + dd];
                acc[dd]   += p * v.x; acc[dd+1] += p * v.y;
                acc[dd+2] += p * v.z; acc[dd+3] += p * v.w;
            }
        }
        int p = qi * 64 + w;
        size_t base = ((size_t)b * TT + p) * DD + h * HD + db;
        #pragma unroll
        for (int dd = 0; dd < 16; dd += 4) {
            float4 pv;
            pv.x = acc[dd]; pv.y = acc[dd+1]; pv.z = acc[dd+2]; pv.w = acc[dd+3];
            *(uint2*)(Oh + base + dd) = pack4h(pv);
        }
    }
}

// ---------------- host ----------------
extern "C" void kernel_launch(void* const* d_in, const int* in_sizes, int n_in,
                              void* d_out, int out_size)
{
    const float* x    = (const float*)d_in[0];
    const int*   pm   = (const int*)d_in[1];
    const float* cosp = (const float*)d_in[2];
    const float* sinp = (const float*)d_in[3];
    const float* ln1_g = (const float*)d_in[4];
    const float* ln1_b = (const float*)d_in[5];
    const float* ln2_g = (const float*)d_in[6];
    const float* ln2_b = (const float*)d_in[7];
    const float* ln3_g = (const float*)d_in[8];
    const float* ln3_b = (const float*)d_in[9];
    const float* lq_w = (const float*)d_in[10];
    const float* lq_b = (const float*)d_in[11];
    const float* lk_w = (const float*)d_in[12];
    const float* lk_b = (const float*)d_in[13];
    const float* lv_w = (const float*)d_in[14];
    const float* lv_b = (const float*)d_in[15];
    const float* lo_w = (const float*)d_in[16];
    const float* lo_b = (const float*)d_in[17];
    const float* gq_w = (const float*)d_in[18];
    const float* gq_b = (const float*)d_in[19];
    const float* gk_w = (const float*)d_in[20];
    const float* gk_b = (const float*)d_in[21];
    const float* gv_w = (const float*)d_in[22];
    const float* gv_b = (const float*)d_in[23];
    const float* go_w = (const float*)d_in[24];
    const float* go_b = (const float*)d_in[25];
    const float* f1_w = (const float*)d_in[26];
    const float* f1_b = (const float*)d_in[27];
    const float* f2_w = (const float*)d_in[28];
    const float* f2_b = (const float*)d_in[29];
    const float* f3_w = (const float*)d_in[30];
    const float* f3_b = (const float*)d_in[31];
    float* out = (float*)d_out;

    float *px, *pq, *pkp, *pvp, *pbcat;
    __half *pxn, *patt, *ph1, *ph2, *pw;
    cudaGetSymbolAddress((void**)&px,    g_x);
    cudaGetSymbolAddress((void**)&pq,    g_q);
    cudaGetSymbolAddress((void**)&pkp,   g_kp);
    cudaGetSymbolAddress((void**)&pvp,   g_vp);
    cudaGetSymbolAddress((void**)&pbcat, g_bcat);
    cudaGetSymbolAddress((void**)&pxn,   g_xn);
    cudaGetSymbolAddress((void**)&patt,  g_att);
    cudaGetSymbolAddress((void**)&ph1,   g_h1);
    cudaGetSymbolAddress((void**)&ph2,   g_h2);
    cudaGetSymbolAddress((void**)&pw,    g_w);

    const int M = BB * TT;
    const int n4 = M * DD / 4;
    const int EW = 256;

    size_t smLoc = (size_t)(2 * 256 * LKS + 32 * LKS + 32 * LSS) * 4 + 256 * 4;
    size_t smGlb = (size_t)(3 * 64 * LKS + 64 * LSS) * 4 + 64 * 4;
    cudaFuncSetAttribute(local_attn_kernel,  cudaFuncAttributeMaxDynamicSharedMemorySize, (int)smLoc);
    cudaFuncSetAttribute(global_attn_kernel, cudaFuncAttributeMaxDynamicSharedMemorySize, (int)smGlb);
    cudaFuncSetAttribute(gemm_mma_kernel, cudaFuncAttributeMaxDynamicSharedMemorySize, 65536);

    const int OLQKV=0, OGQKV=786432, OLO=1572864, OGO=1835008,
              OF1=2097152, OF2=2621440, OF3=3670016;

    dim3 gQKV(12, M / 128);
    dim3 g512(4,  M / 128);
    dim3 g1k (8,  M / 128);

    rope_init_kernel<<<64, 256>>>();
    WPtrs wp;
    wp.p[0]=lq_w; wp.p[1]=lk_w; wp.p[2]=lv_w; wp.p[3]=gq_w; wp.p[4]=gk_w;
    wp.p[5]=gv_w; wp.p[6]=lo_w; wp.p[7]=go_w; wp.p[8]=f1_w; wp.p[9]=f2_w; wp.p[10]=f3_w;
    cvt_w_kernel<<<dim3(1024, 11), 256>>>(wp);
    BPtrs bp;
    bp.p[0]=lq_b; bp.p[1]=lk_b; bp.p[2]=lv_b; bp.p[3]=gq_b; bp.p[4]=gk_b; bp.p[5]=gv_b;
    bias_cat_kernel<<<1, 512>>>(bp);

    mask_mul4_kernel<<<(n4 + EW - 1) / EW, EW>>>(x, pm, px, n4);
    ln_kernel<<<M, 128>>>(px, ln1_g, ln1_b, pm, pxn, 1);

    // local QKV fused (k/v padded scatter)
    gemm_mma_kernel<<<gQKV, 512, 65536>>>(pxn, pw+OLQKV, pbcat,
                                          pq, 0, pkp, pvp, 0, 0, DD, DD, 0, 2, 1);
    fill_pad_kernel<<<(BB * 128 * DD + EW - 1) / EW, EW>>>(lk_b, lv_b);

    local_attn_kernel<<<dim3(NLOC, HH, BB), 256, smLoc>>>(pq, pm, patt);

    // O proj + residual + mask (in place on px)
    gemm_mma_kernel<<<g512, 512, 65536>>>(patt, pw+OLO, lo_b,
                                          px, 0, 0, 0, px, pm, DD, DD, 0, 3, 0);

    ln_kernel<<<M, 128>>>(px, ln2_g, ln2_b, pm, pxn, 0);

    // global QKV fused (plain layout)
    gemm_mma_kernel<<<gQKV, 512, 65536>>>(pxn, pw+OGQKV, pbcat + 1536,
                                          pq, 0, pkp, pvp, 0, 0, DD, DD, 0, 2, 0);

    global_attn_kernel<<<dim3(NDIL, HH, BB), 256, smGlb>>>(pq, pkp, pvp, pm, cosp, sinp, patt);

    gemm_mma_kernel<<<g512, 512, 65536>>>(patt, pw+OGO, go_b,
                                          px, 0, 0, 0, px, pm, DD, DD, 0, 3, 0);

    ln_kernel<<<M, 128>>>(px, ln3_g, ln3_b, pm, pxn, 0);
    gemm_mma_kernel<<<g1k,  512, 65536>>>(pxn, pw+OF1, f1_b,
                                          0, ph1, 0, 0, 0, 0, 512,  1024, 1, 1, 0);
    gemm_mma_kernel<<<g1k,  512, 65536>>>(ph1, pw+OF2, f2_b,
                                          0, ph2, 0, 0, 0, 0, 1024, 1024, 1, 1, 0);
    // f3 + residual + mask -> out
    gemm_mma_kernel<<<g512, 512, 65536>>>(ph2, pw+OF3, f3_b,
                                          out, 0, 0, 0, px, pm, 1024, 512, 0, 3, 0);
}

// round 9
// speedup vs baseline: 5.1733x; 1.9431x over previous
#include <cuda_runtime.h>
#include <cuda_bf16.h>
#include <cuda_fp16.h>
#include <math.h>
#include <stdint.h>

#define BB 8
#define TT 4096
#define DD 512
#define HH 8
#define HD 64
#define TP 4224
#define NLOC 32
#define NDIL 64

// ---------------- scratch ----------------
__device__ float g_x  [BB*TT*DD];
__device__ __half g_q  [BB*TT*DD];
__device__ __half g_kp [BB*TP*DD];
__device__ __half g_vp [BB*TP*DD];
__device__ __half g_xn [BB*TT*DD];
__device__ __half g_att[BB*TT*DD];
__device__ __half g_h1 [BB*TT*1024];
__device__ __half g_h2 [BB*TT*1024];
__device__ __half g_w  [4194304];
__device__ float g_bcat[3072];
__device__ float g_lcos[256*64];
__device__ float g_lsin[256*64];

// ---------------- helpers ----------------
__device__ __forceinline__ uint32_t smem_u32(const void* p) {
    uint32_t a;
    asm("{ .reg .u64 t; cvta.to.shared.u64 t, %1; cvt.u32.u64 %0, t; }" : "=r"(a) : "l"(p));
    return a;
}
__device__ __forceinline__ void ldsm4(uint32_t* r, uint32_t addr) {
    asm volatile("ldmatrix.sync.aligned.m8n8.x4.shared.b16 {%0,%1,%2,%3}, [%4];"
        : "=r"(r[0]), "=r"(r[1]), "=r"(r[2]), "=r"(r[3]) : "r"(addr));
}
__device__ __forceinline__ void ldsm4t(uint32_t* r, uint32_t addr) {
    asm volatile("ldmatrix.sync.aligned.m8n8.x4.trans.shared.b16 {%0,%1,%2,%3}, [%4];"
        : "=r"(r[0]), "=r"(r[1]), "=r"(r[2]), "=r"(r[3]) : "r"(addr));
}
__device__ __forceinline__ void mma_f16(float* c, const uint32_t* a, uint32_t b0, uint32_t b1) {
    asm volatile("mma.sync.aligned.m16n8k16.row.col.f32.f16.f16.f32 "
        "{%0,%1,%2,%3}, {%4,%5,%6,%7}, {%8,%9}, {%0,%1,%2,%3};"
        : "+f"(c[0]), "+f"(c[1]), "+f"(c[2]), "+f"(c[3])
        : "r"(a[0]), "r"(a[1]), "r"(a[2]), "r"(a[3]), "r"(b0), "r"(b1));
}
#define SWZ64(x) ((x) ^ (((x) >> 3) & 0x30))
#define CPA(dst, src) asm volatile("cp.async.cg.shared.global [%0], [%1], 16;" :: "r"(dst), "l"(src))
#define CPC() asm volatile("cp.async.commit_group;" ::: "memory")
#define CPW(n) asm volatile("cp.async.wait_group %0;" :: "n"(n) : "memory")

__device__ __forceinline__ uint32_t packh(float a, float b) {
    __half2 h = __floats2half2_rn(a, b);
    return *(uint32_t*)&h;
}
__device__ __forceinline__ uint2 pack4h(float4 v) {
    uint2 r; r.x = packh(v.x, v.y); r.y = packh(v.z, v.w); return r;
}

// ---------------- GEMM (fp16): modes 1=fp16 out, 2=QKV triple (fp16), 3=fp32+res+mask ----
__global__ void __launch_bounds__(512, 1) gemm_mma_kernel(
    const __half* __restrict__ A, const __half* __restrict__ W,
    const float* __restrict__ bias,
    float* __restrict__ Cf, __half* __restrict__ Ch,
    __half* __restrict__ Ck, __half* __restrict__ Cv,
    const float* __restrict__ R, const int* __restrict__ pm,
    int K, int Nt, int act, int mode, int padKV)
{
    extern __shared__ char sm[];
    uint32_t smb = smem_u32(sm);
    int tid = threadIdx.x, lane = tid & 31, wid = tid >> 5;
    int row0 = blockIdx.y * 128, col0 = blockIdx.x * 128;
    int wm = (wid & 3) * 32, wn = (wid >> 2) * 32;

    float acc[2][4][4];
    #pragma unroll
    for (int i = 0; i < 2; i++)
        #pragma unroll
        for (int j = 0; j < 4; j++)
            #pragma unroll
            for (int c = 0; c < 4; c++) acc[i][j][c] = 0.0f;

    int srow = tid >> 2, sc16 = tid & 3;
    uint32_t sdst = SWZ64((uint32_t)(srow * 64 + sc16 * 16));
    size_t gA = (size_t)(row0 + srow) * K + sc16 * 8;
    size_t gW = (size_t)(col0 + srow) * K + sc16 * 8;

    uint32_t aoff[2], boff[2];
    #pragma unroll
    for (int i = 0; i < 2; i++) {
        int r = wm + i * 16 + (lane & 15);
        aoff[i] = r * 64 + ((lane >> 4) << 4);
    }
    #pragma unroll
    for (int j = 0; j < 2; j++) {
        int r = wn + j * 16 + (lane & 7) + ((lane >> 4) & 1) * 8;
        boff[j] = r * 64 + (((lane >> 3) & 1) << 4);
    }

    int nch = K >> 5;
    #define G_ISSUE(ch) { \
        uint32_t st_ = smb + ((ch) & 3) * 16384; \
        size_t k0_ = (size_t)(ch) * 32; \
        CPA(st_ + sdst,        A + gA + k0_); \
        CPA(st_ + 8192 + sdst, W + gW + k0_); \
        CPC(); }

    G_ISSUE(0); G_ISSUE(1); G_ISSUE(2);

    for (int ch = 0; ch < nch; ch++) {
        CPW(2);
        __syncthreads();
        if (ch + 3 < nch) { G_ISSUE(ch + 3); } else { CPC(); }
        uint32_t st = smb + (ch & 3) * 16384;
        #pragma unroll
        for (int ks = 0; ks < 2; ks++) {
            uint32_t ah[2][4], bh[2][4];
            #pragma unroll
            for (int i = 0; i < 2; i++)
                ldsm4(ah[i], st + SWZ64(aoff[i] + ks * 32));
            #pragma unroll
            for (int j = 0; j < 2; j++)
                ldsm4(bh[j], st + 8192 + SWZ64(boff[j] + ks * 32));
            #pragma unroll
            for (int i = 0; i < 2; i++)
                #pragma unroll
                for (int j = 0; j < 2; j++) {
                    mma_f16(acc[i][2*j],   ah[i], bh[j][0], bh[j][1]);
                    mma_f16(acc[i][2*j+1], ah[i], bh[j][2], bh[j][3]);
                }
        }
    }

    // epilogue
    int g = lane >> 2, t4 = lane & 3;
    int seg = col0 >> 9;
    #pragma unroll
    for (int i = 0; i < 2; i++) {
        int r1 = row0 + wm + i * 16 + g;
        int r2 = r1 + 8;
        #pragma unroll
        for (int nj = 0; nj < 4; nj++) {
            int colG = col0 + wn + nj * 8 + t4 * 2;
            float b0 = bias[colG], b1 = bias[colG + 1];
            float v0 = acc[i][nj][0] + b0, v1 = acc[i][nj][1] + b1;
            float v2 = acc[i][nj][2] + b0, v3 = acc[i][nj][3] + b1;
            if (act) {
                v0 = 0.5f * v0 * (1.0f + erff(v0 * 0.70710678118654752f));
                v1 = 0.5f * v1 * (1.0f + erff(v1 * 0.70710678118654752f));
                v2 = 0.5f * v2 * (1.0f + erff(v2 * 0.70710678118654752f));
                v3 = 0.5f * v3 * (1.0f + erff(v3 * 0.70710678118654752f));
            }
            if (mode == 1) {
                *(uint32_t*)(Ch + (size_t)r1 * Nt + colG) = packh(v0, v1);
                *(uint32_t*)(Ch + (size_t)r2 * Nt + colG) = packh(v2, v3);
            } else if (mode == 2) {
                int colLoc = colG - (seg << 9);
                __half* dst = (seg == 0) ? Ch : (seg == 1 ? Ck : Cv);
                int doPad = (seg != 0) && padKV;
                size_t o1 = doPad ? ((size_t)(r1 >> 12) * TP + 64 + (r1 & 4095)) : (size_t)r1;
                size_t o2 = doPad ? ((size_t)(r2 >> 12) * TP + 64 + (r2 & 4095)) : (size_t)r2;
                *(uint32_t*)(dst + o1 * 512 + colLoc) = packh(v0, v1);
                *(uint32_t*)(dst + o2 * 512 + colLoc) = packh(v2, v3);
            } else {
                float m1 = pm[r1] ? 1.0f : 0.0f;
                float m2 = pm[r2] ? 1.0f : 0.0f;
                const float* rr1 = R + (size_t)r1 * Nt + colG;
                const float* rr2 = R + (size_t)r2 * Nt + colG;
                float2 w1; w1.x = (v0 + rr1[0]) * m1; w1.y = (v1 + rr1[1]) * m1;
                float2 w2; w2.x = (v2 + rr2[0]) * m2; w2.y = (v3 + rr2[1]) * m2;
                *(float2*)(Cf + (size_t)r1 * Nt + colG) = w1;
                *(float2*)(Cf + (size_t)r2 * Nt + colG) = w2;
            }
        }
    }
}

// ---------------- weight convert ----------------
struct WPtrs { const float* p[11]; };
__global__ void cvt_w_kernel(WPtrs wp) {
    const int sizes[11] = {262144,262144,262144,262144,262144,262144,262144,262144,
                           524288,1048576,524288};
    const int offs[11]  = {0,262144,524288, 786432,1048576,1310720,
                           1572864,1835008, 2097152,2621440,3670016};
    int wi = blockIdx.y;
    int i4 = blockIdx.x * blockDim.x + threadIdx.x;
    if (i4 >= (sizes[wi] >> 2)) return;
    float4 v = ((const float4*)wp.p[wi])[i4];
    ((uint2*)(g_w + offs[wi]))[i4] = pack4h(v);
}

struct BPtrs { const float* p[6]; };
__global__ void bias_cat_kernel(BPtrs bp) {
    int t = threadIdx.x;
    for (int i = 0; i < 6; i++)
        g_bcat[i * 512 + t] = bp.p[i][t];
}

// ---------------- local rope tables ----------------
__global__ void rope_init_kernel() {
    int idx = blockIdx.x * blockDim.x + threadIdx.x;
    if (idx >= 256 * 64) return;
    int t = idx >> 6, d = idx & 63;
    double inv = pow(10000.0, -(double)(d & 31) / 32.0);
    double a = (double)t * inv;
    g_lcos[idx] = (float)cos(a);
    g_lsin[idx] = (float)sin(a);
}

// ---------------- elementwise ----------------
__global__ void mask_mul4_kernel(const float* __restrict__ X,
                                 const int* __restrict__ pm,
                                 float* __restrict__ Y, int n4) {
    int i = blockIdx.x * blockDim.x + threadIdx.x;
    if (i >= n4) return;
    float m = pm[i >> 7] ? 1.0f : 0.0f;
    float4 v = ((const float4*)X)[i];
    v.x *= m; v.y *= m; v.z *= m; v.w *= m;
    ((float4*)Y)[i] = v;
}

// ---------------- layernorm -> fp16 ----------------
__global__ void __launch_bounds__(128) ln_kernel(
    const float* __restrict__ X, const float* __restrict__ g,
    const float* __restrict__ b, const int* __restrict__ pm,
    __half* __restrict__ Yh, int maskOut)
{
    int row = blockIdx.x;
    int tid = threadIdx.x;
    const float4* x4 = (const float4*)(X + (size_t)row * DD);
    float4 v = x4[tid];
    float s  = v.x + v.y + v.z + v.w;
    float ss = v.x*v.x + v.y*v.y + v.z*v.z + v.w*v.w;
    #pragma unroll
    for (int o = 16; o; o >>= 1) {
        s  += __shfl_xor_sync(~0u, s,  o);
        ss += __shfl_xor_sync(~0u, ss, o);
    }
    __shared__ float sh[8];
    int w = tid >> 5, lane = tid & 31;
    if (lane == 0) { sh[w] = s; sh[4 + w] = ss; }
    __syncthreads();
    s  = sh[0] + sh[1] + sh[2] + sh[3];
    ss = sh[4] + sh[5] + sh[6] + sh[7];
    float mean = s * (1.0f / 512.0f);
    float var  = ss * (1.0f / 512.0f) - mean * mean;
    float inv  = rsqrtf(var + 1e-5f);
    float m = maskOut ? (pm[row] ? 1.0f : 0.0f) : 1.0f;
    float4 gg = ((const float4*)g)[tid];
    float4 bb = ((const float4*)b)[tid];
    float4 o;
    o.x = ((v.x - mean) * inv * gg.x + bb.x) * m;
    o.y = ((v.y - mean) * inv * gg.y + bb.y) * m;
    o.z = ((v.z - mean) * inv * gg.z + bb.z) * m;
    o.w = ((v.w - mean) * inv * gg.w + bb.w) * m;
    ((uint2*)(Yh + (size_t)row * DD))[tid] = pack4h(o);
}

// ---------------- fill pad rows (fp16) ----------------
__global__ void fill_pad_kernel(const float* __restrict__ kb, const float* __restrict__ vb) {
    int idx = blockIdx.x * blockDim.x + threadIdx.x;
    if (idx >= BB * 128 * DD) return;
    int c  = idx & 511;
    int rr = (idx >> 9) & 127;
    int b  = idx >> 16;
    int prow = (rr < 64) ? rr : (TT + rr);
    size_t o = ((size_t)b * TP + prow) * DD + c;
    g_kp[o] = __float2half(kb[c]);
    g_vp[o] = __float2half(vb[c]);
}

// ---------------- local attention (mma, online softmax over 4 chunks of 64 keys) ----------------
#define ATS 72   // smem row stride in halves (144B)
__global__ void __launch_bounds__(256, 1) local_attn_kernel(
    const __half* __restrict__ Qg, const int* __restrict__ pm,
    __half* __restrict__ Og)
{
    int j = blockIdx.x, h = blockIdx.y, b = blockIdx.z;
    extern __shared__ char smc[];
    __half* Ks = (__half*)smc;                 // 256 x 72
    __half* Vs = Ks + 256 * ATS;               // 256 x 72
    __half* Qs = Vs + 256 * ATS;               // 128 x 72
    float* keepneg = (float*)(Qs + 128 * ATS); // 256
    int tid = threadIdx.x, lane = tid & 31;

    // load K (rope) and V, fp16
    #pragma unroll 4
    for (int it = 0; it < 32; it++) {
        int idx = tid + it * 256;
        int r = idx >> 5, d = (idx & 31) * 2;
        size_t base = ((size_t)b * TP + (size_t)j * 128 + r) * DD + h * HD;
        float c0 = g_lcos[r * 64 + d], c1 = g_lcos[r * 64 + d + 1];
        float s0 = g_lsin[r * 64 + d], s1 = g_lsin[r * 64 + d + 1];
        float k0 = __half2float(Qg == 0 ? __float2half(0.f) : g_kp[base + d]);  // (never taken branch removed below)
        k0 = __half2float(g_kp[base + d]);
        float k1 = __half2float(g_kp[base + d + 1]);
        float o0 = __half2float(g_kp[base + (d ^ 32)]);
        float o1 = __half2float(g_kp[base + (d ^ 32) + 1]);
        float r0 = (d < 32) ? (k0 * c0 - o0 * s0) : (k0 * c0 + o0 * s0);
        float r1 = (d < 32) ? (k1 * c1 - o1 * s1) : (k1 * c1 + o1 * s1);
        *(uint32_t*)&Ks[r * ATS + d] = packh(r0, r1);
        *(uint32_t*)&Vs[r * ATS + d] = *(const uint32_t*)&g_vp[base + d];
    }
    // load Q (rope)
    #pragma unroll 4
    for (int it = 0; it < 16; it++) {
        int idx = tid + it * 256;
        int r = idx >> 5, d = (idx & 31) * 2;
        size_t base = ((size_t)b * TT + (size_t)j * 128 + r) * DD + h * HD;
        int ti = 64 + r;
        float c0 = g_lcos[ti * 64 + d], c1 = g_lcos[ti * 64 + d + 1];
        float s0 = g_lsin[ti * 64 + d], s1 = g_lsin[ti * 64 + d + 1];
        float q0 = __half2float(Qg[base + d]);
        float q1 = __half2float(Qg[base + d + 1]);
        float o0 = __half2float(Qg[base + (d ^ 32)]);
        float o1 = __half2float(Qg[base + (d ^ 32) + 1]);
        float r0 = (d < 32) ? (q0 * c0 - o0 * s0) : (q0 * c0 + o0 * s0);
        float r1 = (d < 32) ? (q1 * c1 - o1 * s1) : (q1 * c1 + o1 * s1);
        *(uint32_t*)&Qs[r * ATS + d] = packh(r0, r1);
    }
    if (tid < 256) {
        int orig = j * 128 + tid - 64;
        keepneg[tid] = (orig >= 0 && orig < TT && pm[(size_t)b * TT + orig]) ? 0.0f : -1e9f;
    }
    __syncthreads();
    if (tid == 0) {
        int any = 0;
        for (int i = 0; i < 256; i++) any |= (keepneg[i] == 0.0f);
        if (!any) keepneg[0] = 0.0f;
    }
    __syncthreads();

    int m0 = (tid >> 5) * 16;
    float O[8][4];
    #pragma unroll
    for (int n = 0; n < 8; n++)
        #pragma unroll
        for (int c = 0; c < 4; c++) O[n][c] = 0.0f;
    float mr_lo = -1e30f, mr_hi = -1e30f, sr_lo = 0.0f, sr_hi = 0.0f;

    uint32_t qbase = smem_u32(Qs) + (uint32_t)(((m0 + (lane & 15)) * ATS + ((lane >> 4) << 3)) * 2);
    uint32_t kbaseS = smem_u32(Ks);
    uint32_t vbaseS = smem_u32(Vs);
    uint32_t krow = (lane & 7) + ((lane >> 4) & 1) * 8;
    uint32_t kcol = ((lane >> 3) & 1) * 8;
    uint32_t vrow = (lane & 15);
    uint32_t vcol = (lane >> 4) * 8;

    for (int ck = 0; ck < 4; ck++) {
        int k0 = ck * 64;
        float S[8][4];
        #pragma unroll
        for (int n = 0; n < 8; n++)
            #pragma unroll
            for (int c = 0; c < 4; c++) S[n][c] = 0.0f;
        #pragma unroll
        for (int kt = 0; kt < 4; kt++) {
            uint32_t aq[4];
            ldsm4(aq, qbase + kt * 32);
            #pragma unroll
            for (int ntp = 0; ntp < 4; ntp++) {
                uint32_t bk[4];
                ldsm4(bk, kbaseS + (uint32_t)(((k0 + ntp * 16 + krow) * ATS + kt * 16 + kcol) * 2));
                mma_f16(S[2*ntp],   aq, bk[0], bk[1]);
                mma_f16(S[2*ntp+1], aq, bk[2], bk[3]);
            }
        }
        // scale + mask + chunk max
        float cm_lo = -1e30f, cm_hi = -1e30f;
        #pragma unroll
        for (int nt = 0; nt < 8; nt++) {
            int colg = k0 + nt * 8 + (lane & 3) * 2;
            float kn0 = keepneg[colg], kn1 = keepneg[colg + 1];
            S[nt][0] = S[nt][0] * 0.125f + kn0;
            S[nt][1] = S[nt][1] * 0.125f + kn1;
            S[nt][2] = S[nt][2] * 0.125f + kn0;
            S[nt][3] = S[nt][3] * 0.125f + kn1;
            cm_lo = fmaxf(cm_lo, fmaxf(S[nt][0], S[nt][1]));
            cm_hi = fmaxf(cm_hi, fmaxf(S[nt][2], S[nt][3]));
        }
        cm_lo = fmaxf(cm_lo, __shfl_xor_sync(~0u, cm_lo, 1));
        cm_lo = fmaxf(cm_lo, __shfl_xor_sync(~0u, cm_lo, 2));
        cm_hi = fmaxf(cm_hi, __shfl_xor_sync(~0u, cm_hi, 1));
        cm_hi = fmaxf(cm_hi, __shfl_xor_sync(~0u, cm_hi, 2));
        float mn_lo = fmaxf(mr_lo, cm_lo), mn_hi = fmaxf(mr_hi, cm_hi);
        float al_lo = expf(mr_lo - mn_lo), al_hi = expf(mr_hi - mn_hi);
        mr_lo = mn_lo; mr_hi = mn_hi;
        sr_lo *= al_lo; sr_hi *= al_hi;
        #pragma unroll
        for (int n = 0; n < 8; n++) {
            O[n][0] *= al_lo; O[n][1] *= al_lo;
            O[n][2] *= al_hi; O[n][3] *= al_hi;
        }
        uint32_t pa[4][4];
        #pragma unroll
        for (int kt = 0; kt < 4; kt++) {
            int t0 = 2 * kt, t1 = 2 * kt + 1;
            float p00 = expf(S[t0][0] - mn_lo), p01 = expf(S[t0][1] - mn_lo);
            float p02 = expf(S[t0][2] - mn_hi), p03 = expf(S[t0][3] - mn_hi);
            float p10 = expf(S[t1][0] - mn_lo), p11 = expf(S[t1][1] - mn_lo);
            float p12 = expf(S[t1][2] - mn_hi), p13 = expf(S[t1][3] - mn_hi);
            sr_lo += p00 + p01 + p10 + p11;
            sr_hi += p02 + p03 + p12 + p13;
            pa[kt][0] = packh(p00, p01);
            pa[kt][1] = packh(p02, p03);
            pa[kt][2] = packh(p10, p11);
            pa[kt][3] = packh(p12, p13);
        }
        #pragma unroll
        for (int kt = 0; kt < 4; kt++) {
            #pragma unroll
            for (int ntp = 0; ntp < 4; ntp++) {
                uint32_t vf[4];
                ldsm4t(vf, vbaseS + (uint32_t)(((k0 + kt * 16 + vrow) * ATS + ntp * 16 + vcol) * 2));
                mma_f16(O[2*ntp],   pa[kt], vf[0], vf[1]);
                mma_f16(O[2*ntp+1], pa[kt], vf[2], vf[3]);
            }
        }
    }
    sr_lo += __shfl_xor_sync(~0u, sr_lo, 1);
    sr_lo += __shfl_xor_sync(~0u, sr_lo, 2);
    sr_hi += __shfl_xor_sync(~0u, sr_hi, 1);
    sr_hi += __shfl_xor_sync(~0u, sr_hi, 2);
    float inv_lo = 1.0f / sr_lo, inv_hi = 1.0f / sr_hi;

    int r_lo = j * 128 + m0 + (lane >> 2);
    int r_hi = r_lo + 8;
    size_t b_lo = ((size_t)b * TT + r_lo) * DD + h * HD;
    size_t b_hi = ((size_t)b * TT + r_hi) * DD + h * HD;
    #pragma unroll
    for (int nt = 0; nt < 8; nt++) {
        int col = nt * 8 + (lane & 3) * 2;
        *(uint32_t*)&Og[b_lo + col] = packh(O[nt][0] * inv_lo, O[nt][1] * inv_lo);
        *(uint32_t*)&Og[b_hi + col] = packh(O[nt][2] * inv_hi, O[nt][3] * inv_hi);
    }
}

// ---------------- global (dilated) attention (mma, single 64-key tile) ----------------
__global__ void __launch_bounds__(128, 1) global_attn_kernel(
    const __half* __restrict__ Qg, const __half* __restrict__ Kg,
    const __half* __restrict__ Vg, const int* __restrict__ pm,
    const float* __restrict__ cosp, const float* __restrict__ sinp,
    __half* __restrict__ Og)
{
    int w = blockIdx.x, h = blockIdx.y, b = blockIdx.z;
    extern __shared__ char smc[];
    __half* Qs = (__half*)smc;                 // 64 x 72
    __half* Ks = Qs + 64 * ATS;
    __half* Vs = Ks + 64 * ATS;
    float* keepneg = (float*)(Vs + 64 * ATS);  // 64
    int tid = threadIdx.x, lane = tid & 31;

    #pragma unroll 4
    for (int it = 0; it < 16; it++) {
        int idx = tid + it * 128;
        int r = idx >> 5, d = (idx & 31) * 2;
        int p = r * 64 + w;
        size_t base = ((size_t)b * TT + p) * DD + h * HD;
        float c0 = cosp[p * 64 + d], c1 = cosp[p * 64 + d + 1];
        float s0 = sinp[p * 64 + d], s1 = sinp[p * 64 + d + 1];
        float q0 = __half2float(Qg[base + d]), q1 = __half2float(Qg[base + d + 1]);
        float qo0 = __half2float(Qg[base + (d ^ 32)]), qo1 = __half2float(Qg[base + (d ^ 32) + 1]);
        float k0 = __half2float(Kg[base + d]), k1 = __half2float(Kg[base + d + 1]);
        float ko0 = __half2float(Kg[base + (d ^ 32)]), ko1 = __half2float(Kg[base + (d ^ 32) + 1]);
        float qr0, qr1, kr0, kr1;
        if (d < 32) {
            qr0 = q0 * c0 - qo0 * s0; qr1 = q1 * c1 - qo1 * s1;
            kr0 = k0 * c0 - ko0 * s0; kr1 = k1 * c1 - ko1 * s1;
        } else {
            qr0 = q0 * c0 + qo0 * s0; qr1 = q1 * c1 + qo1 * s1;
            kr0 = k0 * c0 + ko0 * s0; kr1 = k1 * c1 + ko1 * s1;
        }
        *(uint32_t*)&Qs[r * ATS + d] = packh(qr0, qr1);
        *(uint32_t*)&Ks[r * ATS + d] = packh(kr0, kr1);
        *(uint32_t*)&Vs[r * ATS + d] = *(const uint32_t*)&Vg[base + d];
    }
    if (tid < 64) keepneg[tid] = pm[(size_t)b * TT + tid * 64 + w] ? 0.0f : -1e9f;
    __syncthreads();

    int m0 = (tid >> 5) * 16;
    uint32_t qbase = smem_u32(Qs) + (uint32_t)(((m0 + (lane & 15)) * ATS + ((lane >> 4) << 3)) * 2);
    uint32_t kbaseS = smem_u32(Ks);
    uint32_t vbaseS = smem_u32(Vs);
    uint32_t krow = (lane & 7) + ((lane >> 4) & 1) * 8;
    uint32_t kcol = ((lane >> 3) & 1) * 8;
    uint32_t vrow = (lane & 15);
    uint32_t vcol = (lane >> 4) * 8;

    float S[8][4];
    #pragma unroll
    for (int n = 0; n < 8; n++)
        #pragma unroll
        for (int c = 0; c < 4; c++) S[n][c] = 0.0f;
    #pragma unroll
    for (int kt = 0; kt < 4; kt++) {
        uint32_t aq[4];
        ldsm4(aq, qbase + kt * 32);
        #pragma unroll
        for (int ntp = 0; ntp < 4; ntp++) {
            uint32_t bk[4];
            ldsm4(bk, kbaseS + (uint32_t)(((ntp * 16 + krow) * ATS + kt * 16 + kcol) * 2));
            mma_f16(S[2*ntp],   aq, bk[0], bk[1]);
            mma_f16(S[2*ntp+1], aq, bk[2], bk[3]);
        }
    }
    float cm_lo = -1e30f, cm_hi = -1e30f;
    #pragma unroll
    for (int nt = 0; nt < 8; nt++) {
        int colg = nt * 8 + (lane & 3) * 2;
        float kn0 = keepneg[colg], kn1 = keepneg[colg + 1];
        S[nt][0] = S[nt][0] * 0.125f + kn0;
        S[nt][1] = S[nt][1] * 0.125f + kn1;
        S[nt][2] = S[nt][2] * 0.125f + kn0;
        S[nt][3] = S[nt][3] * 0.125f + kn1;
        cm_lo = fmaxf(cm_lo, fmaxf(S[nt][0], S[nt][1]));
        cm_hi = fmaxf(cm_hi, fmaxf(S[nt][2], S[nt][3]));
    }
    cm_lo = fmaxf(cm_lo, __shfl_xor_sync(~0u, cm_lo, 1));
    cm_lo = fmaxf(cm_lo, __shfl_xor_sync(~0u, cm_lo, 2));
    cm_hi = fmaxf(cm_hi, __shfl_xor_sync(~0u, cm_hi, 1));
    cm_hi = fmaxf(cm_hi, __shfl_xor_sync(~0u, cm_hi, 2));

    float sr_lo = 0.0f, sr_hi = 0.0f;
    uint32_t pa[4][4];
    float O[8][4];
    #pragma unroll
    for (int n = 0; n < 8; n++)
        #pragma unroll
        for (int c = 0; c < 4; c++) O[n][c] = 0.0f;
    #pragma unroll
    for (int kt = 0; kt < 4; kt++) {
        int t0 = 2 * kt, t1 = 2 * kt + 1;
        float p00 = expf(S[t0][0] - cm_lo), p01 = expf(S[t0][1] - cm_lo);
        float p02 = expf(S[t0][2] - cm_hi), p03 = expf(S[t0][3] - cm_hi);
        float p10 = expf(S[t1][0] - cm_lo), p11 = expf(S[t1][1] - cm_lo);
        float p12 = expf(S[t1][2] - cm_hi), p13 = expf(S[t1][3] - cm_hi);
        sr_lo += p00 + p01 + p10 + p11;
        sr_hi += p02 + p03 + p12 + p13;
        pa[kt][0] = packh(p00, p01);
        pa[kt][1] = packh(p02, p03);
        pa[kt][2] = packh(p10, p11);
        pa[kt][3] = packh(p12, p13);
    }
    #pragma unroll
    for (int kt = 0; kt < 4; kt++) {
        #pragma unroll
        for (int ntp = 0; ntp < 4; ntp++) {
            uint32_t vf[4];
            ldsm4t(vf, vbaseS + (uint32_t)(((kt * 16 + vrow) * ATS + ntp * 16 + vcol) * 2));
            mma_f16(O[2*ntp],   pa[kt], vf[0], vf[1]);
            mma_f16(O[2*ntp+1], pa[kt], vf[2], vf[3]);
        }
    }
    sr_lo += __shfl_xor_sync(~0u, sr_lo, 1);
    sr_lo += __shfl_xor_sync(~0u, sr_lo, 2);
    sr_hi += __shfl_xor_sync(~0u, sr_hi, 1);
    sr_hi += __shfl_xor_sync(~0u, sr_hi, 2);
    float inv_lo = 1.0f / sr_lo, inv_hi = 1.0f / sr_hi;

    int p_lo = (m0 + (lane >> 2)) * 64 + w;
    int p_hi = p_lo + 8 * 64;
    size_t b_lo = ((size_t)b * TT + p_lo) * DD + h * HD;
    size_t b_hi = ((size_t)b * TT + p_hi) * DD + h * HD;
    #pragma unroll
    for (int nt = 0; nt < 8; nt++) {
        int col = nt * 8 + (lane & 3) * 2;
        *(uint32_t*)&Og[b_lo + col] = packh(O[nt][0] * inv_lo, O[nt][1] * inv_lo);
        *(uint32_t*)&Og[b_hi + col] = packh(O[nt][2] * inv_hi, O[nt][3] * inv_hi);
    }
}

// ---------------- host ----------------
extern "C" void kernel_launch(void* const* d_in, const int* in_sizes, int n_in,
                              void* d_out, int out_size)
{
    const float* x    = (const float*)d_in[0];
    const int*   pm   = (const int*)d_in[1];
    const float* cosp = (const float*)d_in[2];
    const float* sinp = (const float*)d_in[3];
    const float* ln1_g = (const float*)d_in[4];
    const float* ln1_b = (const float*)d_in[5];
    const float* ln2_g = (const float*)d_in[6];
    const float* ln2_b = (const float*)d_in[7];
    const float* ln3_g = (const float*)d_in[8];
    const float* ln3_b = (const float*)d_in[9];
    const float* lq_w = (const float*)d_in[10];
    const float* lq_b = (const float*)d_in[11];
    const float* lk_w = (const float*)d_in[12];
    const float* lk_b = (const float*)d_in[13];
    const float* lv_w = (const float*)d_in[14];
    const float* lv_b = (const float*)d_in[15];
    const float* lo_w = (const float*)d_in[16];
    const float* lo_b = (const float*)d_in[17];
    const float* gq_w = (const float*)d_in[18];
    const float* gq_b = (const float*)d_in[19];
    const float* gk_w = (const float*)d_in[20];
    const float* gk_b = (const float*)d_in[21];
    const float* gv_w = (const float*)d_in[22];
    const float* gv_b = (const float*)d_in[23];
    const float* go_w = (const float*)d_in[24];
    const float* go_b = (const float*)d_in[25];
    const float* f1_w = (const float*)d_in[26];
    const float* f1_b = (const float*)d_in[27];
    const float* f2_w = (const float*)d_in[28];
    const float* f2_b = (const float*)d_in[29];
    const float* f3_w = (const float*)d_in[30];
    const float* f3_b = (const float*)d_in[31];
    float* out = (float*)d_out;

    float *px, *pbcat;
    __half *pq, *pkp, *pvp, *pxn, *patt, *ph1, *ph2, *pw;
    cudaGetSymbolAddress((void**)&px,    g_x);
    cudaGetSymbolAddress((void**)&pq,    g_q);
    cudaGetSymbolAddress((void**)&pkp,   g_kp);
    cudaGetSymbolAddress((void**)&pvp,   g_vp);
    cudaGetSymbolAddress((void**)&pbcat, g_bcat);
    cudaGetSymbolAddress((void**)&pxn,   g_xn);
    cudaGetSymbolAddress((void**)&patt,  g_att);
    cudaGetSymbolAddress((void**)&ph1,   g_h1);
    cudaGetSymbolAddress((void**)&ph2,   g_h2);
    cudaGetSymbolAddress((void**)&pw,    g_w);

    const int M = BB * TT;
    const int n4 = M * DD / 4;
    const int EW = 256;

    size_t smLoc = (size_t)(2 * 256 * ATS + 128 * ATS) * 2 + 256 * 4;   // ~93.2 KB
    size_t smGlb = (size_t)(3 * 64 * ATS) * 2 + 64 * 4;                 // ~27.9 KB
    cudaFuncSetAttribute(local_attn_kernel,  cudaFuncAttributeMaxDynamicSharedMemorySize, (int)smLoc);
    cudaFuncSetAttribute(global_attn_kernel, cudaFuncAttributeMaxDynamicSharedMemorySize, (int)smGlb);
    cudaFuncSetAttribute(gemm_mma_kernel, cudaFuncAttributeMaxDynamicSharedMemorySize, 65536);

    const int OLQKV=0, OGQKV=786432, OLO=1572864, OGO=1835008,
              OF1=2097152, OF2=2621440, OF3=3670016;

    dim3 gQKV(12, M / 128);
    dim3 g512(4,  M / 128);
    dim3 g1k (8,  M / 128);

    rope_init_kernel<<<64, 256>>>();
    WPtrs wp;
    wp.p[0]=lq_w; wp.p[1]=lk_w; wp.p[2]=lv_w; wp.p[3]=gq_w; wp.p[4]=gk_w;
    wp.p[5]=gv_w; wp.p[6]=lo_w; wp.p[7]=go_w; wp.p[8]=f1_w; wp.p[9]=f2_w; wp.p[10]=f3_w;
    cvt_w_kernel<<<dim3(1024, 11), 256>>>(wp);
    BPtrs bp;
    bp.p[0]=lq_b; bp.p[1]=lk_b; bp.p[2]=lv_b; bp.p[3]=gq_b; bp.p[4]=gk_b; bp.p[5]=gv_b;
    bias_cat_kernel<<<1, 512>>>(bp);

    mask_mul4_kernel<<<(n4 + EW - 1) / EW, EW>>>(x, pm, px, n4);
    ln_kernel<<<M, 128>>>(px, ln1_g, ln1_b, pm, pxn, 1);

    // local QKV fused (q plain fp16, k/v padded fp16)
    gemm_mma_kernel<<<gQKV, 512, 65536>>>(pxn, pw+OLQKV, pbcat,
                                          0, pq, pkp, pvp, 0, 0, DD, DD, 0, 2, 1);
    fill_pad_kernel<<<(BB * 128 * DD + EW - 1) / EW, EW>>>(lk_b, lv_b);

    local_attn_kernel<<<dim3(NLOC, HH, BB), 256, smLoc>>>(pq, pm, patt);

    // O proj + residual + mask (in place on px)
    gemm_mma_kernel<<<g512, 512, 65536>>>(patt, pw+OLO, lo_b,
                                          px, 0, 0, 0, px, pm, DD, DD, 0, 3, 0);

    ln_kernel<<<M, 128>>>(px, ln2_g, ln2_b, pm, pxn, 0);

    // global QKV fused (plain fp16)
    gemm_mma_kernel<<<gQKV, 512, 65536>>>(pxn, pw+OGQKV, pbcat + 1536,
                                          0, pq, pkp, pvp, 0, 0, DD, DD, 0, 2, 0);

    global_attn_kernel<<<dim3(NDIL, HH, BB), 128, smGlb>>>(pq, pkp, pvp, pm, cosp, sinp, patt);

    gemm_mma_kernel<<<g512, 512, 65536>>>(patt, pw+OGO, go_b,
                                          px, 0, 0, 0, px, pm, DD, DD, 0, 3, 0);

    ln_kernel<<<M, 128>>>(px, ln3_g, ln3_b, pm, pxn, 0);
    gemm_mma_kernel<<<g1k,  512, 65536>>>(pxn, pw+OF1, f1_b,
                                          0, ph1, 0, 0, 0, 0, 512,  1024, 1, 1, 0);
    gemm_mma_kernel<<<g1k,  512, 65536>>>(ph1, pw+OF2, f2_b,
                                          0, ph2, 0, 0, 0, 0, 1024, 1024, 1, 1, 0);
    // f3 + residual + mask -> out
    gemm_mma_kernel<<<g512, 512, 65536>>>(ph2, pw+OF3, f3_b,
                                          out, 0, 0, 0, px, pm, 1024, 512, 0, 3, 0);
}

// round 11
// speedup vs baseline: 5.7072x; 1.1032x over previous
#include <cuda_runtime.h>
#include <cuda_bf16.h>
#include <cuda_fp16.h>
#include <math.h>
#include <stdint.h>

#define BB 8
#define TT 4096
#define DD 512
#define HH 8
#define HD 64
#define TP 4224
#define NLOC 32
#define NDIL 64

// ---------------- scratch ----------------
__device__ float g_x  [BB*TT*DD];
__device__ __half g_q  [BB*TT*DD];
__device__ __half g_kp [BB*TP*DD];
__device__ __half g_vp [BB*TP*DD];
__device__ __half g_xn [BB*TT*DD];
__device__ __half g_att[BB*TT*DD];
__device__ __half g_h1 [BB*TT*1024];
__device__ __half g_h2 [BB*TT*1024];
__device__ __half g_w  [4194304];
__device__ float g_bcat[3072];
__device__ float g_lcos[256*64];
__device__ float g_lsin[256*64];

// ---------------- helpers ----------------
__device__ __forceinline__ uint32_t smem_u32(const void* p) {
    uint32_t a;
    asm("{ .reg .u64 t; cvta.to.shared.u64 t, %1; cvt.u32.u64 %0, t; }" : "=r"(a) : "l"(p));
    return a;
}
__device__ __forceinline__ void ldsm4(uint32_t* r, uint32_t addr) {
    asm volatile("ldmatrix.sync.aligned.m8n8.x4.shared.b16 {%0,%1,%2,%3}, [%4];"
        : "=r"(r[0]), "=r"(r[1]), "=r"(r[2]), "=r"(r[3]) : "r"(addr));
}
__device__ __forceinline__ void ldsm4t(uint32_t* r, uint32_t addr) {
    asm volatile("ldmatrix.sync.aligned.m8n8.x4.trans.shared.b16 {%0,%1,%2,%3}, [%4];"
        : "=r"(r[0]), "=r"(r[1]), "=r"(r[2]), "=r"(r[3]) : "r"(addr));
}
__device__ __forceinline__ void mma_f16(float* c, const uint32_t* a, uint32_t b0, uint32_t b1) {
    asm volatile("mma.sync.aligned.m16n8k16.row.col.f32.f16.f16.f32 "
        "{%0,%1,%2,%3}, {%4,%5,%6,%7}, {%8,%9}, {%0,%1,%2,%3};"
        : "+f"(c[0]), "+f"(c[1]), "+f"(c[2]), "+f"(c[3])
        : "r"(a[0]), "r"(a[1]), "r"(a[2]), "r"(a[3]), "r"(b0), "r"(b1));
}
#define SWZ64(x) ((x) ^ (((x) >> 3) & 0x30))
#define CPA(dst, src) asm volatile("cp.async.cg.shared.global [%0], [%1], 16;" :: "r"(dst), "l"(src))
#define CPC() asm volatile("cp.async.commit_group;" ::: "memory")
#define CPW(n) asm volatile("cp.async.wait_group %0;" :: "n"(n) : "memory")

__device__ __forceinline__ uint32_t packh(float a, float b) {
    __half2 h = __floats2half2_rn(a, b);
    return *(uint32_t*)&h;
}
__device__ __forceinline__ uint2 pack4h(float4 v) {
    uint2 r; r.x = packh(v.x, v.y); r.y = packh(v.z, v.w); return r;
}

// ---------------- GEMM (fp16): CTA 128x256, warp tile 32x64, BK=64, 3-stage ----------------
// modes: 1=fp16 out, 2=QKV triple (fp16), 3=fp32+residual+mask
#define GSTG 49152   // stage bytes: 2 subs x (A 8KB + W 16KB)
__global__ void __launch_bounds__(512, 1) gemm_mma_kernel(
    const __half* __restrict__ A, const __half* __restrict__ W,
    const float* __restrict__ bias,
    float* __restrict__ Cf, __half* __restrict__ Ch,
    __half* __restrict__ Ck, __half* __restrict__ Cv,
    const float* __restrict__ R, const int* __restrict__ pm,
    int K, int Nt, int act, int mode, int padKV)
{
    extern __shared__ char sm[];
    uint32_t smb = smem_u32(sm);
    int tid = threadIdx.x, lane = tid & 31, wid = tid >> 5;
    int row0 = blockIdx.y * 128, col0 = blockIdx.x * 256;
    int wm = (wid & 3) * 32, wn = (wid >> 2) * 64;

    float acc[2][8][4];
    #pragma unroll
    for (int i = 0; i < 2; i++)
        #pragma unroll
        for (int j = 0; j < 8; j++)
            #pragma unroll
            for (int c = 0; c < 4; c++) acc[i][j][c] = 0.0f;

    int srow = tid >> 2, sc = tid & 3;
    uint32_t sdA  = SWZ64((uint32_t)(srow * 64 + sc * 16));
    uint32_t sdW0 = sdA;
    uint32_t sdW1 = SWZ64((uint32_t)((128 + srow) * 64 + sc * 16));
    size_t gA  = (size_t)(row0 + srow) * K + sc * 8;
    size_t gW0 = (size_t)(col0 + srow) * K + sc * 8;
    size_t gW1 = (size_t)(col0 + 128 + srow) * K + sc * 8;

    uint32_t aoff[2], boff[4];
    #pragma unroll
    for (int i = 0; i < 2; i++) {
        int r = wm + i * 16 + (lane & 15);
        aoff[i] = r * 64 + ((lane >> 4) << 4);
    }
    #pragma unroll
    for (int j = 0; j < 4; j++) {
        int r = wn + j * 16 + (lane & 7) + ((lane >> 4) & 1) * 8;
        boff[j] = r * 64 + (((lane >> 3) & 1) << 4);
    }

    int nch = K >> 6;
    #define G_ISSUE(ch) { \
        uint32_t st_ = smb + ((ch) % 3) * GSTG; \
        size_t k0_ = (size_t)(ch) * 64; \
        CPA(st_ + sdA,                  A + gA  + k0_); \
        CPA(st_ + 8192 + sdW0,          W + gW0 + k0_); \
        CPA(st_ + 8192 + sdW1,          W + gW1 + k0_); \
        CPA(st_ + 24576 + sdA,          A + gA  + k0_ + 32); \
        CPA(st_ + 24576 + 8192 + sdW0,  W + gW0 + k0_ + 32); \
        CPA(st_ + 24576 + 8192 + sdW1,  W + gW1 + k0_ + 32); \
        CPC(); }

    G_ISSUE(0);
    if (nch > 1) G_ISSUE(1);

    for (int ch = 0; ch < nch; ch++) {
        if (ch + 1 < nch) { CPW(1); } else { CPW(0); }
        __syncthreads();
        if (ch + 2 < nch) G_ISSUE(ch + 2);
        uint32_t st = smb + (ch % 3) * GSTG;
        #pragma unroll
        for (int sub = 0; sub < 2; sub++) {
            uint32_t sA = st + sub * 24576;
            uint32_t sW = sA + 8192;
            #pragma unroll
            for (int ks = 0; ks < 2; ks++) {
                uint32_t ah[2][4], bh[4][4];
                #pragma unroll
                for (int i = 0; i < 2; i++)
                    ldsm4(ah[i], sA + SWZ64(aoff[i] + ks * 32));
                #pragma unroll
                for (int j = 0; j < 4; j++)
                    ldsm4(bh[j], sW + SWZ64(boff[j] + ks * 32));
                #pragma unroll
                for (int i = 0; i < 2; i++)
                    #pragma unroll
                    for (int j = 0; j < 4; j++) {
                        mma_f16(acc[i][2*j],   ah[i], bh[j][0], bh[j][1]);
                        mma_f16(acc[i][2*j+1], ah[i], bh[j][2], bh[j][3]);
                    }
            }
        }
    }

    // epilogue
    int g = lane >> 2, t4 = lane & 3;
    #pragma unroll
    for (int i = 0; i < 2; i++) {
        int r1 = row0 + wm + i * 16 + g;
        int r2 = r1 + 8;
        #pragma unroll
        for (int nj = 0; nj < 8; nj++) {
            int colG = col0 + wn + nj * 8 + t4 * 2;
            float b0 = bias[colG], b1 = bias[colG + 1];
            float v0 = acc[i][nj][0] + b0, v1 = acc[i][nj][1] + b1;
            float v2 = acc[i][nj][2] + b0, v3 = acc[i][nj][3] + b1;
            if (act) {
                v0 = 0.5f * v0 * (1.0f + erff(v0 * 0.70710678118654752f));
                v1 = 0.5f * v1 * (1.0f + erff(v1 * 0.70710678118654752f));
                v2 = 0.5f * v2 * (1.0f + erff(v2 * 0.70710678118654752f));
                v3 = 0.5f * v3 * (1.0f + erff(v3 * 0.70710678118654752f));
            }
            if (mode == 1) {
                *(uint32_t*)(Ch + (size_t)r1 * Nt + colG) = packh(v0, v1);
                *(uint32_t*)(Ch + (size_t)r2 * Nt + colG) = packh(v2, v3);
            } else if (mode == 2) {
                int seg = colG >> 9;
                int colLoc = colG - (seg << 9);
                __half* dst = (seg == 0) ? Ch : (seg == 1 ? Ck : Cv);
                int doPad = (seg != 0) && padKV;
                size_t o1 = doPad ? ((size_t)(r1 >> 12) * TP + 64 + (r1 & 4095)) : (size_t)r1;
                size_t o2 = doPad ? ((size_t)(r2 >> 12) * TP + 64 + (r2 & 4095)) : (size_t)r2;
                *(uint32_t*)(dst + o1 * 512 + colLoc) = packh(v0, v1);
                *(uint32_t*)(dst + o2 * 512 + colLoc) = packh(v2, v3);
            } else {
                float m1 = pm[r1] ? 1.0f : 0.0f;
                float m2 = pm[r2] ? 1.0f : 0.0f;
                const float* rr1 = R + (size_t)r1 * Nt + colG;
                const float* rr2 = R + (size_t)r2 * Nt + colG;
                float2 w1; w1.x = (v0 + rr1[0]) * m1; w1.y = (v1 + rr1[1]) * m1;
                float2 w2; w2.x = (v2 + rr2[0]) * m2; w2.y = (v3 + rr2[1]) * m2;
                *(float2*)(Cf + (size_t)r1 * Nt + colG) = w1;
                *(float2*)(Cf + (size_t)r2 * Nt + colG) = w2;
            }
        }
    }
}

// ---------------- weight convert ----------------
struct WPtrs { const float* p[11]; };
__global__ void cvt_w_kernel(WPtrs wp) {
    const int sizes[11] = {262144,262144,262144,262144,262144,262144,262144,262144,
                           524288,1048576,524288};
    const int offs[11]  = {0,262144,524288, 786432,1048576,1310720,
                           1572864,1835008, 2097152,2621440,3670016};
    int wi = blockIdx.y;
    int i4 = blockIdx.x * blockDim.x + threadIdx.x;
    if (i4 >= (sizes[wi] >> 2)) return;
    float4 v = ((const float4*)wp.p[wi])[i4];
    ((uint2*)(g_w + offs[wi]))[i4] = pack4h(v);
}

struct BPtrs { const float* p[6]; };
__global__ void bias_cat_kernel(BPtrs bp) {
    int t = threadIdx.x;
    for (int i = 0; i < 6; i++)
        g_bcat[i * 512 + t] = bp.p[i][t];
}

// ---------------- local rope tables ----------------
__global__ void rope_init_kernel() {
    int idx = blockIdx.x * blockDim.x + threadIdx.x;
    if (idx >= 256 * 64) return;
    int t = idx >> 6, d = idx & 63;
    double inv = pow(10000.0, -(double)(d & 31) / 32.0);
    double a = (double)t * inv;
    g_lcos[idx] = (float)cos(a);
    g_lsin[idx] = (float)sin(a);
}

// ---------------- elementwise ----------------
__global__ void mask_mul4_kernel(const float* __restrict__ X,
                                 const int* __restrict__ pm,
                                 float* __restrict__ Y, int n4) {
    int i = blockIdx.x * blockDim.x + threadIdx.x;
    if (i >= n4) return;
    float m = pm[i >> 7] ? 1.0f : 0.0f;
    float4 v = ((const float4*)X)[i];
    v.x *= m; v.y *= m; v.z *= m; v.w *= m;
    ((float4*)Y)[i] = v;
}

// ---------------- layernorm -> fp16 ----------------
__global__ void __launch_bounds__(128) ln_kernel(
    const float* __restrict__ X, const float* __restrict__ g,
    const float* __restrict__ b, const int* __restrict__ pm,
    __half* __restrict__ Yh, int maskOut)
{
    int row = blockIdx.x;
    int tid = threadIdx.x;
    const float4* x4 = (const float4*)(X + (size_t)row * DD);
    float4 v = x4[tid];
    float s  = v.x + v.y + v.z + v.w;
    float ss = v.x*v.x + v.y*v.y + v.z*v.z + v.w*v.w;
    #pragma unroll
    for (int o = 16; o; o >>= 1) {
        s  += __shfl_xor_sync(~0u, s,  o);
        ss += __shfl_xor_sync(~0u, ss, o);
    }
    __shared__ float sh[8];
    int w = tid >> 5, lane = tid & 31;
    if (lane == 0) { sh[w] = s; sh[4 + w] = ss; }
    __syncthreads();
    s  = sh[0] + sh[1] + sh[2] + sh[3];
    ss = sh[4] + sh[5] + sh[6] + sh[7];
    float mean = s * (1.0f / 512.0f);
    float var  = ss * (1.0f / 512.0f) - mean * mean;
    float inv  = rsqrtf(var + 1e-5f);
    float m = maskOut ? (pm[row] ? 1.0f : 0.0f) : 1.0f;
    float4 gg = ((const float4*)g)[tid];
    float4 bb = ((const float4*)b)[tid];
    float4 o;
    o.x = ((v.x - mean) * inv * gg.x + bb.x) * m;
    o.y = ((v.y - mean) * inv * gg.y + bb.y) * m;
    o.z = ((v.z - mean) * inv * gg.z + bb.z) * m;
    o.w = ((v.w - mean) * inv * gg.w + bb.w) * m;
    ((uint2*)(Yh + (size_t)row * DD))[tid] = pack4h(o);
}

// ---------------- fill pad rows (fp16) ----------------
__global__ void fill_pad_kernel(const float* __restrict__ kb, const float* __restrict__ vb) {
    int idx = blockIdx.x * blockDim.x + threadIdx.x;
    if (idx >= BB * 128 * DD) return;
    int c  = idx & 511;
    int rr = (idx >> 9) & 127;
    int b  = idx >> 16;
    int prow = (rr < 64) ? rr : (TT + rr);
    size_t o = ((size_t)b * TP + prow) * DD + c;
    g_kp[o] = __float2half(kb[c]);
    g_vp[o] = __float2half(vb[c]);
}

// ---------------- local attention (mma, online softmax over 4 chunks of 64 keys) ----------------
#define ATS 72   // smem row stride in halves (144B)
__global__ void __launch_bounds__(256, 1) local_attn_kernel(
    const __half* __restrict__ Qg, const int* __restrict__ pm,
    __half* __restrict__ Og)
{
    int j = blockIdx.x, h = blockIdx.y, b = blockIdx.z;
    extern __shared__ char smc[];
    __half* Ks = (__half*)smc;                 // 256 x 72
    __half* Vs = Ks + 256 * ATS;               // 256 x 72
    __half* Qs = Vs + 256 * ATS;               // 128 x 72
    float* keepneg = (float*)(Qs + 128 * ATS); // 256
    int tid = threadIdx.x, lane = tid & 31;

    // load K (rope) and V, fp16
    #pragma unroll 4
    for (int it = 0; it < 32; it++) {
        int idx = tid + it * 256;
        int r = idx >> 5, d = (idx & 31) * 2;
        size_t base = ((size_t)b * TP + (size_t)j * 128 + r) * DD + h * HD;
        float c0 = g_lcos[r * 64 + d], c1 = g_lcos[r * 64 + d + 1];
        float s0 = g_lsin[r * 64 + d], s1 = g_lsin[r * 64 + d + 1];
        float k0 = __half2float(g_kp[base + d]);
        float k1 = __half2float(g_kp[base + d + 1]);
        float o0 = __half2float(g_kp[base + (d ^ 32)]);
        float o1 = __half2float(g_kp[base + (d ^ 32) + 1]);
        float r0 = (d < 32) ? (k0 * c0 - o0 * s0) : (k0 * c0 + o0 * s0);
        float r1 = (d < 32) ? (k1 * c1 - o1 * s1) : (k1 * c1 + o1 * s1);
        *(uint32_t*)&Ks[r * ATS + d] = packh(r0, r1);
        *(uint32_t*)&Vs[r * ATS + d] = *(const uint32_t*)&g_vp[base + d];
    }
    // load Q (rope)
    #pragma unroll 4
    for (int it = 0; it < 16; it++) {
        int idx = tid + it * 256;
        int r = idx >> 5, d = (idx & 31) * 2;
        size_t base = ((size_t)b * TT + (size_t)j * 128 + r) * DD + h * HD;
        int ti = 64 + r;
        float c0 = g_lcos[ti * 64 + d], c1 = g_lcos[ti * 64 + d + 1];
        float s0 = g_lsin[ti * 64 + d], s1 = g_lsin[ti * 64 + d + 1];
        float q0 = __half2float(Qg[base + d]);
        float q1 = __half2float(Qg[base + d + 1]);
        float o0 = __half2float(Qg[base + (d ^ 32)]);
        float o1 = __half2float(Qg[base + (d ^ 32) + 1]);
        float r0 = (d < 32) ? (q0 * c0 - o0 * s0) : (q0 * c0 + o0 * s0);
        float r1 = (d < 32) ? (q1 * c1 - o1 * s1) : (q1 * c1 + o1 * s1);
        *(uint32_t*)&Qs[r * ATS + d] = packh(r0, r1);
    }
    if (tid < 256) {
        int orig = j * 128 + tid - 64;
        keepneg[tid] = (orig >= 0 && orig < TT && pm[(size_t)b * TT + orig]) ? 0.0f : -1e9f;
    }
    __syncthreads();
    if (tid == 0) {
        int any = 0;
        for (int i = 0; i < 256; i++) any |= (keepneg[i] == 0.0f);
        if (!any) keepneg[0] = 0.0f;
    }
    __syncthreads();

    int m0 = (tid >> 5) * 16;
    float O[8][4];
    #pragma unroll
    for (int n = 0; n < 8; n++)
        #pragma unroll
        for (int c = 0; c < 4; c++) O[n][c] = 0.0f;
    float mr_lo = -1e30f, mr_hi = -1e30f, sr_lo = 0.0f, sr_hi = 0.0f;

    uint32_t qbase = smem_u32(Qs) + (uint32_t)(((m0 + (lane & 15)) * ATS + ((lane >> 4) << 3)) * 2);
    uint32_t kbaseS = smem_u32(Ks);
    uint32_t vbaseS = smem_u32(Vs);
    uint32_t krow = (lane & 7) + ((lane >> 4) & 1) * 8;
    uint32_t kcol = ((lane >> 3) & 1) * 8;
    uint32_t vrow = (lane & 15);
    uint32_t vcol = (lane >> 4) * 8;

    for (int ck = 0; ck < 4; ck++) {
        int k0 = ck * 64;
        float S[8][4];
        #pragma unroll
        for (int n = 0; n < 8; n++)
            #pragma unroll
            for (int c = 0; c < 4; c++) S[n][c] = 0.0f;
        #pragma unroll
        for (int kt = 0; kt < 4; kt++) {
            uint32_t aq[4];
            ldsm4(aq, qbase + kt * 32);
            #pragma unroll
            for (int ntp = 0; ntp < 4; ntp++) {
                uint32_t bk[4];
                ldsm4(bk, kbaseS + (uint32_t)(((k0 + ntp * 16 + krow) * ATS + kt * 16 + kcol) * 2));
                mma_f16(S[2*ntp],   aq, bk[0], bk[1]);
                mma_f16(S[2*ntp+1], aq, bk[2], bk[3]);
            }
        }
        // scale + mask + chunk max
        float cm_lo = -1e30f, cm_hi = -1e30f;
        #pragma unroll
        for (int nt = 0; nt < 8; nt++) {
            int colg = k0 + nt * 8 + (lane & 3) * 2;
            float kn0 = keepneg[colg], kn1 = keepneg[colg + 1];
            S[nt][0] = S[nt][0] * 0.125f + kn0;
            S[nt][1] = S[nt][1] * 0.125f + kn1;
            S[nt][2] = S[nt][2] * 0.125f + kn0;
            S[nt][3] = S[nt][3] * 0.125f + kn1;
            cm_lo = fmaxf(cm_lo, fmaxf(S[nt][0], S[nt][1]));
            cm_hi = fmaxf(cm_hi, fmaxf(S[nt][2], S[nt][3]));
        }
        cm_lo = fmaxf(cm_lo, __shfl_xor_sync(~0u, cm_lo, 1));
        cm_lo = fmaxf(cm_lo, __shfl_xor_sync(~0u, cm_lo, 2));
        cm_hi = fmaxf(cm_hi, __shfl_xor_sync(~0u, cm_hi, 1));
        cm_hi = fmaxf(cm_hi, __shfl_xor_sync(~0u, cm_hi, 2));
        float mn_lo = fmaxf(mr_lo, cm_lo), mn_hi = fmaxf(mr_hi, cm_hi);
        float al_lo = expf(mr_lo - mn_lo), al_hi = expf(mr_hi - mn_hi);
        mr_lo = mn_lo; mr_hi = mn_hi;
        sr_lo *= al_lo; sr_hi *= al_hi;
        #pragma unroll
        for (int n = 0; n < 8; n++) {
            O[n][0] *= al_lo; O[n][1] *= al_lo;
            O[n][2] *= al_hi; O[n][3] *= al_hi;
        }
        uint32_t pa[4][4];
        #pragma unroll
        for (int kt = 0; kt < 4; kt++) {
            int t0 = 2 * kt, t1 = 2 * kt + 1;
            float p00 = expf(S[t0][0] - mn_lo), p01 = expf(S[t0][1] - mn_lo);
            float p02 = expf(S[t0][2] - mn_hi), p03 = expf(S[t0][3] - mn_hi);
            float p10 = expf(S[t1][0] - mn_lo), p11 = expf(S[t1][1] - mn_lo);
            float p12 = expf(S[t1][2] - mn_hi), p13 = expf(S[t1][3] - mn_hi);
            sr_lo += p00 + p01 + p10 + p11;
            sr_hi += p02 + p03 + p12 + p13;
            pa[kt][0] = packh(p00, p01);
            pa[kt][1] = packh(p02, p03);
            pa[kt][2] = packh(p10, p11);
            pa[kt][3] = packh(p12, p13);
        }
        #pragma unroll
        for (int kt = 0; kt < 4; kt++) {
            #pragma unroll
            for (int ntp = 0; ntp < 4; ntp++) {
                uint32_t vf[4];
                ldsm4t(vf, vbaseS + (uint32_t)(((k0 + kt * 16 + vrow) * ATS + ntp * 16 + vcol) * 2));
                mma_f16(O[2*ntp],   pa[kt], vf[0], vf[1]);
                mma_f16(O[2*ntp+1], pa[kt], vf[2], vf[3]);
            }
        }
    }
    sr_lo += __shfl_xor_sync(~0u, sr_lo, 1);
    sr_lo += __shfl_xor_sync(~0u, sr_lo, 2);
    sr_hi += __shfl_xor_sync(~0u, sr_hi, 1);
    sr_hi += __shfl_xor_sync(~0u, sr_hi, 2);
    float inv_lo = 1.0f / sr_lo, inv_hi = 1.0f / sr_hi;

    int r_lo = j * 128 + m0 + (lane >> 2);
    int r_hi = r_lo + 8;
    size_t b_lo = ((size_t)b * TT + r_lo) * DD + h * HD;
    size_t b_hi = ((size_t)b * TT + r_hi) * DD + h * HD;
    #pragma unroll
    for (int nt = 0; nt < 8; nt++) {
        int col = nt * 8 + (lane & 3) * 2;
        *(uint32_t*)&Og[b_lo + col] = packh(O[nt][0] * inv_lo, O[nt][1] * inv_lo);
        *(uint32_t*)&Og[b_hi + col] = packh(O[nt][2] * inv_hi, O[nt][3] * inv_hi);
    }
}

// ---------------- global (dilated) attention (mma, single 64-key tile) ----------------
__global__ void __launch_bounds__(128, 1) global_attn_kernel(
    const __half* __restrict__ Qg, const __half* __restrict__ Kg,
    const __half* __restrict__ Vg, const int* __restrict__ pm,
    const float* __restrict__ cosp, const float* __restrict__ sinp,
    __half* __restrict__ Og)
{
    int w = blockIdx.x, h = blockIdx.y, b = blockIdx.z;
    extern __shared__ char smc[];
    __half* Qs = (__half*)smc;                 // 64 x 72
    __half* Ks = Qs + 64 * ATS;
    __half* Vs = Ks + 64 * ATS;
    float* keepneg = (float*)(Vs + 64 * ATS);  // 64
    int tid = threadIdx.x, lane = tid & 31;

    #pragma unroll 4
    for (int it = 0; it < 16; it++) {
        int idx = tid + it * 128;
        int r = idx >> 5, d = (idx & 31) * 2;
        int p = r * 64 + w;
        size_t base = ((size_t)b * TT + p) * DD + h * HD;
        float c0 = cosp[p * 64 + d], c1 = cosp[p * 64 + d + 1];
        float s0 = sinp[p * 64 + d], s1 = sinp[p * 64 + d + 1];
        float q0 = __half2float(Qg[base + d]), q1 = __half2float(Qg[base + d + 1]);
        float qo0 = __half2float(Qg[base + (d ^ 32)]), qo1 = __half2float(Qg[base + (d ^ 32) + 1]);
        float k0 = __half2float(Kg[base + d]), k1 = __half2float(Kg[base + d + 1]);
        float ko0 = __half2float(Kg[base + (d ^ 32)]), ko1 = __half2float(Kg[base + (d ^ 32) + 1]);
        float qr0, qr1, kr0, kr1;
        if (d < 32) {
            qr0 = q0 * c0 - qo0 * s0; qr1 = q1 * c1 - qo1 * s1;
            kr0 = k0 * c0 - ko0 * s0; kr1 = k1 * c1 - ko1 * s1;
        } else {
            qr0 = q0 * c0 + qo0 * s0; qr1 = q1 * c1 + qo1 * s1;
            kr0 = k0 * c0 + ko0 * s0; kr1 = k1 * c1 + ko1 * s1;
        }
        *(uint32_t*)&Qs[r * ATS + d] = packh(qr0, qr1);
        *(uint32_t*)&Ks[r * ATS + d] = packh(kr0, kr1);
        *(uint32_t*)&Vs[r * ATS + d] = *(const uint32_t*)&Vg[base + d];
    }
    if (tid < 64) keepneg[tid] = pm[(size_t)b * TT + tid * 64 + w] ? 0.0f : -1e9f;
    __syncthreads();

    int m0 = (tid >> 5) * 16;
    uint32_t qbase = smem_u32(Qs) + (uint32_t)(((m0 + (lane & 15)) * ATS + ((lane >> 4) << 3)) * 2);
    uint32_t kbaseS = smem_u32(Ks);
    uint32_t vbaseS = smem_u32(Vs);
    uint32_t krow = (lane & 7) + ((lane >> 4) & 1) * 8;
    uint32_t kcol = ((lane >> 3) & 1) * 8;
    uint32_t vrow = (lane & 15);
    uint32_t vcol = (lane >> 4) * 8;

    float S[8][4];
    #pragma unroll
    for (int n = 0; n < 8; n++)
        #pragma unroll
        for (int c = 0; c < 4; c++) S[n][c] = 0.0f;
    #pragma unroll
    for (int kt = 0; kt < 4; kt++) {
        uint32_t aq[4];
        ldsm4(aq, qbase + kt * 32);
        #pragma unroll
        for (int ntp = 0; ntp < 4; ntp++) {
            uint32_t bk[4];
            ldsm4(bk, kbaseS + (uint32_t)(((ntp * 16 + krow) * ATS + kt * 16 + kcol) * 2));
            mma_f16(S[2*ntp],   aq, bk[0], bk[1]);
            mma_f16(S[2*ntp+1], aq, bk[2], bk[3]);
        }
    }
    float cm_lo = -1e30f, cm_hi = -1e30f;
    #pragma unroll
    for (int nt = 0; nt < 8; nt++) {
        int colg = nt * 8 + (lane & 3) * 2;
        float kn0 = keepneg[colg], kn1 = keepneg[colg + 1];
        S[nt][0] = S[nt][0] * 0.125f + kn0;
        S[nt][1] = S[nt][1] * 0.125f + kn1;
        S[nt][2] = S[nt][2] * 0.125f + kn0;
        S[nt][3] = S[nt][3] * 0.125f + kn1;
        cm_lo = fmaxf(cm_lo, fmaxf(S[nt][0], S[nt][1]));
        cm_hi = fmaxf(cm_hi, fmaxf(S[nt][2], S[nt][3]));
    }
    cm_lo = fmaxf(cm_lo, __shfl_xor_sync(~0u, cm_lo, 1));
    cm_lo = fmaxf(cm_lo, __shfl_xor_sync(~0u, cm_lo, 2));
    cm_hi = fmaxf(cm_hi, __shfl_xor_sync(~0u, cm_hi, 1));
    cm_hi = fmaxf(cm_hi, __shfl_xor_sync(~0u, cm_hi, 2));

    float sr_lo = 0.0f, sr_hi = 0.0f;
    uint32_t pa[4][4];
    float O[8][4];
    #pragma unroll
    for (int n = 0; n < 8; n++)
        #pragma unroll
        for (int c = 0; c < 4; c++) O[n][c] = 0.0f;
    #pragma unroll
    for (int kt = 0; kt < 4; kt++) {
        int t0 = 2 * kt, t1 = 2 * kt + 1;
        float p00 = expf(S[t0][0] - cm_lo), p01 = expf(S[t0][1] - cm_lo);
        float p02 = expf(S[t0][2] - cm_hi), p03 = expf(S[t0][3] - cm_hi);
        float p10 = expf(S[t1][0] - cm_lo), p11 = expf(S[t1][1] - cm_lo);
        float p12 = expf(S[t1][2] - cm_hi), p13 = expf(S[t1][3] - cm_hi);
        sr_lo += p00 + p01 + p10 + p11;
        sr_hi += p02 + p03 + p12 + p13;
        pa[kt][0] = packh(p00, p01);
        pa[kt][1] = packh(p02, p03);
        pa[kt][2] = packh(p10, p11);
        pa[kt][3] = packh(p12, p13);
    }
    #pragma unroll
    for (int kt = 0; kt < 4; kt++) {
        #pragma unroll
        for (int ntp = 0; ntp < 4; ntp++) {
            uint32_t vf[4];
            ldsm4t(vf, vbaseS + (uint32_t)(((kt * 16 + vrow) * ATS + ntp * 16 + vcol) * 2));
            mma_f16(O[2*ntp],   pa[kt], vf[0], vf[1]);
            mma_f16(O[2*ntp+1], pa[kt], vf[2], vf[3]);
        }
    }
    sr_lo += __shfl_xor_sync(~0u, sr_lo, 1);
    sr_lo += __shfl_xor_sync(~0u, sr_lo, 2);
    sr_hi += __shfl_xor_sync(~0u, sr_hi, 1);
    sr_hi += __shfl_xor_sync(~0u, sr_hi, 2);
    float inv_lo = 1.0f / sr_lo, inv_hi = 1.0f / sr_hi;

    int p_lo = (m0 + (lane >> 2)) * 64 + w;
    int p_hi = p_lo + 8 * 64;
    size_t b_lo = ((size_t)b * TT + p_lo) * DD + h * HD;
    size_t b_hi = ((size_t)b * TT + p_hi) * DD + h * HD;
    #pragma unroll
    for (int nt = 0; nt < 8; nt++) {
        int col = nt * 8 + (lane & 3) * 2;
        *(uint32_t*)&Og[b_lo + col] = packh(O[nt][0] * inv_lo, O[nt][1] * inv_lo);
        *(uint32_t*)&Og[b_hi + col] = packh(O[nt][2] * inv_hi, O[nt][3] * inv_hi);
    }
}

// ---------------- host ----------------
extern "C" void kernel_launch(void* const* d_in, const int* in_sizes, int n_in,
                              void* d_out, int out_size)
{
    const float* x    = (const float*)d_in[0];
    const int*   pm   = (const int*)d_in[1];
    const float* cosp = (const float*)d_in[2];
    const float* sinp = (const float*)d_in[3];
    const float* ln1_g = (const float*)d_in[4];
    const float* ln1_b = (const float*)d_in[5];
    const float* ln2_g = (const float*)d_in[6];
    const float* ln2_b = (const float*)d_in[7];
    const float* ln3_g = (const float*)d_in[8];
    const float* ln3_b = (const float*)d_in[9];
    const float* lq_w = (const float*)d_in[10];
    const float* lq_b = (const float*)d_in[11];
    const float* lk_w = (const float*)d_in[12];
    const float* lk_b = (const float*)d_in[13];
    const float* lv_w = (const float*)d_in[14];
    const float* lv_b = (const float*)d_in[15];
    const float* lo_w = (const float*)d_in[16];
    const float* lo_b = (const float*)d_in[17];
    const float* gq_w = (const float*)d_in[18];
    const float* gq_b = (const float*)d_in[19];
    const float* gk_w = (const float*)d_in[20];
    const float* gk_b = (const float*)d_in[21];
    const float* gv_w = (const float*)d_in[22];
    const float* gv_b = (const float*)d_in[23];
    const float* go_w = (const float*)d_in[24];
    const float* go_b = (const float*)d_in[25];
    const float* f1_w = (const float*)d_in[26];
    const float* f1_b = (const float*)d_in[27];
    const float* f2_w = (const float*)d_in[28];
    const float* f2_b = (const float*)d_in[29];
    const float* f3_w = (const float*)d_in[30];
    const float* f3_b = (const float*)d_in[31];
    float* out = (float*)d_out;

    float *px, *pbcat;
    __half *pq, *pkp, *pvp, *pxn, *patt, *ph1, *ph2, *pw;
    cudaGetSymbolAddress((void**)&px,    g_x);
    cudaGetSymbolAddress((void**)&pq,    g_q);
    cudaGetSymbolAddress((void**)&pkp,   g_kp);
    cudaGetSymbolAddress((void**)&pvp,   g_vp);
    cudaGetSymbolAddress((void**)&pbcat, g_bcat);
    cudaGetSymbolAddress((void**)&pxn,   g_xn);
    cudaGetSymbolAddress((void**)&patt,  g_att);
    cudaGetSymbolAddress((void**)&ph1,   g_h1);
    cudaGetSymbolAddress((void**)&ph2,   g_h2);
    cudaGetSymbolAddress((void**)&pw,    g_w);

    const int M = BB * TT;
    const int n4 = M * DD / 4;
    const int EW = 256;

    size_t smLoc = (size_t)(2 * 256 * ATS + 128 * ATS) * 2 + 256 * 4;   // ~93.2 KB
    size_t smGlb = (size_t)(3 * 64 * ATS) * 2 + 64 * 4;                 // ~27.9 KB
    size_t smGemm = 3 * GSTG;                                           // 144 KB
    cudaFuncSetAttribute(local_attn_kernel,  cudaFuncAttributeMaxDynamicSharedMemorySize, (int)smLoc);
    cudaFuncSetAttribute(global_attn_kernel, cudaFuncAttributeMaxDynamicSharedMemorySize, (int)smGlb);
    cudaFuncSetAttribute(gemm_mma_kernel, cudaFuncAttributeMaxDynamicSharedMemorySize, (int)smGemm);

    const int OLQKV=0, OGQKV=786432, OLO=1572864, OGO=1835008,
              OF1=2097152, OF2=2621440, OF3=3670016;

    dim3 gQKV(6, M / 128);
    dim3 g512(2, M / 128);
    dim3 g1k (4, M / 128);

    rope_init_kernel<<<64, 256>>>();
    WPtrs wp;
    wp.p[0]=lq_w; wp.p[1]=lk_w; wp.p[2]=lv_w; wp.p[3]=gq_w; wp.p[4]=gk_w;
    wp.p[5]=gv_w; wp.p[6]=lo_w; wp.p[7]=go_w; wp.p[8]=f1_w; wp.p[9]=f2_w; wp.p[10]=f3_w;
    cvt_w_kernel<<<dim3(1024, 11), 256>>>(wp);
    BPtrs bp;
    bp.p[0]=lq_b; bp.p[1]=lk_b; bp.p[2]=lv_b; bp.p[3]=gq_b; bp.p[4]=gk_b; bp.p[5]=gv_b;
    bias_cat_kernel<<<1, 512>>>(bp);

    mask_mul4_kernel<<<(n4 + EW - 1) / EW, EW>>>(x, pm, px, n4);
    ln_kernel<<<M, 128>>>(px, ln1_g, ln1_b, pm, pxn, 1);

    // local QKV fused (q plain fp16, k/v padded fp16)
    gemm_mma_kernel<<<gQKV, 512, smGemm>>>(pxn, pw+OLQKV, pbcat,
                                           0, pq, pkp, pvp, 0, 0, DD, DD, 0, 2, 1);
    fill_pad_kernel<<<(BB * 128 * DD + EW - 1) / EW, EW>>>(lk_b, lv_b);

    local_attn_kernel<<<dim3(NLOC, HH, BB), 256, smLoc>>>(pq, pm, patt);

    // O proj + residual + mask (in place on px)
    gemm_mma_kernel<<<g512, 512, smGemm>>>(patt, pw+OLO, lo_b,
                                           px, 0, 0, 0, px, pm, DD, DD, 0, 3, 0);

    ln_kernel<<<M, 128>>>(px, ln2_g, ln2_b, pm, pxn, 0);

    // global QKV fused (plain fp16)
    gemm_mma_kernel<<<gQKV, 512, smGemm>>>(pxn, pw+OGQKV, pbcat + 1536,
                                           0, pq, pkp, pvp, 0, 0, DD, DD, 0, 2, 0);

    global_attn_kernel<<<dim3(NDIL, HH, BB), 128, smGlb>>>(pq, pkp, pvp, pm, cosp, sinp, patt);

    gemm_mma_kernel<<<g512, 512, smGemm>>>(patt, pw+OGO, go_b,
                                           px, 0, 0, 0, px, pm, DD, DD, 0, 3, 0);

    ln_kernel<<<M, 128>>>(px, ln3_g, ln3_b, pm, pxn, 0);
    gemm_mma_kernel<<<g1k,  512, smGemm>>>(pxn, pw+OF1, f1_b,
                                           0, ph1, 0, 0, 0, 0, 512,  1024, 1, 1, 0);
    gemm_mma_kernel<<<g1k,  512, smGemm>>>(ph1, pw+OF2, f2_b,
                                           0, ph2, 0, 0, 0, 0, 1024, 1024, 1, 1, 0);
    // f3 + residual + mask -> out
    gemm_mma_kernel<<<g512, 512, smGemm>>>(ph2, pw+OF3, f3_b,
                                           out, 0, 0, 0, px, pm, 1024, 512, 0, 3, 0);
}

// round 12
// speedup vs baseline: 5.8918x; 1.0323x over previous
#include <cuda_runtime.h>
#include <cuda_bf16.h>
#include <cuda_fp16.h>
#include <math.h>
#include <stdint.h>

#define BB 8
#define TT 4096
#define DD 512
#define HH 8
#define HD 64
#define TP 4224
#define NLOC 32
#define NDIL 64

// ---------------- scratch ----------------
__device__ float g_x  [BB*TT*DD];
__device__ __half g_q  [BB*TT*DD];
__device__ __half g_kp [BB*TP*DD];
__device__ __half g_vp [BB*TP*DD];
__device__ __half g_xn [BB*TT*DD];
__device__ __half g_att[BB*TT*DD];
__device__ __half g_h1 [BB*TT*1024];
__device__ __half g_h2 [BB*TT*1024];
__device__ __half g_w  [4194304];
__device__ float g_bcat[3072];
__device__ float g_lcos[256*64];
__device__ float g_lsin[256*64];

// ---------------- helpers ----------------
__device__ __forceinline__ uint32_t smem_u32(const void* p) {
    uint32_t a;
    asm("{ .reg .u64 t; cvta.to.shared.u64 t, %1; cvt.u32.u64 %0, t; }" : "=r"(a) : "l"(p));
    return a;
}
__device__ __forceinline__ void ldsm4(uint32_t* r, uint32_t addr) {
    asm volatile("ldmatrix.sync.aligned.m8n8.x4.shared.b16 {%0,%1,%2,%3}, [%4];"
        : "=r"(r[0]), "=r"(r[1]), "=r"(r[2]), "=r"(r[3]) : "r"(addr));
}
__device__ __forceinline__ void ldsm4t(uint32_t* r, uint32_t addr) {
    asm volatile("ldmatrix.sync.aligned.m8n8.x4.trans.shared.b16 {%0,%1,%2,%3}, [%4];"
        : "=r"(r[0]), "=r"(r[1]), "=r"(r[2]), "=r"(r[3]) : "r"(addr));
}
__device__ __forceinline__ void mma_f16(float* c, const uint32_t* a, uint32_t b0, uint32_t b1) {
    asm volatile("mma.sync.aligned.m16n8k16.row.col.f32.f16.f16.f32 "
        "{%0,%1,%2,%3}, {%4,%5,%6,%7}, {%8,%9}, {%0,%1,%2,%3};"
        : "+f"(c[0]), "+f"(c[1]), "+f"(c[2]), "+f"(c[3])
        : "r"(a[0]), "r"(a[1]), "r"(a[2]), "r"(a[3]), "r"(b0), "r"(b1));
}
#define SWZ64(x) ((x) ^ (((x) >> 3) & 0x30))
#define CPA(dst, src) asm volatile("cp.async.cg.shared.global [%0], [%1], 16;" :: "r"(dst), "l"(src))
#define CPC() asm volatile("cp.async.commit_group;" ::: "memory")
#define CPW(n) asm volatile("cp.async.wait_group %0;" :: "n"(n) : "memory")

__device__ __forceinline__ uint32_t packh(float a, float b) {
    __half2 h = __floats2half2_rn(a, b);
    return *(uint32_t*)&h;
}
__device__ __forceinline__ uint2 pack4h(float4 v) {
    uint2 r; r.x = packh(v.x, v.y); r.y = packh(v.z, v.w); return r;
}
__device__ __forceinline__ void unpack4h(uint2 u, float* f) {
    __half2 a = *(__half2*)&u.x, b = *(__half2*)&u.y;
    f[0] = __low2float(a); f[1] = __high2float(a);
    f[2] = __low2float(b); f[3] = __high2float(b);
}

// ---------------- GEMM (fp16): CTA 128x256, warp tile 32x64, BK=64, 3-stage ----------------
// modes: 1=fp16 out, 2=QKV triple (fp16), 3=fp32+residual+mask
#define GSTG 49152
__global__ void __launch_bounds__(512, 1) gemm_mma_kernel(
    const __half* __restrict__ A, const __half* __restrict__ W,
    const float* __restrict__ bias,
    float* __restrict__ Cf, __half* __restrict__ Ch,
    __half* __restrict__ Ck, __half* __restrict__ Cv,
    const float* __restrict__ R, const int* __restrict__ pm,
    int K, int Nt, int act, int mode, int padKV)
{
    extern __shared__ char sm[];
    uint32_t smb = smem_u32(sm);
    int tid = threadIdx.x, lane = tid & 31, wid = tid >> 5;
    int row0 = blockIdx.y * 128, col0 = blockIdx.x * 256;
    int wm = (wid & 3) * 32, wn = (wid >> 2) * 64;

    float acc[2][8][4];
    #pragma unroll
    for (int i = 0; i < 2; i++)
        #pragma unroll
        for (int j = 0; j < 8; j++)
            #pragma unroll
            for (int c = 0; c < 4; c++) acc[i][j][c] = 0.0f;

    int srow = tid >> 2, sc = tid & 3;
    uint32_t sdA  = SWZ64((uint32_t)(srow * 64 + sc * 16));
    uint32_t sdW0 = sdA;
    uint32_t sdW1 = SWZ64((uint32_t)((128 + srow) * 64 + sc * 16));
    size_t gA  = (size_t)(row0 + srow) * K + sc * 8;
    size_t gW0 = (size_t)(col0 + srow) * K + sc * 8;
    size_t gW1 = (size_t)(col0 + 128 + srow) * K + sc * 8;

    uint32_t aoff[2], boff[4];
    #pragma unroll
    for (int i = 0; i < 2; i++) {
        int r = wm + i * 16 + (lane & 15);
        aoff[i] = r * 64 + ((lane >> 4) << 4);
    }
    #pragma unroll
    for (int j = 0; j < 4; j++) {
        int r = wn + j * 16 + (lane & 7) + ((lane >> 4) & 1) * 8;
        boff[j] = r * 64 + (((lane >> 3) & 1) << 4);
    }

    int nch = K >> 6;
    #define G_ISSUE(ch) { \
        uint32_t st_ = smb + ((ch) % 3) * GSTG; \
        size_t k0_ = (size_t)(ch) * 64; \
        CPA(st_ + sdA,                  A + gA  + k0_); \
        CPA(st_ + 8192 + sdW0,          W + gW0 + k0_); \
        CPA(st_ + 8192 + sdW1,          W + gW1 + k0_); \
        CPA(st_ + 24576 + sdA,          A + gA  + k0_ + 32); \
        CPA(st_ + 24576 + 8192 + sdW0,  W + gW0 + k0_ + 32); \
        CPA(st_ + 24576 + 8192 + sdW1,  W + gW1 + k0_ + 32); \
        CPC(); }

    G_ISSUE(0);
    if (nch > 1) G_ISSUE(1);

    for (int ch = 0; ch < nch; ch++) {
        if (ch + 1 < nch) { CPW(1); } else { CPW(0); }
        __syncthreads();
        if (ch + 2 < nch) G_ISSUE(ch + 2);
        uint32_t st = smb + (ch % 3) * GSTG;
        #pragma unroll
        for (int sub = 0; sub < 2; sub++) {
            uint32_t sA = st + sub * 24576;
            uint32_t sW = sA + 8192;
            #pragma unroll
            for (int ks = 0; ks < 2; ks++) {
                uint32_t ah[2][4], bh[4][4];
                #pragma unroll
                for (int i = 0; i < 2; i++)
                    ldsm4(ah[i], sA + SWZ64(aoff[i] + ks * 32));
                #pragma unroll
                for (int j = 0; j < 4; j++)
                    ldsm4(bh[j], sW + SWZ64(boff[j] + ks * 32));
                #pragma unroll
                for (int i = 0; i < 2; i++)
                    #pragma unroll
                    for (int j = 0; j < 4; j++) {
                        mma_f16(acc[i][2*j],   ah[i], bh[j][0], bh[j][1]);
                        mma_f16(acc[i][2*j+1], ah[i], bh[j][2], bh[j][3]);
                    }
            }
        }
    }

    // epilogue
    int g = lane >> 2, t4 = lane & 3;
    #pragma unroll
    for (int i = 0; i < 2; i++) {
        int r1 = row0 + wm + i * 16 + g;
        int r2 = r1 + 8;
        #pragma unroll
        for (int nj = 0; nj < 8; nj++) {
            int colG = col0 + wn + nj * 8 + t4 * 2;
            float b0 = bias[colG], b1 = bias[colG + 1];
            float v0 = acc[i][nj][0] + b0, v1 = acc[i][nj][1] + b1;
            float v2 = acc[i][nj][2] + b0, v3 = acc[i][nj][3] + b1;
            if (act) {
                v0 = 0.5f * v0 * (1.0f + erff(v0 * 0.70710678118654752f));
                v1 = 0.5f * v1 * (1.0f + erff(v1 * 0.70710678118654752f));
                v2 = 0.5f * v2 * (1.0f + erff(v2 * 0.70710678118654752f));
                v3 = 0.5f * v3 * (1.0f + erff(v3 * 0.70710678118654752f));
            }
            if (mode == 1) {
                *(uint32_t*)(Ch + (size_t)r1 * Nt + colG) = packh(v0, v1);
                *(uint32_t*)(Ch + (size_t)r2 * Nt + colG) = packh(v2, v3);
            } else if (mode == 2) {
                int seg = colG >> 9;
                int colLoc = colG - (seg << 9);
                __half* dst = (seg == 0) ? Ch : (seg == 1 ? Ck : Cv);
                int doPad = (seg != 0) && padKV;
                size_t o1 = doPad ? ((size_t)(r1 >> 12) * TP + 64 + (r1 & 4095)) : (size_t)r1;
                size_t o2 = doPad ? ((size_t)(r2 >> 12) * TP + 64 + (r2 & 4095)) : (size_t)r2;
                *(uint32_t*)(dst + o1 * 512 + colLoc) = packh(v0, v1);
                *(uint32_t*)(dst + o2 * 512 + colLoc) = packh(v2, v3);
            } else {
                float m1 = pm[r1] ? 1.0f : 0.0f;
                float m2 = pm[r2] ? 1.0f : 0.0f;
                const float* rr1 = R + (size_t)r1 * Nt + colG;
                const float* rr2 = R + (size_t)r2 * Nt + colG;
                float2 w1; w1.x = (v0 + rr1[0]) * m1; w1.y = (v1 + rr1[1]) * m1;
                float2 w2; w2.x = (v2 + rr2[0]) * m2; w2.y = (v3 + rr2[1]) * m2;
                *(float2*)(Cf + (size_t)r1 * Nt + colG) = w1;
                *(float2*)(Cf + (size_t)r2 * Nt + colG) = w2;
            }
        }
    }
}

// ---------------- weight convert ----------------
struct WPtrs { const float* p[11]; };
__global__ void cvt_w_kernel(WPtrs wp) {
    const int sizes[11] = {262144,262144,262144,262144,262144,262144,262144,262144,
                           524288,1048576,524288};
    const int offs[11]  = {0,262144,524288, 786432,1048576,1310720,
                           1572864,1835008, 2097152,2621440,3670016};
    int wi = blockIdx.y;
    int i4 = blockIdx.x * blockDim.x + threadIdx.x;
    if (i4 >= (sizes[wi] >> 2)) return;
    float4 v = ((const float4*)wp.p[wi])[i4];
    ((uint2*)(g_w + offs[wi]))[i4] = pack4h(v);
}

struct BPtrs { const float* p[6]; };
__global__ void bias_cat_kernel(BPtrs bp) {
    int t = threadIdx.x;
    for (int i = 0; i < 6; i++)
        g_bcat[i * 512 + t] = bp.p[i][t];
}

// ---------------- local rope tables ----------------
__global__ void rope_init_kernel() {
    int idx = blockIdx.x * blockDim.x + threadIdx.x;
    if (idx >= 256 * 64) return;
    int t = idx >> 6, d = idx & 63;
    double inv = pow(10000.0, -(double)(d & 31) / 32.0);
    double a = (double)t * inv;
    g_lcos[idx] = (float)cos(a);
    g_lsin[idx] = (float)sin(a);
}

// ---------------- layernorm -> fp16 (optional fused input mask + residual copy) ----------------
__global__ void __launch_bounds__(128) ln_kernel(
    const float* __restrict__ X, const float* __restrict__ g,
    const float* __restrict__ b, const int* __restrict__ pm,
    __half* __restrict__ Yh, float* __restrict__ Xout,
    int maskIn, int maskOut)
{
    int row = blockIdx.x;
    int tid = threadIdx.x;
    float4 v = ((const float4*)(X + (size_t)row * DD))[tid];
    float mrow = pm[row] ? 1.0f : 0.0f;
    if (maskIn) {
        v.x *= mrow; v.y *= mrow; v.z *= mrow; v.w *= mrow;
        ((float4*)(Xout + (size_t)row * DD))[tid] = v;
    }
    float s  = v.x + v.y + v.z + v.w;
    float ss = v.x*v.x + v.y*v.y + v.z*v.z + v.w*v.w;
    #pragma unroll
    for (int o = 16; o; o >>= 1) {
        s  += __shfl_xor_sync(~0u, s,  o);
        ss += __shfl_xor_sync(~0u, ss, o);
    }
    __shared__ float sh[8];
    int w = tid >> 5, lane = tid & 31;
    if (lane == 0) { sh[w] = s; sh[4 + w] = ss; }
    __syncthreads();
    s  = sh[0] + sh[1] + sh[2] + sh[3];
    ss = sh[4] + sh[5] + sh[6] + sh[7];
    float mean = s * (1.0f / 512.0f);
    float var  = ss * (1.0f / 512.0f) - mean * mean;
    float inv  = rsqrtf(var + 1e-5f);
    float m = maskOut ? mrow : 1.0f;
    float4 gg = ((const float4*)g)[tid];
    float4 bb = ((const float4*)b)[tid];
    float4 o;
    o.x = ((v.x - mean) * inv * gg.x + bb.x) * m;
    o.y = ((v.y - mean) * inv * gg.y + bb.y) * m;
    o.z = ((v.z - mean) * inv * gg.z + bb.z) * m;
    o.w = ((v.w - mean) * inv * gg.w + bb.w) * m;
    ((uint2*)(Yh + (size_t)row * DD))[tid] = pack4h(o);
}

// ---------------- fill pad rows (fp16) ----------------
__global__ void fill_pad_kernel(const float* __restrict__ kb, const float* __restrict__ vb) {
    int idx = blockIdx.x * blockDim.x + threadIdx.x;
    if (idx >= BB * 128 * DD) return;
    int c  = idx & 511;
    int rr = (idx >> 9) & 127;
    int b  = idx >> 16;
    int prow = (rr < 64) ? rr : (TT + rr);
    size_t o = ((size_t)b * TP + prow) * DD + c;
    g_kp[o] = __float2half(kb[c]);
    g_vp[o] = __float2half(vb[c]);
}

// ---------------- local attention (mma, online softmax over 4 chunks of 64 keys) ----------------
#define ATS 72
__global__ void __launch_bounds__(256, 1) local_attn_kernel(
    const __half* __restrict__ Qg, const int* __restrict__ pm,
    __half* __restrict__ Og)
{
    int j = blockIdx.x, h = blockIdx.y, b = blockIdx.z;
    extern __shared__ char smc[];
    __half* Ks = (__half*)smc;                 // 256 x 72
    __half* Vs = Ks + 256 * ATS;               // 256 x 72
    __half* Qs = Vs + 256 * ATS;               // 128 x 72
    float* keepneg = (float*)(Qs + 128 * ATS); // 256
    int tid = threadIdx.x, lane = tid & 31;

    // load K (rope, vectorized 4-half) and V
    #pragma unroll 2
    for (int it = 0; it < 16; it++) {
        int idx = tid + it * 256;              // 4096 quads
        int r = idx >> 4, d = (idx & 15) * 4;
        size_t base = ((size_t)b * TP + (size_t)j * 128 + r) * DD + h * HD;
        float4 cs = *(const float4*)&g_lcos[r * 64 + d];
        float4 sn = *(const float4*)&g_lsin[r * 64 + d];
        float kv[4], ko[4];
        unpack4h(*(const uint2*)&g_kp[base + d], kv);
        unpack4h(*(const uint2*)&g_kp[base + (d ^ 32)], ko);
        float sg = (d < 32) ? -1.0f : 1.0f;
        float4 ro;
        ro.x = kv[0] * cs.x + sg * ko[0] * sn.x;
        ro.y = kv[1] * cs.y + sg * ko[1] * sn.y;
        ro.z = kv[2] * cs.z + sg * ko[2] * sn.z;
        ro.w = kv[3] * cs.w + sg * ko[3] * sn.w;
        *(uint2*)&Ks[r * ATS + d] = pack4h(ro);
        *(uint2*)&Vs[r * ATS + d] = *(const uint2*)&g_vp[base + d];
    }
    // load Q (rope, vectorized)
    #pragma unroll 2
    for (int it = 0; it < 8; it++) {
        int idx = tid + it * 256;              // 2048 quads
        int r = idx >> 4, d = (idx & 15) * 4;
        size_t base = ((size_t)b * TT + (size_t)j * 128 + r) * DD + h * HD;
        int ti = 64 + r;
        float4 cs = *(const float4*)&g_lcos[ti * 64 + d];
        float4 sn = *(const float4*)&g_lsin[ti * 64 + d];
        float qv[4], qo[4];
        unpack4h(*(const uint2*)&Qg[base + d], qv);
        unpack4h(*(const uint2*)&Qg[base + (d ^ 32)], qo);
        float sg = (d < 32) ? -1.0f : 1.0f;
        float4 ro;
        ro.x = qv[0] * cs.x + sg * qo[0] * sn.x;
        ro.y = qv[1] * cs.y + sg * qo[1] * sn.y;
        ro.z = qv[2] * cs.z + sg * qo[2] * sn.z;
        ro.w = qv[3] * cs.w + sg * qo[3] * sn.w;
        *(uint2*)&Qs[r * ATS + d] = pack4h(ro);
    }
    if (tid < 256) {
        int orig = j * 128 + tid - 64;
        keepneg[tid] = (orig >= 0 && orig < TT && pm[(size_t)b * TT + orig]) ? 0.0f : -1e9f;
    }
    __syncthreads();
    if (tid == 0) {
        int any = 0;
        for (int i = 0; i < 256; i++) any |= (keepneg[i] == 0.0f);
        if (!any) keepneg[0] = 0.0f;
    }
    __syncthreads();

    int m0 = (tid >> 5) * 16;
    float O[8][4];
    #pragma unroll
    for (int n = 0; n < 8; n++)
        #pragma unroll
        for (int c = 0; c < 4; c++) O[n][c] = 0.0f;
    float mr_lo = -1e30f, mr_hi = -1e30f, sr_lo = 0.0f, sr_hi = 0.0f;

    uint32_t qbase = smem_u32(Qs) + (uint32_t)(((m0 + (lane & 15)) * ATS + ((lane >> 4) << 3)) * 2);
    uint32_t kbaseS = smem_u32(Ks);
    uint32_t vbaseS = smem_u32(Vs);
    uint32_t krow = (lane & 7) + ((lane >> 4) & 1) * 8;
    uint32_t kcol = ((lane >> 3) & 1) * 8;
    uint32_t vrow = (lane & 15);
    uint32_t vcol = (lane >> 4) * 8;

    for (int ck = 0; ck < 4; ck++) {
        int k0 = ck * 64;
        float S[8][4];
        #pragma unroll
        for (int n = 0; n < 8; n++)
            #pragma unroll
            for (int c = 0; c < 4; c++) S[n][c] = 0.0f;
        #pragma unroll
        for (int kt = 0; kt < 4; kt++) {
            uint32_t aq[4];
            ldsm4(aq, qbase + kt * 32);
            #pragma unroll
            for (int ntp = 0; ntp < 4; ntp++) {
                uint32_t bk[4];
                ldsm4(bk, kbaseS + (uint32_t)(((k0 + ntp * 16 + krow) * ATS + kt * 16 + kcol) * 2));
                mma_f16(S[2*ntp],   aq, bk[0], bk[1]);
                mma_f16(S[2*ntp+1], aq, bk[2], bk[3]);
            }
        }
        float cm_lo = -1e30f, cm_hi = -1e30f;
        #pragma unroll
        for (int nt = 0; nt < 8; nt++) {
            int colg = k0 + nt * 8 + (lane & 3) * 2;
            float kn0 = keepneg[colg], kn1 = keepneg[colg + 1];
            S[nt][0] = S[nt][0] * 0.125f + kn0;
            S[nt][1] = S[nt][1] * 0.125f + kn1;
            S[nt][2] = S[nt][2] * 0.125f + kn0;
            S[nt][3] = S[nt][3] * 0.125f + kn1;
            cm_lo = fmaxf(cm_lo, fmaxf(S[nt][0], S[nt][1]));
            cm_hi = fmaxf(cm_hi, fmaxf(S[nt][2], S[nt][3]));
        }
        cm_lo = fmaxf(cm_lo, __shfl_xor_sync(~0u, cm_lo, 1));
        cm_lo = fmaxf(cm_lo, __shfl_xor_sync(~0u, cm_lo, 2));
        cm_hi = fmaxf(cm_hi, __shfl_xor_sync(~0u, cm_hi, 1));
        cm_hi = fmaxf(cm_hi, __shfl_xor_sync(~0u, cm_hi, 2));
        float mn_lo = fmaxf(mr_lo, cm_lo), mn_hi = fmaxf(mr_hi, cm_hi);
        float al_lo = expf(mr_lo - mn_lo), al_hi = expf(mr_hi - mn_hi);
        mr_lo = mn_lo; mr_hi = mn_hi;
        sr_lo *= al_lo; sr_hi *= al_hi;
        #pragma unroll
        for (int n = 0; n < 8; n++) {
            O[n][0] *= al_lo; O[n][1] *= al_lo;
            O[n][2] *= al_hi; O[n][3] *= al_hi;
        }
        uint32_t pa[4][4];
        #pragma unroll
        for (int kt = 0; kt < 4; kt++) {
            int t0 = 2 * kt, t1 = 2 * kt + 1;
            float p00 = expf(S[t0][0] - mn_lo), p01 = expf(S[t0][1] - mn_lo);
            float p02 = expf(S[t0][2] - mn_hi), p03 = expf(S[t0][3] - mn_hi);
            float p10 = expf(S[t1][0] - mn_lo), p11 = expf(S[t1][1] - mn_lo);
            float p12 = expf(S[t1][2] - mn_hi), p13 = expf(S[t1][3] - mn_hi);
            sr_lo += p00 + p01 + p10 + p11;
            sr_hi += p02 + p03 + p12 + p13;
            pa[kt][0] = packh(p00, p01);
            pa[kt][1] = packh(p02, p03);
            pa[kt][2] = packh(p10, p11);
            pa[kt][3] = packh(p12, p13);
        }
        #pragma unroll
        for (int kt = 0; kt < 4; kt++) {
            #pragma unroll
            for (int ntp = 0; ntp < 4; ntp++) {
                uint32_t vf[4];
                ldsm4t(vf, vbaseS + (uint32_t)(((k0 + kt * 16 + vrow) * ATS + ntp * 16 + vcol) * 2));
                mma_f16(O[2*ntp],   pa[kt], vf[0], vf[1]);
                mma_f16(O[2*ntp+1], pa[kt], vf[2], vf[3]);
            }
        }
    }
    sr_lo += __shfl_xor_sync(~0u, sr_lo, 1);
    sr_lo += __shfl_xor_sync(~0u, sr_lo, 2);
    sr_hi += __shfl_xor_sync(~0u, sr_hi, 1);
    sr_hi += __shfl_xor_sync(~0u, sr_hi, 2);
    float inv_lo = 1.0f / sr_lo, inv_hi = 1.0f / sr_hi;

    int r_lo = j * 128 + m0 + (lane >> 2);
    int r_hi = r_lo + 8;
    size_t b_lo = ((size_t)b * TT + r_lo) * DD + h * HD;
    size_t b_hi = ((size_t)b * TT + r_hi) * DD + h * HD;
    #pragma unroll
    for (int nt = 0; nt < 8; nt++) {
        int col = nt * 8 + (lane & 3) * 2;
        *(uint32_t*)&Og[b_lo + col] = packh(O[nt][0] * inv_lo, O[nt][1] * inv_lo);
        *(uint32_t*)&Og[b_hi + col] = packh(O[nt][2] * inv_hi, O[nt][3] * inv_hi);
    }
}

// ---------------- global (dilated) attention (mma, single 64-key tile) ----------------
__global__ void __launch_bounds__(128, 1) global_attn_kernel(
    const __half* __restrict__ Qg, const __half* __restrict__ Kg,
    const __half* __restrict__ Vg, const int* __restrict__ pm,
    const float* __restrict__ cosp, const float* __restrict__ sinp,
    __half* __restrict__ Og)
{
    int w = blockIdx.x, h = blockIdx.y, b = blockIdx.z;
    extern __shared__ char smc[];
    __half* Qs = (__half*)smc;                 // 64 x 72
    __half* Ks = Qs + 64 * ATS;
    __half* Vs = Ks + 64 * ATS;
    float* keepneg = (float*)(Vs + 64 * ATS);  // 64
    int tid = threadIdx.x, lane = tid & 31;

    #pragma unroll 2
    for (int it = 0; it < 8; it++) {
        int idx = tid + it * 128;              // 1024 quads
        int r = idx >> 4, d = (idx & 15) * 4;
        int p = r * 64 + w;
        size_t base = ((size_t)b * TT + p) * DD + h * HD;
        float4 cs = *(const float4*)&cosp[p * 64 + d];
        float4 sn = *(const float4*)&sinp[p * 64 + d];
        float qv[4], qo[4], kv[4], ko[4];
        unpack4h(*(const uint2*)&Qg[base + d], qv);
        unpack4h(*(const uint2*)&Qg[base + (d ^ 32)], qo);
        unpack4h(*(const uint2*)&Kg[base + d], kv);
        unpack4h(*(const uint2*)&Kg[base + (d ^ 32)], ko);
        float sg = (d < 32) ? -1.0f : 1.0f;
        float4 qr, kr;
        qr.x = qv[0] * cs.x + sg * qo[0] * sn.x;
        qr.y = qv[1] * cs.y + sg * qo[1] * sn.y;
        qr.z = qv[2] * cs.z + sg * qo[2] * sn.z;
        qr.w = qv[3] * cs.w + sg * qo[3] * sn.w;
        kr.x = kv[0] * cs.x + sg * ko[0] * sn.x;
        kr.y = kv[1] * cs.y + sg * ko[1] * sn.y;
        kr.z = kv[2] * cs.z + sg * ko[2] * sn.z;
        kr.w = kv[3] * cs.w + sg * ko[3] * sn.w;
        *(uint2*)&Qs[r * ATS + d] = pack4h(qr);
        *(uint2*)&Ks[r * ATS + d] = pack4h(kr);
        *(uint2*)&Vs[r * ATS + d] = *(const uint2*)&Vg[base + d];
    }
    if (tid < 64) keepneg[tid] = pm[(size_t)b * TT + tid * 64 + w] ? 0.0f : -1e9f;
    __syncthreads();

    int m0 = (tid >> 5) * 16;
    uint32_t qbase = smem_u32(Qs) + (uint32_t)(((m0 + (lane & 15)) * ATS + ((lane >> 4) << 3)) * 2);
    uint32_t kbaseS = smem_u32(Ks);
    uint32_t vbaseS = smem_u32(Vs);
    uint32_t krow = (lane & 7) + ((lane >> 4) & 1) * 8;
    uint32_t kcol = ((lane >> 3) & 1) * 8;
    uint32_t vrow = (lane & 15);
    uint32_t vcol = (lane >> 4) * 8;

    float S[8][4];
    #pragma unroll
    for (int n = 0; n < 8; n++)
        #pragma unroll
        for (int c = 0; c < 4; c++) S[n][c] = 0.0f;
    #pragma unroll
    for (int kt = 0; kt < 4; kt++) {
        uint32_t aq[4];
        ldsm4(aq, qbase + kt * 32);
        #pragma unroll
        for (int ntp = 0; ntp < 4; ntp++) {
            uint32_t bk[4];
            ldsm4(bk, kbaseS + (uint32_t)(((ntp * 16 + krow) * ATS + kt * 16 + kcol) * 2));
            mma_f16(S[2*ntp],   aq, bk[0], bk[1]);
            mma_f16(S[2*ntp+1], aq, bk[2], bk[3]);
        }
    }
    float cm_lo = -1e30f, cm_hi = -1e30f;
    #pragma unroll
    for (int nt = 0; nt < 8; nt++) {
        int colg = nt * 8 + (lane & 3) * 2;
        float kn0 = keepneg[colg], kn1 = keepneg[colg + 1];
        S[nt][0] = S[nt][0] * 0.125f + kn0;
        S[nt][1] = S[nt][1] * 0.125f + kn1;
        S[nt][2] = S[nt][2] * 0.125f + kn0;
        S[nt][3] = S[nt][3] * 0.125f + kn1;
        cm_lo = fmaxf(cm_lo, fmaxf(S[nt][0], S[nt][1]));
        cm_hi = fmaxf(cm_hi, fmaxf(S[nt][2], S[nt][3]));
    }
    cm_lo = fmaxf(cm_lo, __shfl_xor_sync(~0u, cm_lo, 1));
    cm_lo = fmaxf(cm_lo, __shfl_xor_sync(~0u, cm_lo, 2));
    cm_hi = fmaxf(cm_hi, __shfl_xor_sync(~0u, cm_hi, 1));
    cm_hi = fmaxf(cm_hi, __shfl_xor_sync(~0u, cm_hi, 2));

    float sr_lo = 0.0f, sr_hi = 0.0f;
    uint32_t pa[4][4];
    float O[8][4];
    #pragma unroll
    for (int n = 0; n < 8; n++)
        #pragma unroll
        for (int c = 0; c < 4; c++) O[n][c] = 0.0f;
    #pragma unroll
    for (int kt = 0; kt < 4; kt++) {
        int t0 = 2 * kt, t1 = 2 * kt + 1;
        float p00 = expf(S[t0][0] - cm_lo), p01 = expf(S[t0][1] - cm_lo);
        float p02 = expf(S[t0][2] - cm_hi), p03 = expf(S[t0][3] - cm_hi);
        float p10 = expf(S[t1][0] - cm_lo), p11 = expf(S[t1][1] - cm_lo);
        float p12 = expf(S[t1][2] - cm_hi), p13 = expf(S[t1][3] - cm_hi);
        sr_lo += p00 + p01 + p10 + p11;
        sr_hi += p02 + p03 + p12 + p13;
        pa[kt][0] = packh(p00, p01);
        pa[kt][1] = packh(p02, p03);
        pa[kt][2] = packh(p10, p11);
        pa[kt][3] = packh(p12, p13);
    }
    #pragma unroll
    for (int kt = 0; kt < 4; kt++) {
        #pragma unroll
        for (int ntp = 0; ntp < 4; ntp++) {
            uint32_t vf[4];
            ldsm4t(vf, vbaseS + (uint32_t)(((kt * 16 + vrow) * ATS + ntp * 16 + vcol) * 2));
            mma_f16(O[2*ntp],   pa[kt], vf[0], vf[1]);
            mma_f16(O[2*ntp+1], pa[kt], vf[2], vf[3]);
        }
    }
    sr_lo += __shfl_xor_sync(~0u, sr_lo, 1);
    sr_lo += __shfl_xor_sync(~0u, sr_lo, 2);
    sr_hi += __shfl_xor_sync(~0u, sr_hi, 1);
    sr_hi += __shfl_xor_sync(~0u, sr_hi, 2);
    float inv_lo = 1.0f / sr_lo, inv_hi = 1.0f / sr_hi;

    int p_lo = (m0 + (lane >> 2)) * 64 + w;
    int p_hi = p_lo + 8 * 64;
    size_t b_lo = ((size_t)b * TT + p_lo) * DD + h * HD;
    size_t b_hi = ((size_t)b * TT + p_hi) * DD + h * HD;
    #pragma unroll
    for (int nt = 0; nt < 8; nt++) {
        int col = nt * 8 + (lane & 3) * 2;
        *(uint32_t*)&Og[b_lo + col] = packh(O[nt][0] * inv_lo, O[nt][1] * inv_lo);
        *(uint32_t*)&Og[b_hi + col] = packh(O[nt][2] * inv_hi, O[nt][3] * inv_hi);
    }
}

// ---------------- host ----------------
extern "C" void kernel_launch(void* const* d_in, const int* in_sizes, int n_in,
                              void* d_out, int out_size)
{
    const float* x    = (const float*)d_in[0];
    const int*   pm   = (const int*)d_in[1];
    const float* cosp = (const float*)d_in[2];
    const float* sinp = (const float*)d_in[3];
    const float* ln1_g = (const float*)d_in[4];
    const float* ln1_b = (const float*)d_in[5];
    const float* ln2_g = (const float*)d_in[6];
    const float* ln2_b = (const float*)d_in[7];
    const float* ln3_g = (const float*)d_in[8];
    const float* ln3_b = (const float*)d_in[9];
    const float* lq_w = (const float*)d_in[10];
    const float* lq_b = (const float*)d_in[11];
    const float* lk_w = (const float*)d_in[12];
    const float* lk_b = (const float*)d_in[13];
    const float* lv_w = (const float*)d_in[14];
    const float* lv_b = (const float*)d_in[15];
    const float* lo_w = (const float*)d_in[16];
    const float* lo_b = (const float*)d_in[17];
    const float* gq_w = (const float*)d_in[18];
    const float* gq_b = (const float*)d_in[19];
    const float* gk_w = (const float*)d_in[20];
    const float* gk_b = (const float*)d_in[21];
    const float* gv_w = (const float*)d_in[22];
    const float* gv_b = (const float*)d_in[23];
    const float* go_w = (const float*)d_in[24];
    const float* go_b = (const float*)d_in[25];
    const float* f1_w = (const float*)d_in[26];
    const float* f1_b = (const float*)d_in[27];
    const float* f2_w = (const float*)d_in[28];
    const float* f2_b = (const float*)d_in[29];
    const float* f3_w = (const float*)d_in[30];
    const float* f3_b = (const float*)d_in[31];
    float* out = (float*)d_out;

    float *px, *pbcat;
    __half *pq, *pkp, *pvp, *pxn, *patt, *ph1, *ph2, *pw;
    cudaGetSymbolAddress((void**)&px,    g_x);
    cudaGetSymbolAddress((void**)&pq,    g_q);
    cudaGetSymbolAddress((void**)&pkp,   g_kp);
    cudaGetSymbolAddress((void**)&pvp,   g_vp);
    cudaGetSymbolAddress((void**)&pbcat, g_bcat);
    cudaGetSymbolAddress((void**)&pxn,   g_xn);
    cudaGetSymbolAddress((void**)&patt,  g_att);
    cudaGetSymbolAddress((void**)&ph1,   g_h1);
    cudaGetSymbolAddress((void**)&ph2,   g_h2);
    cudaGetSymbolAddress((void**)&pw,    g_w);

    const int M = BB * TT;
    const int EW = 256;

    size_t smLoc = (size_t)(2 * 256 * ATS + 128 * ATS) * 2 + 256 * 4;
    size_t smGlb = (size_t)(3 * 64 * ATS) * 2 + 64 * 4;
    size_t smGemm = 3 * GSTG;
    cudaFuncSetAttribute(local_attn_kernel,  cudaFuncAttributeMaxDynamicSharedMemorySize, (int)smLoc);
    cudaFuncSetAttribute(global_attn_kernel, cudaFuncAttributeMaxDynamicSharedMemorySize, (int)smGlb);
    cudaFuncSetAttribute(gemm_mma_kernel, cudaFuncAttributeMaxDynamicSharedMemorySize, (int)smGemm);

    const int OLQKV=0, OGQKV=786432, OLO=1572864, OGO=1835008,
              OF1=2097152, OF2=2621440, OF3=3670016;

    dim3 gQKV(6, M / 128);
    dim3 g512(2, M / 128);
    dim3 g1k (4, M / 128);

    rope_init_kernel<<<64, 256>>>();
    WPtrs wp;
    wp.p[0]=lq_w; wp.p[1]=lk_w; wp.p[2]=lv_w; wp.p[3]=gq_w; wp.p[4]=gk_w;
    wp.p[5]=gv_w; wp.p[6]=lo_w; wp.p[7]=go_w; wp.p[8]=f1_w; wp.p[9]=f2_w; wp.p[10]=f3_w;
    cvt_w_kernel<<<dim3(1024, 11), 256>>>(wp);
    BPtrs bp;
    bp.p[0]=lq_b; bp.p[1]=lk_b; bp.p[2]=lv_b; bp.p[3]=gq_b; bp.p[4]=gk_b; bp.p[5]=gv_b;
    bias_cat_kernel<<<1, 512>>>(bp);

    // fused: px = x*mask; xn = LN(px)*mask
    ln_kernel<<<M, 128>>>(x, ln1_g, ln1_b, pm, pxn, px, 1, 1);

    // local QKV fused (q plain fp16, k/v padded fp16)
    gemm_mma_kernel<<<gQKV, 512, smGemm>>>(pxn, pw+OLQKV, pbcat,
                                           0, pq, pkp, pvp, 0, 0, DD, DD, 0, 2, 1);
    fill_pad_kernel<<<(BB * 128 * DD + EW - 1) / EW, EW>>>(lk_b, lv_b);

    local_attn_kernel<<<dim3(NLOC, HH, BB), 256, smLoc>>>(pq, pm, patt);

    // O proj + residual + mask (in place on px)
    gemm_mma_kernel<<<g512, 512, smGemm>>>(patt, pw+OLO, lo_b,
                                           px, 0, 0, 0, px, pm, DD, DD, 0, 3, 0);

    ln_kernel<<<M, 128>>>(px, ln2_g, ln2_b, pm, pxn, 0, 0, 0);

    // global QKV fused (plain fp16)
    gemm_mma_kernel<<<gQKV, 512, smGemm>>>(pxn, pw+OGQKV, pbcat + 1536,
                                           0, pq, pkp, pvp, 0, 0, DD, DD, 0, 2, 0);

    global_attn_kernel<<<dim3(NDIL, HH, BB), 128, smGlb>>>(pq, pkp, pvp, pm, cosp, sinp, patt);

    gemm_mma_kernel<<<g512, 512, smGemm>>>(patt, pw+OGO, go_b,
                                           px, 0, 0, 0, px, pm, DD, DD, 0, 3, 0);

    ln_kernel<<<M, 128>>>(px, ln3_g, ln3_b, pm, pxn, 0, 0, 0);
    gemm_mma_kernel<<<g1k,  512, smGemm>>>(pxn, pw+OF1, f1_b,
                                           0, ph1, 0, 0, 0, 0, 512,  1024, 1, 1, 0);
    gemm_mma_kernel<<<g1k,  512, smGemm>>>(ph1, pw+OF2, f2_b,
                                           0, ph2, 0, 0, 0, 0, 1024, 1024, 1, 1, 0);
    // f3 + residual + mask -> out
    gemm_mma_kernel<<<g512, 512, smGemm>>>(ph2, pw+OF3, f3_b,
                                           out, 0, 0, 0, px, pm, 1024, 512, 0, 3, 0);
}